// round 2
// baseline (speedup 1.0000x reference)
#include <cuda_runtime.h>

#define N_NODES 8192
#define F_IN    512
#define F_OUT   64
#define NSPLIT  4
#define JCHUNK  (N_NODES / NSPLIT)   // 2048
#define BM      128
#define BJ      32
#define K2_THREADS 256
#define WT_PITCH 130                 // ull units per jj row (128 rows + pad, even for 16B align)
#define HS_PITCH 68                  // floats per jj row (64 + pad)

typedef unsigned long long ull;

__device__ float g_h[N_NODES * F_OUT];
__device__ float g_s1[N_NODES];
__device__ float g_s2[N_NODES];
__device__ float g_accP[NSPLIT][N_NODES * F_OUT];
__device__ float g_lP[NSPLIT][N_NODES];

__device__ __forceinline__ void ffma2(ull &d, ull a, ull b) {
    asm("fma.rn.f32x2 %0, %1, %2, %0;" : "+l"(d) : "l"(a), "l"(b));
}
__device__ __forceinline__ ull dup2(float x) {
    ull r; asm("mov.b64 %0, {%1, %1};" : "=l"(r) : "f"(x)); return r;
}
__device__ __forceinline__ float2 unpack2(ull v) {
    float2 r; asm("mov.b64 {%0, %1}, %2;" : "=f"(r.x), "=f"(r.y) : "l"(v)); return r;
}

// ---------------------------------------------------------------------------
// Kernel 1: h = input @ W   (8192x512 @ 512x64, fp32)
// CTA: 256 threads computes 64 rows x 64 cols, K tiled by 64.
// ---------------------------------------------------------------------------
__global__ __launch_bounds__(256) void k_hproj(const float* __restrict__ inp,
                                               const float* __restrict__ W) {
    __shared__ float inp_s[64 * 68];   // [k][row] transposed
    __shared__ float W_s[64 * 68];     // [k][col]
    const int tid  = threadIdx.x;
    const int row0 = blockIdx.x * 64;
    const int rg = tid >> 4;           // 0..15, 4 rows each
    const int cg = tid & 15;           // 0..15, 4 cols each

    float acc[4][4];
#pragma unroll
    for (int i = 0; i < 4; i++)
#pragma unroll
        for (int j = 0; j < 4; j++) acc[i][j] = 0.f;

    for (int k0 = 0; k0 < F_IN; k0 += 64) {
        __syncthreads();
        {
            const int q = tid & 15;    // quad index
            const int b = tid >> 4;    // 0..15
#pragma unroll
            for (int p = 0; p < 4; p++) {
                int r = b + p * 16;
                float4 v = *(const float4*)&inp[(size_t)(row0 + r) * F_IN + k0 + q * 4];
                inp_s[(q * 4 + 0) * 68 + r] = v.x;
                inp_s[(q * 4 + 1) * 68 + r] = v.y;
                inp_s[(q * 4 + 2) * 68 + r] = v.z;
                inp_s[(q * 4 + 3) * 68 + r] = v.w;
            }
#pragma unroll
            for (int p = 0; p < 4; p++) {
                int k = b + p * 16;
                *(float4*)&W_s[k * 68 + q * 4] =
                    *(const float4*)&W[(size_t)(k0 + k) * F_OUT + q * 4];
            }
        }
        __syncthreads();
#pragma unroll 8
        for (int kk = 0; kk < 64; kk++) {
            float4 a4 = *(const float4*)&inp_s[kk * 68 + rg * 4];
            float4 b4 = *(const float4*)&W_s[kk * 68 + cg * 4];
            float av[4] = {a4.x, a4.y, a4.z, a4.w};
            float bv[4] = {b4.x, b4.y, b4.z, b4.w};
#pragma unroll
            for (int i = 0; i < 4; i++)
#pragma unroll
                for (int j = 0; j < 4; j++) acc[i][j] += av[i] * bv[j];
        }
    }
#pragma unroll
    for (int i = 0; i < 4; i++) {
        float4 o = make_float4(acc[i][0], acc[i][1], acc[i][2], acc[i][3]);
        *(float4*)&g_h[(size_t)(row0 + rg * 4 + i) * F_OUT + cg * 4] = o;
    }
}

// ---------------------------------------------------------------------------
// Kernel S: s1 = h @ a1, s2 = h @ a2. One warp per row.
// ---------------------------------------------------------------------------
__global__ __launch_bounds__(256) void k_scores(const float* __restrict__ a) {
    const int row  = blockIdx.x * 8 + (threadIdx.x >> 5);
    const int lane = threadIdx.x & 31;
    float2 hv = *(const float2*)&g_h[(size_t)row * F_OUT + lane * 2];
    float p1 = hv.x * a[lane * 2]      + hv.y * a[lane * 2 + 1];
    float p2 = hv.x * a[64 + lane * 2] + hv.y * a[64 + lane * 2 + 1];
#pragma unroll
    for (int o = 16; o > 0; o >>= 1) {
        p1 += __shfl_xor_sync(0xffffffffu, p1, o);
        p2 += __shfl_xor_sync(0xffffffffu, p2, o);
    }
    if (lane == 0) { g_s1[row] = p1; g_s2[row] = p2; }
}

// ---------------------------------------------------------------------------
// Kernel 2: fused masked-softmax-weight x h accumulation (no max needed:
// e = leaky(s1+s2) is bounded, exp never overflows; masked entries exact 0).
// Grid: (64 row-blocks of 128, 4 j-splits of 2048). Disjoint partial outputs.
// Phase A: compute W tile (128x32) -> smem as duplicated f32x2, [j][row].
// Phase B: register-tiled f32x2 GEMM: 8 rows x 4 feats per thread.
// ---------------------------------------------------------------------------
__global__ __launch_bounds__(K2_THREADS) void k_attn(const int* __restrict__ adj) {
    __shared__ ull   wT[BJ * WT_PITCH];   // [jj][row], each entry = {w,w}
    __shared__ float hs[BJ * HS_PITCH];   // [jj][feat]

    const int tid  = threadIdx.x;
    const int row0 = blockIdx.x * BM;
    const int s    = blockIdx.y;
    const int jbase = s * JCHUNK;

    // phase A mapping: 2 threads per row, 16 j each
    const int rowA = tid >> 1;
    const int jh   = (tid & 1) * 16;
    const float s1r = g_s1[row0 + rowA];
    const int*   adjRow = adj + (size_t)(row0 + rowA) * N_NODES + jbase + jh;
    const float* s2p    = g_s2 + jbase + jh;
    float lpart = 0.f;

    // phase B mapping: 16 row-groups x 16 feat-groups
    const int rg = tid >> 4;   // rows rg*8 .. rg*8+7
    const int fg = tid & 15;   // feats fg*4 .. fg*4+3
    ull acc[16];
#pragma unroll
    for (int i = 0; i < 16; i++) acc[i] = 0ull;

    // h-tile load mapping: 512 float4 slots per tile, 2 per thread
    const int hjl = tid >> 4;  // 0..15
    const int hf4 = tid & 15;

    const int ntiles = JCHUNK / BJ;  // 64
    for (int t = 0; t < ntiles; t++) {
        const int jt = jbase + t * BJ;
        // prefetch global data into registers before the barrier
        const int4* ap = (const int4*)(adjRow + t * BJ);
        int4 A0 = ap[0], A1 = ap[1], A2 = ap[2], A3 = ap[3];
        float4 S0 = *(const float4*)(s2p + t * BJ);
        float4 S1 = *(const float4*)(s2p + t * BJ + 4);
        float4 S2 = *(const float4*)(s2p + t * BJ + 8);
        float4 S3 = *(const float4*)(s2p + t * BJ + 12);
        float4 H0 = *(const float4*)&g_h[(size_t)(jt + hjl) * F_OUT + hf4 * 4];
        float4 H1 = *(const float4*)&g_h[(size_t)(jt + 16 + hjl) * F_OUT + hf4 * 4];

        __syncthreads();  // previous phase B done reading smem

        *(float4*)&hs[hjl * HS_PITCH + hf4 * 4]        = H0;
        *(float4*)&hs[(16 + hjl) * HS_PITCH + hf4 * 4] = H1;

        int   av[16]; float sv[16];
        *(int4*)&av[0] = A0; *(int4*)&av[4] = A1; *(int4*)&av[8] = A2; *(int4*)&av[12] = A3;
        *(float4*)&sv[0] = S0; *(float4*)&sv[4] = S1; *(float4*)&sv[8] = S2; *(float4*)&sv[12] = S3;

#pragma unroll
        for (int jj = 0; jj < 16; jj++) {
            float e  = s1r + sv[jj];
            float le = fmaxf(e, 0.2f * e);       // LeakyReLU(0.2)
            float w  = __expf(le);
            w = (av[jj] > 0) ? w : 0.f;          // mask => exact 0 (matches exp(NEG_BIG-max))
            lpart += w;
            wT[(jh + jj) * WT_PITCH + rowA] = dup2(w);
        }
        __syncthreads();  // tiles ready

#pragma unroll 4
        for (int jj = 0; jj < BJ; jj++) {
            const ulonglong2* wp = (const ulonglong2*)&wT[jj * WT_PITCH + rg * 8];
            ulonglong2 w01 = wp[0], w23 = wp[1], w45 = wp[2], w67 = wp[3];
            ulonglong2 hv  = *(const ulonglong2*)&hs[jj * HS_PITCH + fg * 4];
            ffma2(acc[0],  w01.x, hv.x); ffma2(acc[1],  w01.x, hv.y);
            ffma2(acc[2],  w01.y, hv.x); ffma2(acc[3],  w01.y, hv.y);
            ffma2(acc[4],  w23.x, hv.x); ffma2(acc[5],  w23.x, hv.y);
            ffma2(acc[6],  w23.y, hv.x); ffma2(acc[7],  w23.y, hv.y);
            ffma2(acc[8],  w45.x, hv.x); ffma2(acc[9],  w45.x, hv.y);
            ffma2(acc[10], w45.y, hv.x); ffma2(acc[11], w45.y, hv.y);
            ffma2(acc[12], w67.x, hv.x); ffma2(acc[13], w67.x, hv.y);
            ffma2(acc[14], w67.y, hv.x); ffma2(acc[15], w67.y, hv.y);
        }
    }

    // write partial row-sums l (combine the 2 threads per row; same warp)
    float lo = __shfl_xor_sync(0xffffffffu, lpart, 1);
    if ((tid & 1) == 0) g_lP[s][row0 + rowA] = lpart + lo;

    // write partial accumulators (exclusive ownership per (block.x, s))
    float* ap2 = g_accP[s];
#pragma unroll
    for (int r = 0; r < 8; r++) {
        float2 x = unpack2(acc[r * 2]);
        float2 y = unpack2(acc[r * 2 + 1]);
        float4 o = make_float4(x.x, x.y, y.x, y.y);
        *(float4*)&ap2[(size_t)(row0 + rg * 8 + r) * F_OUT + fg * 4] = o;
    }
}

// ---------------------------------------------------------------------------
// Kernel 3: out[i][f] = sum_s accP[s][i][f] / sum_s lP[s][i]
// ---------------------------------------------------------------------------
__global__ __launch_bounds__(256) void k_norm(float* __restrict__ out) {
    const int idx = blockIdx.x * 256 + threadIdx.x;
    const int i = idx >> 6;
    float v = g_accP[0][idx] + g_accP[1][idx] + g_accP[2][idx] + g_accP[3][idx];
    float l = g_lP[0][i] + g_lP[1][i] + g_lP[2][i] + g_lP[3][i];
    out[idx] = v / l;
}

extern "C" void kernel_launch(void* const* d_in, const int* in_sizes, int n_in,
                              void* d_out, int out_size) {
    const float* inp = (const float*)d_in[0];
    const int*   adj = (const int*)d_in[1];
    const float* W   = (const float*)d_in[2];
    const float* a   = (const float*)d_in[3];
    float* out = (float*)d_out;

    k_hproj<<<N_NODES / 64, 256>>>(inp, W);
    k_scores<<<N_NODES / 8, 256>>>(a);
    dim3 g2(N_NODES / BM, NSPLIT);
    k_attn<<<g2, K2_THREADS>>>(adj);
    k_norm<<<(N_NODES * F_OUT) / 256, 256>>>(out);
}

// round 4
// speedup vs baseline: 1.3380x; 1.3380x over previous
#include <cuda_runtime.h>

#define N_NODES 8192
#define F_IN    512
#define F_OUT   64
#define NSPLIT  4
#define JCHUNK  (N_NODES / NSPLIT)   // 2048
#define BM      128
#define BJ      64
#define NT      (JCHUNK / BJ)        // 32 tiles per CTA

// dynamic smem layout for tcgen05 path (tile bases 1024-aligned for SW128)
#define SM_TMEM 0
#define SM_MBAR 8
#define SM_AHI  1024
#define SM_ALO  (SM_AHI + 16384)     // 17408
#define SM_BHI  (SM_ALO + 16384)     // 33792
#define SM_BLO  (SM_BHI + 8192)      // 41984
#define SM_TOT  (SM_BLO + 8192)      // 50176

// fallback (FMA) path smem layout inside the same dynamic buffer
#define BJ_F     32
#define NT_F     (JCHUNK / BJ_F)     // 64
#define WT_PITCH 130                 // ull per jj row
#define HS_PITCH 68                  // floats per jj row
#define SMF_WT   0                   // ull[BJ_F * WT_PITCH]  = 33280 B
#define SMF_HS   (BJ_F * WT_PITCH * 8)

// idesc kind::f16: F32 accum, bf16 A/B, N=64, M=128
#define MMA_IDESC 0x08100490u

#define SW(x) ((x) ^ ((((unsigned)(x)) >> 3) & 0x70u))

// tcgen05 only exists in the arch-specific ('a') compilation pass.
#if defined(__CUDA_ARCH_FEAT_SM103_ALL) || defined(__CUDA_ARCH_FEAT_SM100_ALL) || \
    defined(__CUDA_ARCH_FEAT_SM101_ALL) || defined(__CUDA_ARCH_SPECIFIC__)
#define HAS_TC 1
#else
#define HAS_TC 0
#endif

typedef unsigned long long ull;

__device__ float          g_h[N_NODES * F_OUT];
__device__ unsigned short g_hT_hi[F_OUT * N_NODES];
__device__ unsigned short g_hT_lo[F_OUT * N_NODES];
__device__ float          g_s1[N_NODES];
__device__ float          g_s2[N_NODES];
__device__ float          g_accP[NSPLIT][N_NODES * F_OUT];
__device__ float          g_lP[NSPLIT][N_NODES];

// ---------------- generic helpers ----------------
__device__ __forceinline__ unsigned smem_u32(const void* p) {
    unsigned r;
    asm("{ .reg .u64 t; cvta.to.shared.u64 t, %1; cvt.u32.u64 %0, t; }" : "=r"(r) : "l"(p));
    return r;
}
__device__ __forceinline__ unsigned short bf16of(float v) {
    unsigned short h; asm("cvt.rn.bf16.f32 %0, %1;" : "=h"(h) : "f"(v)); return h;
}
__device__ __forceinline__ void ffma2(ull &d, ull a, ull b) {
    asm("fma.rn.f32x2 %0, %1, %2, %0;" : "+l"(d) : "l"(a), "l"(b));
}
__device__ __forceinline__ ull dup2(float x) {
    ull r; asm("mov.b64 %0, {%1, %1};" : "=l"(r) : "f"(x)); return r;
}
__device__ __forceinline__ float2 unpack2(ull v) {
    float2 r; asm("mov.b64 {%0, %1}, %2;" : "=f"(r.x), "=f"(r.y) : "l"(v)); return r;
}

#if HAS_TC
// ---------------- tcgen05 helpers (guarded: 'a'-pass only) ----------------
__device__ __forceinline__ unsigned elect_one() {
    unsigned p;
    asm volatile("{ .reg .pred p; elect.sync _|p, 0xFFFFFFFF; selp.b32 %0, 1, 0, p; }" : "=r"(p));
    return p;
}
__device__ __forceinline__ unsigned pack2(float a, float b) {  // lower = a, upper = b
    unsigned r; asm("cvt.rn.bf16x2.f32 %0, %2, %1;" : "=r"(r) : "f"(a), "f"(b)); return r;
}
__device__ __forceinline__ void mma_f16_ss(unsigned d, ull a, ull b, unsigned idesc, unsigned en) {
    asm volatile(
        "{ .reg .pred p; setp.ne.u32 p, %4, 0;\n\t"
        "tcgen05.mma.cta_group::1.kind::f16 [%0], %1, %2, %3, {%5,%5,%5,%5}, p; }"
        :: "r"(d), "l"(a), "l"(b), "r"(idesc), "r"(en), "r"(0u) : "memory");
}
__device__ __forceinline__ void mbar_init(unsigned m, unsigned cnt) {
    asm volatile("mbarrier.init.shared.b64 [%0], %1;" :: "r"(m), "r"(cnt) : "memory");
}
__device__ __forceinline__ void mbar_wait(unsigned m, unsigned parity) {
    asm volatile(
        "{ .reg .pred P;\n\t"
        "WL_%=: mbarrier.try_wait.parity.acquire.cta.shared::cta.b64 P, [%0], %1, 0x989680;\n\t"
        "@P bra.uni WD_%=;\n\t"
        "bra.uni WL_%=;\n\t"
        "WD_%=: }"
        :: "r"(m), "r"(parity) : "memory");
}
__device__ __forceinline__ void tmem_alloc(unsigned smem_dst, unsigned ncols) {
    asm volatile("tcgen05.alloc.cta_group::1.sync.aligned.shared::cta.b32 [%0], %1;"
                 :: "r"(smem_dst), "r"(ncols) : "memory");
}
__device__ __forceinline__ void tmem_dealloc(unsigned tmem, unsigned ncols) {
    asm volatile("tcgen05.dealloc.cta_group::1.sync.aligned.b32 %0, %1;" :: "r"(tmem), "r"(ncols));
}
__device__ __forceinline__ void tmem_relinquish() {
    asm volatile("tcgen05.relinquish_alloc_permit.cta_group::1.sync.aligned;");
}
__device__ __forceinline__ void tc_commit(unsigned mbar) {
    asm volatile("tcgen05.commit.cta_group::1.mbarrier::arrive::one.shared::cluster.b64 [%0];"
                 :: "r"(mbar) : "memory");
}
__device__ __forceinline__ void fence_async_smem() {
    asm volatile("fence.proxy.async.shared::cta;" ::: "memory");
}
__device__ __forceinline__ void tc_fence_after() {
    asm volatile("tcgen05.fence::after_thread_sync;" ::: "memory");
}
__device__ __forceinline__ void tc_fence_before() {
    asm volatile("tcgen05.fence::before_thread_sync;" ::: "memory");
}
__device__ __forceinline__ void tmem_ld_x32(unsigned* r, unsigned addr) {
    asm volatile(
        "tcgen05.ld.sync.aligned.32x32b.x32.b32 "
        "{%0,%1,%2,%3,%4,%5,%6,%7,%8,%9,%10,%11,%12,%13,%14,%15,"
        "%16,%17,%18,%19,%20,%21,%22,%23,%24,%25,%26,%27,%28,%29,%30,%31}, [%32];"
        : "=r"(r[0]), "=r"(r[1]), "=r"(r[2]), "=r"(r[3]), "=r"(r[4]), "=r"(r[5]), "=r"(r[6]), "=r"(r[7]),
          "=r"(r[8]), "=r"(r[9]), "=r"(r[10]), "=r"(r[11]), "=r"(r[12]), "=r"(r[13]), "=r"(r[14]), "=r"(r[15]),
          "=r"(r[16]), "=r"(r[17]), "=r"(r[18]), "=r"(r[19]), "=r"(r[20]), "=r"(r[21]), "=r"(r[22]), "=r"(r[23]),
          "=r"(r[24]), "=r"(r[25]), "=r"(r[26]), "=r"(r[27]), "=r"(r[28]), "=r"(r[29]), "=r"(r[30]), "=r"(r[31])
        : "r"(addr));
}
__device__ __forceinline__ void tmem_wait_ld() {
    asm volatile("tcgen05.wait::ld.sync.aligned;" ::: "memory");
}
static constexpr ull DESC_BASE_SW128 =
    (2ull << 61) | (1ull << 46) | (64ull << 32) | (1ull << 16);
__device__ __forceinline__ ull smem_desc(unsigned addr) {
    return DESC_BASE_SW128 | ((ull)(addr >> 4) & 0x3FFFull);
}
#endif  // HAS_TC

// ---------------------------------------------------------------------------
// Kernel 1: h = input @ W. Also emits bf16 hi/lo transposed copies hT[f][n].
// ---------------------------------------------------------------------------
__global__ __launch_bounds__(256) void k_hproj(const float* __restrict__ inp,
                                               const float* __restrict__ W) {
    __shared__ float inp_s[64 * 68];   // [k][row]
    __shared__ float W_s[64 * 68];     // [k][col]
    const int tid  = threadIdx.x;
    const int row0 = blockIdx.x * 64;
    const int rg = tid >> 4;
    const int cg = tid & 15;

    float acc[4][4];
#pragma unroll
    for (int i = 0; i < 4; i++)
#pragma unroll
        for (int j = 0; j < 4; j++) acc[i][j] = 0.f;

    for (int k0 = 0; k0 < F_IN; k0 += 64) {
        __syncthreads();
        {
            const int q = tid & 15;
            const int b = tid >> 4;
#pragma unroll
            for (int p = 0; p < 4; p++) {
                int r = b + p * 16;
                float4 v = *(const float4*)&inp[(size_t)(row0 + r) * F_IN + k0 + q * 4];
                inp_s[(q * 4 + 0) * 68 + r] = v.x;
                inp_s[(q * 4 + 1) * 68 + r] = v.y;
                inp_s[(q * 4 + 2) * 68 + r] = v.z;
                inp_s[(q * 4 + 3) * 68 + r] = v.w;
            }
#pragma unroll
            for (int p = 0; p < 4; p++) {
                int k = b + p * 16;
                *(float4*)&W_s[k * 68 + q * 4] =
                    *(const float4*)&W[(size_t)(k0 + k) * F_OUT + q * 4];
            }
        }
        __syncthreads();
#pragma unroll 8
        for (int kk = 0; kk < 64; kk++) {
            float4 a4 = *(const float4*)&inp_s[kk * 68 + rg * 4];
            float4 b4 = *(const float4*)&W_s[kk * 68 + cg * 4];
            float av[4] = {a4.x, a4.y, a4.z, a4.w};
            float bv[4] = {b4.x, b4.y, b4.z, b4.w};
#pragma unroll
            for (int i = 0; i < 4; i++)
#pragma unroll
                for (int j = 0; j < 4; j++) acc[i][j] += av[i] * bv[j];
        }
    }
#pragma unroll
    for (int i = 0; i < 4; i++) {
        float4 o = make_float4(acc[i][0], acc[i][1], acc[i][2], acc[i][3]);
        *(float4*)&g_h[(size_t)(row0 + rg * 4 + i) * F_OUT + cg * 4] = o;
#pragma unroll
        for (int j = 0; j < 4; j++) {
            float v = acc[i][j];
            unsigned short hb = bf16of(v);
            float fhi = __uint_as_float(((unsigned)hb) << 16);
            unsigned short lb = bf16of(v - fhi);
            size_t idx = (size_t)(cg * 4 + j) * N_NODES + row0 + rg * 4 + i;
            g_hT_hi[idx] = hb;
            g_hT_lo[idx] = lb;
        }
    }
}

// ---------------------------------------------------------------------------
// Kernel S: s1 = h @ a1, s2 = h @ a2. One warp per row.
// ---------------------------------------------------------------------------
__global__ __launch_bounds__(256) void k_scores(const float* __restrict__ a) {
    const int row  = blockIdx.x * 8 + (threadIdx.x >> 5);
    const int lane = threadIdx.x & 31;
    float2 hv = *(const float2*)&g_h[(size_t)row * F_OUT + lane * 2];
    float p1 = hv.x * a[lane * 2]      + hv.y * a[lane * 2 + 1];
    float p2 = hv.x * a[64 + lane * 2] + hv.y * a[64 + lane * 2 + 1];
#pragma unroll
    for (int o = 16; o > 0; o >>= 1) {
        p1 += __shfl_xor_sync(0xffffffffu, p1, o);
        p2 += __shfl_xor_sync(0xffffffffu, p2, o);
    }
    if (lane == 0) { g_s1[row] = p1; g_s2[row] = p2; }
}

// ---------------------------------------------------------------------------
// Kernel 2: fused masked-softmax-weights x h accumulation.
// tcgen05 path (sm_103a cubin): 3x bf16 hi/lo SS MMA into fp32 TMEM.
// Fallback path (non-'a' cubin): f32x2 FMA register-tiled GEMM.
// No row-max needed: e = leaky(s1+s2) bounded; masked weights exact 0.
// ---------------------------------------------------------------------------
__global__ __launch_bounds__(256, 1) void k_attn_tc(const int* __restrict__ adj) {
    extern __shared__ char smem[];
    const int tid  = threadIdx.x;
    const int row0 = blockIdx.x * BM;
    const int s    = blockIdx.y;
    const int jbase = s * JCHUNK;

#if HAS_TC
    const unsigned sbase = smem_u32(smem);
    const int wid  = tid >> 5;
    const int lane = tid & 31;

    if (wid == 0) tmem_alloc(sbase + SM_TMEM, 64);
    if (tid == 0) mbar_init(sbase + SM_MBAR, 1);
    __syncthreads();
    unsigned tmem;
    asm volatile("ld.shared.b32 %0, [%1];" : "=r"(tmem) : "r"(sbase + SM_TMEM));
    const unsigned mbar = sbase + SM_MBAR;

    // phase-A mapping: 2 threads per row, 32 j each
    const int rowA = tid >> 1;
    const int jh   = (tid & 1) * 32;
    const float s1r = g_s1[row0 + rowA];
    const int*   adjRow = adj + (size_t)(row0 + rowA) * N_NODES + jbase + jh;
    const float* s2p    = g_s2 + jbase + jh;

    // B staging: 512 16B chunks per tile, 2 per thread
    const int c0 = tid * 2, c1 = c0 + 1;
    const int bf0 = c0 >> 3, bc0 = c0 & 7;
    const int bf1 = c1 >> 3, bc1 = c1 & 7;

    const ull dAhi = smem_desc(sbase + SM_AHI);
    const ull dAlo = smem_desc(sbase + SM_ALO);
    const ull dBhi = smem_desc(sbase + SM_BHI);
    const ull dBlo = smem_desc(sbase + SM_BLO);

    float lpart = 0.f;

    int4 aReg[8];
#pragma unroll
    for (int u = 0; u < 8; u++) aReg[u] = ((const int4*)adjRow)[u];

    for (int t = 0; t < NT; t++) {
        const int j0 = jbase + t * BJ;

        int4 bhi0 = *(const int4*)(g_hT_hi + (size_t)bf0 * N_NODES + j0 + bc0 * 8);
        int4 bhi1 = *(const int4*)(g_hT_hi + (size_t)bf1 * N_NODES + j0 + bc1 * 8);
        int4 blo0 = *(const int4*)(g_hT_lo + (size_t)bf0 * N_NODES + j0 + bc0 * 8);
        int4 blo1 = *(const int4*)(g_hT_lo + (size_t)bf1 * N_NODES + j0 + bc1 * 8);

        float w[32];
#pragma unroll
        for (int u = 0; u < 8; u++) {
            int4   av = aReg[u];
            float4 sv = ((const float4*)(s2p + t * BJ))[u];
            float e0 = s1r + sv.x, e1 = s1r + sv.y, e2 = s1r + sv.z, e3 = s1r + sv.w;
            float w0 = __expf(fmaxf(e0, 0.2f * e0));
            float w1 = __expf(fmaxf(e1, 0.2f * e1));
            float w2 = __expf(fmaxf(e2, 0.2f * e2));
            float w3 = __expf(fmaxf(e3, 0.2f * e3));
            w0 = (av.x > 0) ? w0 : 0.f;
            w1 = (av.y > 0) ? w1 : 0.f;
            w2 = (av.z > 0) ? w2 : 0.f;
            w3 = (av.w > 0) ? w3 : 0.f;
            lpart += (w0 + w1) + (w2 + w3);
            w[u * 4 + 0] = w0; w[u * 4 + 1] = w1; w[u * 4 + 2] = w2; w[u * 4 + 3] = w3;
        }

        if (t + 1 < NT) {
#pragma unroll
            for (int u = 0; u < 8; u++)
                aReg[u] = ((const int4*)(adjRow + (t + 1) * BJ))[u];
        }

        int4 hiv[4], lov[4];
#pragma unroll
        for (int q = 0; q < 4; q++) {
            unsigned h[4], l[4];
#pragma unroll
            for (int p = 0; p < 4; p++) {
                float wa = w[q * 8 + p * 2], wb = w[q * 8 + p * 2 + 1];
                unsigned hh = pack2(wa, wb);
                float fa = __uint_as_float(hh << 16);
                float fb = __uint_as_float(hh & 0xffff0000u);
                h[p] = hh;
                l[p] = pack2(wa - fa, wb - fb);
            }
            hiv[q] = make_int4(h[0], h[1], h[2], h[3]);
            lov[q] = make_int4(l[0], l[1], l[2], l[3]);
        }

        if (t > 0) mbar_wait(mbar, (t - 1) & 1);

        const unsigned abase = rowA * 128 + jh * 2;
#pragma unroll
        for (int q = 0; q < 4; q++) {
            *(int4*)(smem + SM_AHI + SW(abase + q * 16)) = hiv[q];
            *(int4*)(smem + SM_ALO + SW(abase + q * 16)) = lov[q];
        }
        *(int4*)(smem + SM_BHI + SW(bf0 * 128 + bc0 * 16)) = bhi0;
        *(int4*)(smem + SM_BHI + SW(bf1 * 128 + bc1 * 16)) = bhi1;
        *(int4*)(smem + SM_BLO + SW(bf0 * 128 + bc0 * 16)) = blo0;
        *(int4*)(smem + SM_BLO + SW(bf1 * 128 + bc1 * 16)) = blo1;

        fence_async_smem();
        __syncthreads();

        if (wid == 0) {
            if (elect_one()) {
                ull aD[3] = {dAhi, dAhi, dAlo};
                ull bD[3] = {dBhi, dBlo, dBhi};
#pragma unroll
                for (int p = 0; p < 3; p++)
#pragma unroll
                    for (int k = 0; k < 4; k++)
                        mma_f16_ss(tmem, aD[p] + k * 2, bD[p] + k * 2, MMA_IDESC,
                                   !(t == 0 && p == 0 && k == 0));
                tc_commit(mbar);
            }
        }
    }

    float lo = __shfl_xor_sync(0xffffffffu, lpart, 1);
    if ((tid & 1) == 0) g_lP[s][row0 + rowA] = lpart + lo;

    mbar_wait(mbar, (NT - 1) & 1);
    tc_fence_after();
    if (wid < 4) {
        unsigned d0[32], d1[32];
        tmem_ld_x32(d0, tmem);
        tmem_ld_x32(d1, tmem + 32);
        tmem_wait_ld();
        tc_fence_before();
        float* dst = &g_accP[s][(size_t)(row0 + wid * 32 + lane) * F_OUT];
#pragma unroll
        for (int c = 0; c < 8; c++) {
            *(float4*)&dst[c * 4] = make_float4(
                __uint_as_float(d0[c * 4]), __uint_as_float(d0[c * 4 + 1]),
                __uint_as_float(d0[c * 4 + 2]), __uint_as_float(d0[c * 4 + 3]));
            *(float4*)&dst[32 + c * 4] = make_float4(
                __uint_as_float(d1[c * 4]), __uint_as_float(d1[c * 4 + 1]),
                __uint_as_float(d1[c * 4 + 2]), __uint_as_float(d1[c * 4 + 3]));
        }
    }
    __syncthreads();
    if (wid == 0) {
        tmem_relinquish();
        tmem_dealloc(tmem, 64);
    }

#else  // ------------------- FMA fallback (non-'a' pass) -------------------
    ull*   wT = (ull*)(smem + SMF_WT);     // [jj][row] duplicated f32x2
    float* hs = (float*)(smem + SMF_HS);   // [jj][feat]

    const int rowA = tid >> 1;
    const int jh   = (tid & 1) * 16;
    const float s1r = g_s1[row0 + rowA];
    const int*   adjRow = adj + (size_t)(row0 + rowA) * N_NODES + jbase + jh;
    const float* s2p    = g_s2 + jbase + jh;
    float lpart = 0.f;

    const int rg = tid >> 4;
    const int fg = tid & 15;
    ull acc[16];
#pragma unroll
    for (int i = 0; i < 16; i++) acc[i] = 0ull;

    const int hjl = tid >> 4;
    const int hf4 = tid & 15;

    for (int t = 0; t < NT_F; t++) {
        const int jt = jbase + t * BJ_F;
        const int4* ap = (const int4*)(adjRow + t * BJ_F);
        int4 A0 = ap[0], A1 = ap[1], A2 = ap[2], A3 = ap[3];
        float4 S0 = *(const float4*)(s2p + t * BJ_F);
        float4 S1 = *(const float4*)(s2p + t * BJ_F + 4);
        float4 S2 = *(const float4*)(s2p + t * BJ_F + 8);
        float4 S3 = *(const float4*)(s2p + t * BJ_F + 12);
        float4 H0 = *(const float4*)&g_h[(size_t)(jt + hjl) * F_OUT + hf4 * 4];
        float4 H1 = *(const float4*)&g_h[(size_t)(jt + 16 + hjl) * F_OUT + hf4 * 4];

        __syncthreads();

        *(float4*)&hs[hjl * HS_PITCH + hf4 * 4]        = H0;
        *(float4*)&hs[(16 + hjl) * HS_PITCH + hf4 * 4] = H1;

        int   av[16]; float sv[16];
        *(int4*)&av[0] = A0; *(int4*)&av[4] = A1; *(int4*)&av[8] = A2; *(int4*)&av[12] = A3;
        *(float4*)&sv[0] = S0; *(float4*)&sv[4] = S1; *(float4*)&sv[8] = S2; *(float4*)&sv[12] = S3;

#pragma unroll
        for (int jj = 0; jj < 16; jj++) {
            float e  = s1r + sv[jj];
            float le = fmaxf(e, 0.2f * e);
            float w  = __expf(le);
            w = (av[jj] > 0) ? w : 0.f;
            lpart += w;
            wT[(jh + jj) * WT_PITCH + rowA] = dup2(w);
        }
        __syncthreads();

#pragma unroll 4
        for (int jj = 0; jj < BJ_F; jj++) {
            const ulonglong2* wp = (const ulonglong2*)&wT[jj * WT_PITCH + rg * 8];
            ulonglong2 w01 = wp[0], w23 = wp[1], w45 = wp[2], w67 = wp[3];
            ulonglong2 hv  = *(const ulonglong2*)&hs[jj * HS_PITCH + fg * 4];
            ffma2(acc[0],  w01.x, hv.x); ffma2(acc[1],  w01.x, hv.y);
            ffma2(acc[2],  w01.y, hv.x); ffma2(acc[3],  w01.y, hv.y);
            ffma2(acc[4],  w23.x, hv.x); ffma2(acc[5],  w23.x, hv.y);
            ffma2(acc[6],  w23.y, hv.x); ffma2(acc[7],  w23.y, hv.y);
            ffma2(acc[8],  w45.x, hv.x); ffma2(acc[9],  w45.x, hv.y);
            ffma2(acc[10], w45.y, hv.x); ffma2(acc[11], w45.y, hv.y);
            ffma2(acc[12], w67.x, hv.x); ffma2(acc[13], w67.x, hv.y);
            ffma2(acc[14], w67.y, hv.x); ffma2(acc[15], w67.y, hv.y);
        }
    }

    float lo2 = __shfl_xor_sync(0xffffffffu, lpart, 1);
    if ((tid & 1) == 0) g_lP[s][row0 + rowA] = lpart + lo2;

    float* ap2 = g_accP[s];
#pragma unroll
    for (int r = 0; r < 8; r++) {
        float2 x = unpack2(acc[r * 2]);
        float2 y = unpack2(acc[r * 2 + 1]);
        float4 o = make_float4(x.x, x.y, y.x, y.y);
        *(float4*)&ap2[(size_t)(row0 + rg * 8 + r) * F_OUT + fg * 4] = o;
    }
#endif
}

// ---------------------------------------------------------------------------
// Kernel 3: out[i][f] = sum_s accP[s][i][f] / sum_s lP[s][i]
// ---------------------------------------------------------------------------
__global__ __launch_bounds__(256) void k_norm(float* __restrict__ out) {
    const int idx = blockIdx.x * 256 + threadIdx.x;
    const int i = idx >> 6;
    float v = g_accP[0][idx] + g_accP[1][idx] + g_accP[2][idx] + g_accP[3][idx];
    float l = g_lP[0][i] + g_lP[1][i] + g_lP[2][i] + g_lP[3][i];
    out[idx] = v / l;
}

extern "C" void kernel_launch(void* const* d_in, const int* in_sizes, int n_in,
                              void* d_out, int out_size) {
    const float* inp = (const float*)d_in[0];
    const int*   adj = (const int*)d_in[1];
    const float* W   = (const float*)d_in[2];
    const float* a   = (const float*)d_in[3];
    float* out = (float*)d_out;

    cudaFuncSetAttribute(k_attn_tc, cudaFuncAttributeMaxDynamicSharedMemorySize, SM_TOT);

    k_hproj<<<N_NODES / 64, 256>>>(inp, W);
    k_scores<<<N_NODES / 8, 256>>>(a);
    dim3 g2(N_NODES / BM, NSPLIT);
    k_attn_tc<<<g2, 256, SM_TOT>>>(adj);
    k_norm<<<(N_NODES * F_OUT) / 256, 256>>>(out);
}

// round 7
// speedup vs baseline: 2.0745x; 1.5504x over previous
#include <cuda_runtime.h>

#define N_NODES 8192
#define F_IN    512
#define F_OUT   64
#define NSPLIT  2
#define JCHUNK  (N_NODES / NSPLIT)   // 4096
#define BM      128
#define BJ      64
#define NT      (JCHUNK / BJ)        // 64 tiles per CTA
#define NTHR    512

// dynamic smem: [tmem ptr][mbar0][mbar1] + 2 stages of 48KB, 1024-aligned
#define SM_TMEM   0
#define SM_MBAR   8                  // two 8-byte mbarriers: 8, 16
#define SM_STAGE0 1024
#define STAGE_SZ  49152
#define OFF_AHI   0
#define OFF_ALO   16384
#define OFF_BHI   32768
#define OFF_BLO   40960
#define SM_TOT    (SM_STAGE0 + 2 * STAGE_SZ)   // 99328

// fallback (FMA) path smem layout inside the same dynamic buffer
#define BJ_F     32
#define NT_F     (JCHUNK / BJ_F)     // 128
#define WT_PITCH 130
#define HS_PITCH 68
#define SMF_WT   0
#define SMF_HS   (BJ_F * WT_PITCH * 8)

// idesc kind::f16: F32 accum, bf16 A/B, N=64, M=128
#define MMA_IDESC 0x08100490u

#define SW(x) ((x) ^ ((((unsigned)(x)) >> 3) & 0x70u))

#if defined(__CUDA_ARCH_FEAT_SM103_ALL) || defined(__CUDA_ARCH_FEAT_SM100_ALL) || \
    defined(__CUDA_ARCH_FEAT_SM101_ALL) || defined(__CUDA_ARCH_SPECIFIC__)
#define HAS_TC 1
#else
#define HAS_TC 0
#endif

typedef unsigned long long ull;

__device__ float          g_h[N_NODES * F_OUT];
__device__ unsigned short g_hT_hi[F_OUT * N_NODES];
__device__ unsigned short g_hT_lo[F_OUT * N_NODES];
__device__ float          g_s1[N_NODES];
__device__ float          g_s2[N_NODES];
__device__ float          g_p1[N_NODES];    // exp(s1)
__device__ float          g_q1[N_NODES];    // exp(0.2 s1)
__device__ float          g_e1[N_NODES];    // exp(-s1)
__device__ float          g_r2[N_NODES];    // exp(s2)
__device__ float          g_t2[N_NODES];    // exp(0.2 s2)
__device__ float          g_accP[NSPLIT][N_NODES * F_OUT];
__device__ float          g_lP[NSPLIT][N_NODES];

// ---------------- generic helpers ----------------
__device__ __forceinline__ unsigned smem_u32(const void* p) {
    unsigned r;
    asm("{ .reg .u64 t; cvta.to.shared.u64 t, %1; cvt.u32.u64 %0, t; }" : "=r"(r) : "l"(p));
    return r;
}
__device__ __forceinline__ unsigned short bf16of(float v) {
    unsigned short h; asm("cvt.rn.bf16.f32 %0, %1;" : "=h"(h) : "f"(v)); return h;
}
__device__ __forceinline__ void ffma2(ull &d, ull a, ull b) {
    asm("fma.rn.f32x2 %0, %1, %2, %0;" : "+l"(d) : "l"(a), "l"(b));
}
__device__ __forceinline__ ull dup2(float x) {
    ull r; asm("mov.b64 %0, {%1, %1};" : "=l"(r) : "f"(x)); return r;
}
__device__ __forceinline__ float2 unpack2(ull v) {
    float2 r; asm("mov.b64 {%0, %1}, %2;" : "=f"(r.x), "=f"(r.y) : "l"(v)); return r;
}

#if HAS_TC
// ---------------- tcgen05 helpers ('a'-pass only) ----------------
__device__ __forceinline__ unsigned elect_one() {
    unsigned p;
    asm volatile("{ .reg .pred p; elect.sync _|p, 0xFFFFFFFF; selp.b32 %0, 1, 0, p; }" : "=r"(p));
    return p;
}
__device__ __forceinline__ unsigned pack2(float a, float b) {  // lower = a, upper = b
    unsigned r; asm("cvt.rn.bf16x2.f32 %0, %2, %1;" : "=r"(r) : "f"(a), "f"(b)); return r;
}
__device__ __forceinline__ void mma_f16_ss(unsigned d, ull a, ull b, unsigned idesc, unsigned en) {
    asm volatile(
        "{ .reg .pred p; setp.ne.u32 p, %4, 0;\n\t"
        "tcgen05.mma.cta_group::1.kind::f16 [%0], %1, %2, %3, {%5,%5,%5,%5}, p; }"
        :: "r"(d), "l"(a), "l"(b), "r"(idesc), "r"(en), "r"(0u) : "memory");
}
__device__ __forceinline__ void mbar_init(unsigned m, unsigned cnt) {
    asm volatile("mbarrier.init.shared.b64 [%0], %1;" :: "r"(m), "r"(cnt) : "memory");
}
__device__ __forceinline__ void mbar_wait(unsigned m, unsigned parity) {
    asm volatile(
        "{ .reg .pred P;\n\t"
        "WL_%=: mbarrier.try_wait.parity.acquire.cta.shared::cta.b64 P, [%0], %1, 0x989680;\n\t"
        "@P bra.uni WD_%=;\n\t"
        "bra.uni WL_%=;\n\t"
        "WD_%=: }"
        :: "r"(m), "r"(parity) : "memory");
}
__device__ __forceinline__ void tmem_alloc(unsigned smem_dst, unsigned ncols) {
    asm volatile("tcgen05.alloc.cta_group::1.sync.aligned.shared::cta.b32 [%0], %1;"
                 :: "r"(smem_dst), "r"(ncols) : "memory");
}
__device__ __forceinline__ void tmem_dealloc(unsigned tmem, unsigned ncols) {
    asm volatile("tcgen05.dealloc.cta_group::1.sync.aligned.b32 %0, %1;" :: "r"(tmem), "r"(ncols));
}
__device__ __forceinline__ void tmem_relinquish() {
    asm volatile("tcgen05.relinquish_alloc_permit.cta_group::1.sync.aligned;");
}
__device__ __forceinline__ void tc_commit(unsigned mbar) {
    asm volatile("tcgen05.commit.cta_group::1.mbarrier::arrive::one.shared::cluster.b64 [%0];"
                 :: "r"(mbar) : "memory");
}
__device__ __forceinline__ void fence_async_smem() {
    asm volatile("fence.proxy.async.shared::cta;" ::: "memory");
}
__device__ __forceinline__ void tc_fence_after() {
    asm volatile("tcgen05.fence::after_thread_sync;" ::: "memory");
}
__device__ __forceinline__ void tc_fence_before() {
    asm volatile("tcgen05.fence::before_thread_sync;" ::: "memory");
}
__device__ __forceinline__ void tmem_ld_x32(unsigned* r, unsigned addr) {
    asm volatile(
        "tcgen05.ld.sync.aligned.32x32b.x32.b32 "
        "{%0,%1,%2,%3,%4,%5,%6,%7,%8,%9,%10,%11,%12,%13,%14,%15,"
        "%16,%17,%18,%19,%20,%21,%22,%23,%24,%25,%26,%27,%28,%29,%30,%31}, [%32];"
        : "=r"(r[0]), "=r"(r[1]), "=r"(r[2]), "=r"(r[3]), "=r"(r[4]), "=r"(r[5]), "=r"(r[6]), "=r"(r[7]),
          "=r"(r[8]), "=r"(r[9]), "=r"(r[10]), "=r"(r[11]), "=r"(r[12]), "=r"(r[13]), "=r"(r[14]), "=r"(r[15]),
          "=r"(r[16]), "=r"(r[17]), "=r"(r[18]), "=r"(r[19]), "=r"(r[20]), "=r"(r[21]), "=r"(r[22]), "=r"(r[23]),
          "=r"(r[24]), "=r"(r[25]), "=r"(r[26]), "=r"(r[27]), "=r"(r[28]), "=r"(r[29]), "=r"(r[30]), "=r"(r[31])
        : "r"(addr));
}
__device__ __forceinline__ void tmem_wait_ld() {
    asm volatile("tcgen05.wait::ld.sync.aligned;" ::: "memory");
}
static constexpr ull DESC_BASE_SW128 =
    (2ull << 61) | (1ull << 46) | (64ull << 32) | (1ull << 16);
__device__ __forceinline__ ull smem_desc(unsigned addr) {
    return DESC_BASE_SW128 | ((ull)(addr >> 4) & 0x3FFFull);
}
#endif  // HAS_TC

// ---------------------------------------------------------------------------
// Kernel 1: h = input @ W, plus bf16 hi/lo transposed copies hT[f][n].
// ---------------------------------------------------------------------------
__global__ __launch_bounds__(256) void k_hproj(const float* __restrict__ inp,
                                               const float* __restrict__ W) {
    __shared__ float inp_s[64 * 68];
    __shared__ float W_s[64 * 68];
    const int tid  = threadIdx.x;
    const int row0 = blockIdx.x * 64;
    const int rg = tid >> 4;
    const int cg = tid & 15;

    float acc[4][4];
#pragma unroll
    for (int i = 0; i < 4; i++)
#pragma unroll
        for (int j = 0; j < 4; j++) acc[i][j] = 0.f;

    for (int k0 = 0; k0 < F_IN; k0 += 64) {
        __syncthreads();
        {
            const int q = tid & 15;
            const int b = tid >> 4;
#pragma unroll
            for (int p = 0; p < 4; p++) {
                int r = b + p * 16;
                float4 v = *(const float4*)&inp[(size_t)(row0 + r) * F_IN + k0 + q * 4];
                inp_s[(q * 4 + 0) * 68 + r] = v.x;
                inp_s[(q * 4 + 1) * 68 + r] = v.y;
                inp_s[(q * 4 + 2) * 68 + r] = v.z;
                inp_s[(q * 4 + 3) * 68 + r] = v.w;
            }
#pragma unroll
            for (int p = 0; p < 4; p++) {
                int k = b + p * 16;
                *(float4*)&W_s[k * 68 + q * 4] =
                    *(const float4*)&W[(size_t)(k0 + k) * F_OUT + q * 4];
            }
        }
        __syncthreads();
#pragma unroll 8
        for (int kk = 0; kk < 64; kk++) {
            float4 a4 = *(const float4*)&inp_s[kk * 68 + rg * 4];
            float4 b4 = *(const float4*)&W_s[kk * 68 + cg * 4];
            float av[4] = {a4.x, a4.y, a4.z, a4.w};
            float bv[4] = {b4.x, b4.y, b4.z, b4.w};
#pragma unroll
            for (int i = 0; i < 4; i++)
#pragma unroll
                for (int j = 0; j < 4; j++) acc[i][j] += av[i] * bv[j];
        }
    }
#pragma unroll
    for (int i = 0; i < 4; i++) {
        float4 o = make_float4(acc[i][0], acc[i][1], acc[i][2], acc[i][3]);
        *(float4*)&g_h[(size_t)(row0 + rg * 4 + i) * F_OUT + cg * 4] = o;
#pragma unroll
        for (int j = 0; j < 4; j++) {
            float v = acc[i][j];
            unsigned short hb = bf16of(v);
            float fhi = __uint_as_float(((unsigned)hb) << 16);
            unsigned short lb = bf16of(v - fhi);
            size_t idx = (size_t)(cg * 4 + j) * N_NODES + row0 + rg * 4 + i;
            g_hT_hi[idx] = hb;
            g_hT_lo[idx] = lb;
        }
    }
}

// ---------------------------------------------------------------------------
// Kernel S: s1/s2 + factorized-exp tables. One warp per row.
// ---------------------------------------------------------------------------
__global__ __launch_bounds__(256) void k_scores(const float* __restrict__ a) {
    const int row  = blockIdx.x * 8 + (threadIdx.x >> 5);
    const int lane = threadIdx.x & 31;
    float2 hv = *(const float2*)&g_h[(size_t)row * F_OUT + lane * 2];
    float p1 = hv.x * a[lane * 2]      + hv.y * a[lane * 2 + 1];
    float p2 = hv.x * a[64 + lane * 2] + hv.y * a[64 + lane * 2 + 1];
#pragma unroll
    for (int o = 16; o > 0; o >>= 1) {
        p1 += __shfl_xor_sync(0xffffffffu, p1, o);
        p2 += __shfl_xor_sync(0xffffffffu, p2, o);
    }
    if (lane == 0) {
        g_s1[row] = p1;  g_s2[row] = p2;
        g_p1[row] = __expf(p1);
        g_q1[row] = __expf(0.2f * p1);
        g_e1[row] = __expf(-p1);
        g_r2[row] = __expf(p2);
        g_t2[row] = __expf(0.2f * p2);
    }
}

// ---------------------------------------------------------------------------
// Kernel 2: fused masked attention-weight x h via tcgen05 (3-product hi/lo
// bf16, fp32 TMEM accum). Double-buffered with ONE MBARRIER PER STAGE so
// parity phases are consumed strictly in order (no skipped-phase aliasing).
// Tile t -> stage st=t&1, phase index pi=t>>1 on mbar[st].
// ---------------------------------------------------------------------------
__global__ __launch_bounds__(NTHR, 1) void k_attn_tc(const int* __restrict__ adj) {
    extern __shared__ char smem[];
    const int tid  = threadIdx.x;
    const int row0 = blockIdx.x * BM;
    const int s    = blockIdx.y;
    const int jbase = s * JCHUNK;

#if HAS_TC
    const unsigned sbase = smem_u32(smem);
    const int wid  = tid >> 5;
    const int lane = tid & 31;

    if (wid == 0) tmem_alloc(sbase + SM_TMEM, 64);
    if (tid == 0) {
        mbar_init(sbase + SM_MBAR, 1);       // stage 0
        mbar_init(sbase + SM_MBAR + 8, 1);   // stage 1
    }
    __syncthreads();
    unsigned tmem;
    asm volatile("ld.shared.b32 %0, [%1];" : "=r"(tmem) : "r"(sbase + SM_TMEM));
    const unsigned mbar0 = sbase + SM_MBAR;

    // phase-A mapping: warp w covers rows w*8..w*8+7; lane = r2*16 + jc:
    // thread handles rows w*8 + u*2 + r2 (u=0..3), j = jc*4..jc*4+3.
    const int r2 = lane >> 4;
    const int jc = lane & 15;

    float P[4], Q[4], E[4], lp[4];
#pragma unroll
    for (int u = 0; u < 4; u++) {
        int r = row0 + wid * 8 + u * 2 + r2;
        P[u] = g_p1[r]; Q[u] = g_q1[r]; E[u] = g_e1[r];
        lp[u] = 0.f;
    }
    const int* adjBase = adj + (size_t)(row0 + wid * 8 + r2) * N_NODES + jbase + jc * 4;

    // B staging: 512 int4 chunks per 8KB tile; one per thread
    const int bf = tid >> 3, bc = tid & 7;

    // rolling adj prefetch (tile 0)
    int4 aCur[4];
#pragma unroll
    for (int u = 0; u < 4; u++)
        aCur[u] = *(const int4*)(adjBase + (size_t)u * 2 * N_NODES);

    for (int t = 0; t < NT; t++) {
        const int j0 = jbase + t * BJ;
        const int st = t & 1;
        char* stage = smem + SM_STAGE0 + st * STAGE_SZ;
        const unsigned mb = mbar0 + (st << 3);

        // early global loads for this tile
        int4 bhi = *(const int4*)(g_hT_hi + (size_t)bf * N_NODES + j0 + bc * 8);
        int4 blo = *(const int4*)(g_hT_lo + (size_t)bf * N_NODES + j0 + bc * 8);
        float4 R4 = *(const float4*)(g_r2 + j0 + jc * 4);
        float4 T4 = *(const float4*)(g_t2 + j0 + jc * 4);

        // wait for this stage's previous user (tile t-2, phase pi-1 on mb).
        // Phases on each barrier are consumed in order -> no aliasing.
        if (t >= 2) mbar_wait(mb, ((t >> 1) + 1) & 1);   // parity (pi-1)&1

        *(int4*)(stage + OFF_BHI + SW(bf * 128 + bc * 16)) = bhi;
        *(int4*)(stage + OFF_BLO + SW(bf * 128 + bc * 16)) = blo;

#pragma unroll
        for (int u = 0; u < 4; u++) {
            int4 av = aCur[u];
            if (t + 1 < NT)
                aCur[u] = *(const int4*)(adjBase + (size_t)u * 2 * N_NODES + (t + 1) * BJ);

            float m0 = (R4.x > E[u]) ? P[u] : Q[u];
            float n0 = (R4.x > E[u]) ? R4.x : T4.x;
            float m1 = (R4.y > E[u]) ? P[u] : Q[u];
            float n1 = (R4.y > E[u]) ? R4.y : T4.y;
            float m2 = (R4.z > E[u]) ? P[u] : Q[u];
            float n2 = (R4.z > E[u]) ? R4.z : T4.z;
            float m3 = (R4.w > E[u]) ? P[u] : Q[u];
            float n3 = (R4.w > E[u]) ? R4.w : T4.w;
            float w0 = m0 * n0; w0 = (av.x > 0) ? w0 : 0.f;
            float w1 = m1 * n1; w1 = (av.y > 0) ? w1 : 0.f;
            float w2 = m2 * n2; w2 = (av.z > 0) ? w2 : 0.f;
            float w3 = m3 * n3; w3 = (av.w > 0) ? w3 : 0.f;
            lp[u] += (w0 + w1) + (w2 + w3);

            unsigned hh01 = pack2(w0, w1);
            unsigned hh23 = pack2(w2, w3);
            float f0 = __uint_as_float(hh01 << 16);
            float f1 = __uint_as_float(hh01 & 0xffff0000u);
            float f2 = __uint_as_float(hh23 << 16);
            float f3 = __uint_as_float(hh23 & 0xffff0000u);
            unsigned ll01 = pack2(w0 - f0, w1 - f1);
            unsigned ll23 = pack2(w2 - f2, w3 - f3);

            const int rloc = wid * 8 + u * 2 + r2;
            const unsigned aoff = SW(rloc * 128 + jc * 8);
            *(uint2*)(stage + OFF_AHI + aoff) = make_uint2(hh01, hh23);
            *(uint2*)(stage + OFF_ALO + aoff) = make_uint2(ll01, ll23);
        }

        fence_async_smem();
        __syncthreads();

        if (wid == 0) {
            if (elect_one()) {
                const unsigned sb = sbase + SM_STAGE0 + st * STAGE_SZ;
                ull dAhi = smem_desc(sb + OFF_AHI);
                ull dAlo = smem_desc(sb + OFF_ALO);
                ull dBhi = smem_desc(sb + OFF_BHI);
                ull dBlo = smem_desc(sb + OFF_BLO);
                ull aD[3] = {dAhi, dAhi, dAlo};
                ull bD[3] = {dBhi, dBlo, dBhi};
#pragma unroll
                for (int p = 0; p < 3; p++)
#pragma unroll
                    for (int k = 0; k < 4; k++)
                        mma_f16_ss(tmem, aD[p] + k * 2, bD[p] + k * 2, MMA_IDESC,
                                   !(t == 0 && p == 0 && k == 0));
                tc_commit(mb);
            }
        }
    }

    // per-row l: reduce lp[u] across the 16 jc-lanes of each row
#pragma unroll
    for (int u = 0; u < 4; u++) {
        float v = lp[u];
        v += __shfl_xor_sync(0xffffffffu, v, 1);
        v += __shfl_xor_sync(0xffffffffu, v, 2);
        v += __shfl_xor_sync(0xffffffffu, v, 4);
        v += __shfl_xor_sync(0xffffffffu, v, 8);
        if (jc == 0)
            g_lP[s][row0 + wid * 8 + u * 2 + r2] = v;
    }

    // FULL DRAIN: each barrier's last phase index is NT/2-1 = 31 (parity 1).
    // Loop already enforced C>=31 per barrier, so the window is alias-free.
    mbar_wait(mbar0,     ((NT / 2) - 1) & 1);
    mbar_wait(mbar0 + 8, ((NT / 2) - 1) & 1);
    tc_fence_after();
    if (wid < 4) {
        unsigned d0[32], d1[32];
        tmem_ld_x32(d0, tmem);
        tmem_ld_x32(d1, tmem + 32);
        tmem_wait_ld();
        tc_fence_before();
        float* dst = &g_accP[s][(size_t)(row0 + wid * 32 + lane) * F_OUT];
#pragma unroll
        for (int c = 0; c < 8; c++) {
            *(float4*)&dst[c * 4] = make_float4(
                __uint_as_float(d0[c * 4]), __uint_as_float(d0[c * 4 + 1]),
                __uint_as_float(d0[c * 4 + 2]), __uint_as_float(d0[c * 4 + 3]));
            *(float4*)&dst[32 + c * 4] = make_float4(
                __uint_as_float(d1[c * 4]), __uint_as_float(d1[c * 4 + 1]),
                __uint_as_float(d1[c * 4 + 2]), __uint_as_float(d1[c * 4 + 3]));
        }
    }
    __syncthreads();
    if (wid == 0) {
        tmem_relinquish();
        tmem_dealloc(tmem, 64);
    }

#else  // ------------------- FMA fallback (non-'a' pass) -------------------
    ull*   wT = (ull*)(smem + SMF_WT);
    float* hs = (float*)(smem + SMF_HS);

    const int rowA = tid >> 2;
    const int jh   = (tid & 3) * 8;
    const float s1r = g_s1[row0 + rowA];
    const int*   adjRow = adj + (size_t)(row0 + rowA) * N_NODES + jbase + jh;
    const float* s2p    = g_s2 + jbase + jh;
    float lpart = 0.f;

    const int rg = tid >> 4;
    const int fg = tid & 15;
    ull acc[8];
#pragma unroll
    for (int i = 0; i < 8; i++) acc[i] = 0ull;

    const int hjl = tid >> 4;
    const int hf4 = tid & 15;

    for (int t = 0; t < NT_F; t++) {
        const int jt = jbase + t * BJ_F;
        const int4* ap = (const int4*)(adjRow + t * BJ_F);
        int4 A0 = ap[0], A1 = ap[1];
        float4 S0 = *(const float4*)(s2p + t * BJ_F);
        float4 S1 = *(const float4*)(s2p + t * BJ_F + 4);
        float4 H0 = *(const float4*)&g_h[(size_t)(jt + hjl) * F_OUT + hf4 * 4];

        __syncthreads();

        *(float4*)&hs[hjl * HS_PITCH + hf4 * 4] = H0;

        int   av[8]; float sv[8];
        *(int4*)&av[0] = A0; *(int4*)&av[4] = A1;
        *(float4*)&sv[0] = S0; *(float4*)&sv[4] = S1;

#pragma unroll
        for (int jj = 0; jj < 8; jj++) {
            float e  = s1r + sv[jj];
            float le = fmaxf(e, 0.2f * e);
            float w  = __expf(le);
            w = (av[jj] > 0) ? w : 0.f;
            lpart += w;
            wT[(jh + jj) * WT_PITCH + rowA] = dup2(w);
        }
        __syncthreads();

#pragma unroll 4
        for (int jj = 0; jj < BJ_F; jj++) {
            const ulonglong2* wp = (const ulonglong2*)&wT[jj * WT_PITCH + rg * 4];
            ulonglong2 w01 = wp[0], w23 = wp[1];
            ulonglong2 hv  = *(const ulonglong2*)&hs[jj * HS_PITCH + fg * 4];
            ffma2(acc[0], w01.x, hv.x); ffma2(acc[1], w01.x, hv.y);
            ffma2(acc[2], w01.y, hv.x); ffma2(acc[3], w01.y, hv.y);
            ffma2(acc[4], w23.x, hv.x); ffma2(acc[5], w23.x, hv.y);
            ffma2(acc[6], w23.y, hv.x); ffma2(acc[7], w23.y, hv.y);
        }
    }

    float l1 = __shfl_xor_sync(0xffffffffu, lpart, 1);
    lpart += l1;
    float l2 = __shfl_xor_sync(0xffffffffu, lpart, 2);
    lpart += l2;
    if ((tid & 3) == 0) g_lP[s][row0 + rowA] = lpart;

    float* ap2 = g_accP[s];
#pragma unroll
    for (int r = 0; r < 4; r++) {
        float2 x = unpack2(acc[r * 2]);
        float2 y = unpack2(acc[r * 2 + 1]);
        float4 o = make_float4(x.x, x.y, y.x, y.y);
        *(float4*)&ap2[(size_t)(row0 + rg * 4 + r) * F_OUT + fg * 4] = o;
    }
#endif
}

// ---------------------------------------------------------------------------
// Kernel 3: out[i][f] = sum_s accP[s][i][f] / sum_s lP[s][i]
// ---------------------------------------------------------------------------
__global__ __launch_bounds__(256) void k_norm(float* __restrict__ out) {
    const int idx = blockIdx.x * 256 + threadIdx.x;
    const int i = idx >> 6;
    float v = g_accP[0][idx] + g_accP[1][idx];
    float l = g_lP[0][i] + g_lP[1][i];
    out[idx] = v / l;
}

extern "C" void kernel_launch(void* const* d_in, const int* in_sizes, int n_in,
                              void* d_out, int out_size) {
    const float* inp = (const float*)d_in[0];
    const int*   adj = (const int*)d_in[1];
    const float* W   = (const float*)d_in[2];
    const float* a   = (const float*)d_in[3];
    float* out = (float*)d_out;

    cudaFuncSetAttribute(k_attn_tc, cudaFuncAttributeMaxDynamicSharedMemorySize, SM_TOT);

    k_hproj<<<N_NODES / 64, 256>>>(inp, W);
    k_scores<<<N_NODES / 8, 256>>>(a);
    dim3 g2(N_NODES / BM, NSPLIT);
    k_attn_tc<<<g2, NTHR, SM_TOT>>>(adj);
    k_norm<<<(N_NODES * F_OUT) / 256, 256>>>(out);
}

// round 8
// speedup vs baseline: 2.3660x; 1.1405x over previous
#include <cuda_runtime.h>

#define N_NODES 8192
#define F_IN    512
#define F_OUT   64
#define NSPLIT  2
#define JCHUNK  (N_NODES / NSPLIT)   // 4096
#define BM      128
#define BJ      64
#define NT      (JCHUNK / BJ)        // 64 tiles per CTA
#define NTHR    512

// dynamic smem: [tmem ptr][done0 done1 full0 full1] + 2 stages of 48KB
#define SM_TMEM   0
#define SM_DONE   8                  // done0=8, done1=16
#define SM_FULL   24                 // full0=24, full1=32
#define SM_STAGE0 1024
#define STAGE_SZ  49152
#define OFF_AHI   0
#define OFF_ALO   16384
#define OFF_BHI   32768
#define OFF_BLO   40960
#define SM_TOT    (SM_STAGE0 + 2 * STAGE_SZ)   // 99328

// fallback (FMA) path smem layout inside the same dynamic buffer
#define BJ_F     32
#define NT_F     (JCHUNK / BJ_F)     // 128
#define WT_PITCH 130
#define HS_PITCH 68
#define SMF_WT   0
#define SMF_HS   (BJ_F * WT_PITCH * 8)

// idesc kind::f16: F32 accum, bf16 A/B, N=64, M=128
#define MMA_IDESC 0x08100490u

#define SW(x) ((x) ^ ((((unsigned)(x)) >> 3) & 0x70u))

#if defined(__CUDA_ARCH_FEAT_SM103_ALL) || defined(__CUDA_ARCH_FEAT_SM100_ALL) || \
    defined(__CUDA_ARCH_FEAT_SM101_ALL) || defined(__CUDA_ARCH_SPECIFIC__)
#define HAS_TC 1
#else
#define HAS_TC 0
#endif

typedef unsigned long long ull;

__device__ float          g_h[N_NODES * F_OUT];
__device__ unsigned short g_hT_hi[F_OUT * N_NODES];
__device__ unsigned short g_hT_lo[F_OUT * N_NODES];
__device__ float          g_s1[N_NODES];
__device__ float          g_s2[N_NODES];
__device__ float          g_p1[N_NODES];    // exp(s1)
__device__ float          g_q1[N_NODES];    // exp(0.2 s1)
__device__ float          g_e1[N_NODES];    // exp(-s1)
__device__ float          g_r2[N_NODES];    // exp(s2)
__device__ float          g_t2[N_NODES];    // exp(0.2 s2)
__device__ float          g_accP[NSPLIT][N_NODES * F_OUT];
__device__ float          g_lP[NSPLIT][N_NODES];

// ---------------- generic helpers ----------------
__device__ __forceinline__ unsigned smem_u32(const void* p) {
    unsigned r;
    asm("{ .reg .u64 t; cvta.to.shared.u64 t, %1; cvt.u32.u64 %0, t; }" : "=r"(r) : "l"(p));
    return r;
}
__device__ __forceinline__ unsigned short bf16of(float v) {
    unsigned short h; asm("cvt.rn.bf16.f32 %0, %1;" : "=h"(h) : "f"(v)); return h;
}
__device__ __forceinline__ void ffma2(ull &d, ull a, ull b) {
    asm("fma.rn.f32x2 %0, %1, %2, %0;" : "+l"(d) : "l"(a), "l"(b));
}
__device__ __forceinline__ ull dup2(float x) {
    ull r; asm("mov.b64 %0, {%1, %1};" : "=l"(r) : "f"(x)); return r;
}
__device__ __forceinline__ float2 unpack2(ull v) {
    float2 r; asm("mov.b64 {%0, %1}, %2;" : "=f"(r.x), "=f"(r.y) : "l"(v)); return r;
}

#if HAS_TC
// ---------------- tcgen05 helpers ('a'-pass only) ----------------
__device__ __forceinline__ unsigned elect_one() {
    unsigned p;
    asm volatile("{ .reg .pred p; elect.sync _|p, 0xFFFFFFFF; selp.b32 %0, 1, 0, p; }" : "=r"(p));
    return p;
}
__device__ __forceinline__ unsigned pack2(float a, float b) {  // lower = a, upper = b
    unsigned r; asm("cvt.rn.bf16x2.f32 %0, %2, %1;" : "=r"(r) : "f"(a), "f"(b)); return r;
}
__device__ __forceinline__ void mma_f16_ss(unsigned d, ull a, ull b, unsigned idesc, unsigned en) {
    asm volatile(
        "{ .reg .pred p; setp.ne.u32 p, %4, 0;\n\t"
        "tcgen05.mma.cta_group::1.kind::f16 [%0], %1, %2, %3, {%5,%5,%5,%5}, p; }"
        :: "r"(d), "l"(a), "l"(b), "r"(idesc), "r"(en), "r"(0u) : "memory");
}
__device__ __forceinline__ void mbar_init(unsigned m, unsigned cnt) {
    asm volatile("mbarrier.init.shared.b64 [%0], %1;" :: "r"(m), "r"(cnt) : "memory");
}
__device__ __forceinline__ void mbar_arrive(unsigned m) {
    asm volatile("mbarrier.arrive.release.cta.shared::cta.b64 _, [%0];" :: "r"(m) : "memory");
}
__device__ __forceinline__ void mbar_wait(unsigned m, unsigned parity) {
    asm volatile(
        "{ .reg .pred P;\n\t"
        "WL_%=: mbarrier.try_wait.parity.acquire.cta.shared::cta.b64 P, [%0], %1, 0x989680;\n\t"
        "@P bra.uni WD_%=;\n\t"
        "bra.uni WL_%=;\n\t"
        "WD_%=: }"
        :: "r"(m), "r"(parity) : "memory");
}
__device__ __forceinline__ void tmem_alloc(unsigned smem_dst, unsigned ncols) {
    asm volatile("tcgen05.alloc.cta_group::1.sync.aligned.shared::cta.b32 [%0], %1;"
                 :: "r"(smem_dst), "r"(ncols) : "memory");
}
__device__ __forceinline__ void tmem_dealloc(unsigned tmem, unsigned ncols) {
    asm volatile("tcgen05.dealloc.cta_group::1.sync.aligned.b32 %0, %1;" :: "r"(tmem), "r"(ncols));
}
__device__ __forceinline__ void tmem_relinquish() {
    asm volatile("tcgen05.relinquish_alloc_permit.cta_group::1.sync.aligned;");
}
__device__ __forceinline__ void tc_commit(unsigned mbar) {
    asm volatile("tcgen05.commit.cta_group::1.mbarrier::arrive::one.shared::cluster.b64 [%0];"
                 :: "r"(mbar) : "memory");
}
__device__ __forceinline__ void fence_async_smem() {
    asm volatile("fence.proxy.async.shared::cta;" ::: "memory");
}
__device__ __forceinline__ void tc_fence_after() {
    asm volatile("tcgen05.fence::after_thread_sync;" ::: "memory");
}
__device__ __forceinline__ void tc_fence_before() {
    asm volatile("tcgen05.fence::before_thread_sync;" ::: "memory");
}
__device__ __forceinline__ void tmem_ld_x32(unsigned* r, unsigned addr) {
    asm volatile(
        "tcgen05.ld.sync.aligned.32x32b.x32.b32 "
        "{%0,%1,%2,%3,%4,%5,%6,%7,%8,%9,%10,%11,%12,%13,%14,%15,"
        "%16,%17,%18,%19,%20,%21,%22,%23,%24,%25,%26,%27,%28,%29,%30,%31}, [%32];"
        : "=r"(r[0]), "=r"(r[1]), "=r"(r[2]), "=r"(r[3]), "=r"(r[4]), "=r"(r[5]), "=r"(r[6]), "=r"(r[7]),
          "=r"(r[8]), "=r"(r[9]), "=r"(r[10]), "=r"(r[11]), "=r"(r[12]), "=r"(r[13]), "=r"(r[14]), "=r"(r[15]),
          "=r"(r[16]), "=r"(r[17]), "=r"(r[18]), "=r"(r[19]), "=r"(r[20]), "=r"(r[21]), "=r"(r[22]), "=r"(r[23]),
          "=r"(r[24]), "=r"(r[25]), "=r"(r[26]), "=r"(r[27]), "=r"(r[28]), "=r"(r[29]), "=r"(r[30]), "=r"(r[31])
        : "r"(addr));
}
__device__ __forceinline__ void tmem_wait_ld() {
    asm volatile("tcgen05.wait::ld.sync.aligned;" ::: "memory");
}
static constexpr ull DESC_BASE_SW128 =
    (2ull << 61) | (1ull << 46) | (64ull << 32) | (1ull << 16);
__device__ __forceinline__ ull smem_desc(unsigned addr) {
    return DESC_BASE_SW128 | ((ull)(addr >> 4) & 0x3FFFull);
}
#endif  // HAS_TC

// ---------------------------------------------------------------------------
// Kernel 1: h = input @ W, bf16 hi/lo transposed copies, AND fused s1/s2 +
// factorized-exp tables (scores computed from register accumulators).
// ---------------------------------------------------------------------------
__global__ __launch_bounds__(256) void k_hproj(const float* __restrict__ inp,
                                               const float* __restrict__ W,
                                               const float* __restrict__ a) {
    __shared__ float inp_s[64 * 68];
    __shared__ float W_s[64 * 68];
    const int tid  = threadIdx.x;
    const int row0 = blockIdx.x * 64;
    const int rg = tid >> 4;
    const int cg = tid & 15;
    const int lane = tid & 31;

    float acc[4][4];
#pragma unroll
    for (int i = 0; i < 4; i++)
#pragma unroll
        for (int j = 0; j < 4; j++) acc[i][j] = 0.f;

    for (int k0 = 0; k0 < F_IN; k0 += 64) {
        __syncthreads();
        {
            const int q = tid & 15;
            const int b = tid >> 4;
#pragma unroll
            for (int p = 0; p < 4; p++) {
                int r = b + p * 16;
                float4 v = *(const float4*)&inp[(size_t)(row0 + r) * F_IN + k0 + q * 4];
                inp_s[(q * 4 + 0) * 68 + r] = v.x;
                inp_s[(q * 4 + 1) * 68 + r] = v.y;
                inp_s[(q * 4 + 2) * 68 + r] = v.z;
                inp_s[(q * 4 + 3) * 68 + r] = v.w;
            }
#pragma unroll
            for (int p = 0; p < 4; p++) {
                int k = b + p * 16;
                *(float4*)&W_s[k * 68 + q * 4] =
                    *(const float4*)&W[(size_t)(k0 + k) * F_OUT + q * 4];
            }
        }
        __syncthreads();
#pragma unroll 8
        for (int kk = 0; kk < 64; kk++) {
            float4 a4 = *(const float4*)&inp_s[kk * 68 + rg * 4];
            float4 b4 = *(const float4*)&W_s[kk * 68 + cg * 4];
            float av[4] = {a4.x, a4.y, a4.z, a4.w};
            float bv[4] = {b4.x, b4.y, b4.z, b4.w};
#pragma unroll
            for (int i = 0; i < 4; i++)
#pragma unroll
                for (int j = 0; j < 4; j++) acc[i][j] += av[i] * bv[j];
        }
    }
#pragma unroll
    for (int i = 0; i < 4; i++) {
        float4 o = make_float4(acc[i][0], acc[i][1], acc[i][2], acc[i][3]);
        *(float4*)&g_h[(size_t)(row0 + rg * 4 + i) * F_OUT + cg * 4] = o;
#pragma unroll
        for (int j = 0; j < 4; j++) {
            float v = acc[i][j];
            unsigned short hb = bf16of(v);
            float fhi = __uint_as_float(((unsigned)hb) << 16);
            unsigned short lb = bf16of(v - fhi);
            size_t idx = (size_t)(cg * 4 + j) * N_NODES + row0 + rg * 4 + i;
            g_hT_hi[idx] = hb;
            g_hT_lo[idx] = lb;
        }
    }

    // fused scores: s1/s2 per row from register accumulators.
    // threads with same rg are lanes (lane&16 fixed) -> 16-lane shfl groups.
    float4 a1v = *(const float4*)&a[cg * 4];
    float4 a2v = *(const float4*)&a[64 + cg * 4];
#pragma unroll
    for (int i = 0; i < 4; i++) {
        float d1 = acc[i][0] * a1v.x + acc[i][1] * a1v.y + acc[i][2] * a1v.z + acc[i][3] * a1v.w;
        float d2 = acc[i][0] * a2v.x + acc[i][1] * a2v.y + acc[i][2] * a2v.z + acc[i][3] * a2v.w;
#pragma unroll
        for (int o = 1; o < 16; o <<= 1) {
            d1 += __shfl_xor_sync(0xffffffffu, d1, o);
            d2 += __shfl_xor_sync(0xffffffffu, d2, o);
        }
        if ((lane & 15) == 0) {
            int row = row0 + rg * 4 + i;
            g_s1[row] = d1;  g_s2[row] = d2;
            g_p1[row] = __expf(d1);
            g_q1[row] = __expf(0.2f * d1);
            g_e1[row] = __expf(-d1);
            g_r2[row] = __expf(d2);
            g_t2[row] = __expf(0.2f * d2);
        }
    }
}

// ---------------------------------------------------------------------------
// Kernel 2: fused masked attention-weight x h via tcgen05 (3-product hi/lo
// bf16, fp32 TMEM accum). Producer/consumer mbarriers per stage; NO in-loop
// __syncthreads -> warps free-run, skew absorbed by the double buffer.
//   full[st]: arrive-count 512, producers arrive after STS+proxy fence.
//   done[st]: MMA commit target; producers gate tile t on done of t-2.
// Phases on each barrier consumed strictly in order -> alias-free.
// ---------------------------------------------------------------------------
__global__ __launch_bounds__(NTHR, 1) void k_attn_tc(const int* __restrict__ adj) {
    extern __shared__ char smem[];
    const int tid  = threadIdx.x;
    const int row0 = blockIdx.x * BM;
    const int s    = blockIdx.y;
    const int jbase = s * JCHUNK;

#if HAS_TC
    const unsigned sbase = smem_u32(smem);
    const int wid  = tid >> 5;
    const int lane = tid & 31;

    if (wid == 0) tmem_alloc(sbase + SM_TMEM, 64);
    if (tid == 0) {
        mbar_init(sbase + SM_DONE, 1);        // done0
        mbar_init(sbase + SM_DONE + 8, 1);    // done1
        mbar_init(sbase + SM_FULL, NTHR);     // full0
        mbar_init(sbase + SM_FULL + 8, NTHR); // full1
    }
    __syncthreads();
    unsigned tmem;
    asm volatile("ld.shared.b32 %0, [%1];" : "=r"(tmem) : "r"(sbase + SM_TMEM));
    const unsigned doneb = sbase + SM_DONE;
    const unsigned fullb = sbase + SM_FULL;

    // phase-A mapping: warp w covers rows w*8..w*8+7; lane = r2*16 + jc:
    // thread handles rows w*8 + u*2 + r2 (u=0..3), j = jc*4..jc*4+3.
    const int r2 = lane >> 4;
    const int jc = lane & 15;

    float P[4], Q[4], E[4], lp[4];
#pragma unroll
    for (int u = 0; u < 4; u++) {
        int r = row0 + wid * 8 + u * 2 + r2;
        P[u] = g_p1[r]; Q[u] = g_q1[r]; E[u] = g_e1[r];
        lp[u] = 0.f;
    }
    const int* adjBase = adj + (size_t)(row0 + wid * 8 + r2) * N_NODES + jbase + jc * 4;

    // B staging: 512 int4 chunks per 8KB tile; one per thread
    const int bf = tid >> 3, bc = tid & 7;

    // rolling adj prefetch (tile 0)
    int4 aCur[4];
#pragma unroll
    for (int u = 0; u < 4; u++)
        aCur[u] = *(const int4*)(adjBase + (size_t)u * 2 * N_NODES);

    for (int t = 0; t < NT; t++) {
        const int j0 = jbase + t * BJ;
        const int st = t & 1;
        char* stage = smem + SM_STAGE0 + st * STAGE_SZ;
        const unsigned mbD = doneb + (st << 3);
        const unsigned mbF = fullb + (st << 3);

        // early global loads for this tile
        int4 bhi = *(const int4*)(g_hT_hi + (size_t)bf * N_NODES + j0 + bc * 8);
        int4 blo = *(const int4*)(g_hT_lo + (size_t)bf * N_NODES + j0 + bc * 8);
        float4 R4 = *(const float4*)(g_r2 + j0 + jc * 4);
        float4 T4 = *(const float4*)(g_t2 + j0 + jc * 4);

        // gate on this stage's previous MMA (tile t-2, phase (t>>1)-1)
        if (t >= 2) mbar_wait(mbD, ((t >> 1) + 1) & 1);

        *(int4*)(stage + OFF_BHI + SW(bf * 128 + bc * 16)) = bhi;
        *(int4*)(stage + OFF_BLO + SW(bf * 128 + bc * 16)) = blo;

#pragma unroll
        for (int u = 0; u < 4; u++) {
            int4 av = aCur[u];
            if (t + 1 < NT)
                aCur[u] = *(const int4*)(adjBase + (size_t)u * 2 * N_NODES + (t + 1) * BJ);

            float m0 = (R4.x > E[u]) ? P[u] : Q[u];
            float n0 = (R4.x > E[u]) ? R4.x : T4.x;
            float m1 = (R4.y > E[u]) ? P[u] : Q[u];
            float n1 = (R4.y > E[u]) ? R4.y : T4.y;
            float m2 = (R4.z > E[u]) ? P[u] : Q[u];
            float n2 = (R4.z > E[u]) ? R4.z : T4.z;
            float m3 = (R4.w > E[u]) ? P[u] : Q[u];
            float n3 = (R4.w > E[u]) ? R4.w : T4.w;
            float w0 = m0 * n0; w0 = (av.x > 0) ? w0 : 0.f;
            float w1 = m1 * n1; w1 = (av.y > 0) ? w1 : 0.f;
            float w2 = m2 * n2; w2 = (av.z > 0) ? w2 : 0.f;
            float w3 = m3 * n3; w3 = (av.w > 0) ? w3 : 0.f;
            lp[u] += (w0 + w1) + (w2 + w3);

            unsigned hh01 = pack2(w0, w1);
            unsigned hh23 = pack2(w2, w3);
            float f0 = __uint_as_float(hh01 << 16);
            float f1 = __uint_as_float(hh01 & 0xffff0000u);
            float f2 = __uint_as_float(hh23 << 16);
            float f3 = __uint_as_float(hh23 & 0xffff0000u);
            unsigned ll01 = pack2(w0 - f0, w1 - f1);
            unsigned ll23 = pack2(w2 - f2, w3 - f3);

            const int rloc = wid * 8 + u * 2 + r2;
            const unsigned aoff = SW(rloc * 128 + jc * 8);
            *(uint2*)(stage + OFF_AHI + aoff) = make_uint2(hh01, hh23);
            *(uint2*)(stage + OFF_ALO + aoff) = make_uint2(ll01, ll23);
        }

        // publish this thread's stores to the async proxy, then arrive
        fence_async_smem();
        mbar_arrive(mbF);

        // consumer: warp 0 waits all 512 arrivals, issues MMAs, commits done
        if (wid == 0) {
            mbar_wait(mbF, (t >> 1) & 1);
            if (elect_one()) {
                const unsigned sb = sbase + SM_STAGE0 + st * STAGE_SZ;
                ull dAhi = smem_desc(sb + OFF_AHI);
                ull dAlo = smem_desc(sb + OFF_ALO);
                ull dBhi = smem_desc(sb + OFF_BHI);
                ull dBlo = smem_desc(sb + OFF_BLO);
                ull aD[3] = {dAhi, dAhi, dAlo};
                ull bD[3] = {dBhi, dBlo, dBhi};
#pragma unroll
                for (int p = 0; p < 3; p++)
#pragma unroll
                    for (int k = 0; k < 4; k++)
                        mma_f16_ss(tmem, aD[p] + k * 2, bD[p] + k * 2, MMA_IDESC,
                                   !(t == 0 && p == 0 && k == 0));
                tc_commit(mbD);
            }
        }
    }

    // per-row l: reduce lp[u] across the 16 jc-lanes of each row
#pragma unroll
    for (int u = 0; u < 4; u++) {
        float v = lp[u];
        v += __shfl_xor_sync(0xffffffffu, v, 1);
        v += __shfl_xor_sync(0xffffffffu, v, 2);
        v += __shfl_xor_sync(0xffffffffu, v, 4);
        v += __shfl_xor_sync(0xffffffffu, v, 8);
        if (jc == 0)
            g_lP[s][row0 + wid * 8 + u * 2 + r2] = v;
    }

    // FULL DRAIN: last phase per done barrier = NT/2-1 = 31 (parity 1);
    // in-loop waits consumed phases <= 30, so these are next-in-order.
    mbar_wait(doneb,     ((NT / 2) - 1) & 1);
    mbar_wait(doneb + 8, ((NT / 2) - 1) & 1);
    tc_fence_after();
    if (wid < 4) {
        unsigned d0[32], d1[32];
        tmem_ld_x32(d0, tmem);
        tmem_ld_x32(d1, tmem + 32);
        tmem_wait_ld();
        tc_fence_before();
        float* dst = &g_accP[s][(size_t)(row0 + wid * 32 + lane) * F_OUT];
#pragma unroll
        for (int c = 0; c < 8; c++) {
            *(float4*)&dst[c * 4] = make_float4(
                __uint_as_float(d0[c * 4]), __uint_as_float(d0[c * 4 + 1]),
                __uint_as_float(d0[c * 4 + 2]), __uint_as_float(d0[c * 4 + 3]));
            *(float4*)&dst[32 + c * 4] = make_float4(
                __uint_as_float(d1[c * 4]), __uint_as_float(d1[c * 4 + 1]),
                __uint_as_float(d1[c * 4 + 2]), __uint_as_float(d1[c * 4 + 3]));
        }
    }
    __syncthreads();
    if (wid == 0) {
        tmem_relinquish();
        tmem_dealloc(tmem, 64);
    }

#else  // ------------------- FMA fallback (non-'a' pass) -------------------
    ull*   wT = (ull*)(smem + SMF_WT);
    float* hs = (float*)(smem + SMF_HS);

    const int rowA = tid >> 2;
    const int jh   = (tid & 3) * 8;
    const float s1r = g_s1[row0 + rowA];
    const int*   adjRow = adj + (size_t)(row0 + rowA) * N_NODES + jbase + jh;
    const float* s2p    = g_s2 + jbase + jh;
    float lpart = 0.f;

    const int rg = tid >> 4;
    const int fg = tid & 15;
    ull acc[8];
#pragma unroll
    for (int i = 0; i < 8; i++) acc[i] = 0ull;

    const int hjl = tid >> 4;
    const int hf4 = tid & 15;

    for (int t = 0; t < NT_F; t++) {
        const int jt = jbase + t * BJ_F;
        const int4* ap = (const int4*)(adjRow + t * BJ_F);
        int4 A0 = ap[0], A1 = ap[1];
        float4 S0 = *(const float4*)(s2p + t * BJ_F);
        float4 S1 = *(const float4*)(s2p + t * BJ_F + 4);
        float4 H0 = *(const float4*)&g_h[(size_t)(jt + hjl) * F_OUT + hf4 * 4];

        __syncthreads();

        *(float4*)&hs[hjl * HS_PITCH + hf4 * 4] = H0;

        int   av[8]; float sv[8];
        *(int4*)&av[0] = A0; *(int4*)&av[4] = A1;
        *(float4*)&sv[0] = S0; *(float4*)&sv[4] = S1;

#pragma unroll
        for (int jj = 0; jj < 8; jj++) {
            float e  = s1r + sv[jj];
            float le = fmaxf(e, 0.2f * e);
            float w  = __expf(le);
            w = (av[jj] > 0) ? w : 0.f;
            lpart += w;
            wT[(jh + jj) * WT_PITCH + rowA] = dup2(w);
        }
        __syncthreads();

#pragma unroll 4
        for (int jj = 0; jj < BJ_F; jj++) {
            const ulonglong2* wp = (const ulonglong2*)&wT[jj * WT_PITCH + rg * 4];
            ulonglong2 w01 = wp[0], w23 = wp[1];
            ulonglong2 hv  = *(const ulonglong2*)&hs[jj * HS_PITCH + fg * 4];
            ffma2(acc[0], w01.x, hv.x); ffma2(acc[1], w01.x, hv.y);
            ffma2(acc[2], w01.y, hv.x); ffma2(acc[3], w01.y, hv.y);
            ffma2(acc[4], w23.x, hv.x); ffma2(acc[5], w23.x, hv.y);
            ffma2(acc[6], w23.y, hv.x); ffma2(acc[7], w23.y, hv.y);
        }
    }

    float l1 = __shfl_xor_sync(0xffffffffu, lpart, 1);
    lpart += l1;
    float l2 = __shfl_xor_sync(0xffffffffu, lpart, 2);
    lpart += l2;
    if ((tid & 3) == 0) g_lP[s][row0 + rowA] = lpart;

    float* ap2 = g_accP[s];
#pragma unroll
    for (int r = 0; r < 4; r++) {
        float2 x = unpack2(acc[r * 2]);
        float2 y = unpack2(acc[r * 2 + 1]);
        float4 o = make_float4(x.x, x.y, y.x, y.y);
        *(float4*)&ap2[(size_t)(row0 + rg * 4 + r) * F_OUT + fg * 4] = o;
    }
#endif
}

// ---------------------------------------------------------------------------
// Kernel 3: out[i][f] = sum_s accP[s][i][f] / sum_s lP[s][i]  (float4)
// ---------------------------------------------------------------------------
__global__ __launch_bounds__(256) void k_norm(float* __restrict__ out) {
    const int idx = blockIdx.x * 256 + threadIdx.x;     // float4 index
    const int i = idx >> 4;                             // 16 float4 per row
    float4 v0 = ((const float4*)g_accP[0])[idx];
    float4 v1 = ((const float4*)g_accP[1])[idx];
    float inv = 1.f / (g_lP[0][i] + g_lP[1][i]);
    float4 o = make_float4((v0.x + v1.x) * inv, (v0.y + v1.y) * inv,
                           (v0.z + v1.z) * inv, (v0.w + v1.w) * inv);
    ((float4*)out)[idx] = o;
}

extern "C" void kernel_launch(void* const* d_in, const int* in_sizes, int n_in,
                              void* d_out, int out_size) {
    const float* inp = (const float*)d_in[0];
    const int*   adj = (const int*)d_in[1];
    const float* W   = (const float*)d_in[2];
    const float* a   = (const float*)d_in[3];
    float* out = (float*)d_out;

    cudaFuncSetAttribute(k_attn_tc, cudaFuncAttributeMaxDynamicSharedMemorySize, SM_TOT);

    k_hproj<<<N_NODES / 64, 256>>>(inp, W, a);
    dim3 g2(N_NODES / BM, NSPLIT);
    k_attn_tc<<<g2, NTHR, SM_TOT>>>(adj);
    k_norm<<<(N_NODES * F_OUT / 4) / 256, 256>>>(out);
}

// round 9
// speedup vs baseline: 2.7561x; 1.1649x over previous
#include <cuda_runtime.h>

#define N_NODES 8192
#define F_IN    512
#define F_OUT   64
#define NSPLIT  2
#define JCHUNK  (N_NODES / NSPLIT)   // 4096
#define BM      128
#define BJ      128
#define NT      (JCHUNK / BJ)        // 32 tiles per CTA
#define NTHR    512

// dynamic smem: header + 2 stages of 96KB
// stage: AHI 32K (two 16K j-blocks) | ALO 32K | BHI 16K (two 8K) | BLO 16K
#define SM_TMEM   0
#define SM_DONE   8                  // done0=8, done1=16
#define SM_FULL   24                 // full0=24, full1=32
#define SM_STAGE0 1024
#define STAGE_SZ  98304
#define OFF_AHI   0
#define OFF_ALO   32768
#define OFF_BHI   65536
#define OFF_BLO   81920
#define SM_TOT    (SM_STAGE0 + 2 * STAGE_SZ)   // 197632

// fallback (FMA) path smem layout inside the same dynamic buffer
#define BJ_F     32
#define NT_F     (JCHUNK / BJ_F)     // 128
#define WT_PITCH 130
#define HS_PITCH 68
#define SMF_WT   0
#define SMF_HS   (BJ_F * WT_PITCH * 8)

// idesc kind::f16: F32 accum, bf16 A/B, N=64, M=128
#define MMA_IDESC 0x08100490u

#define SW(x) ((x) ^ ((((unsigned)(x)) >> 3) & 0x70u))

#if defined(__CUDA_ARCH_FEAT_SM103_ALL) || defined(__CUDA_ARCH_FEAT_SM100_ALL) || \
    defined(__CUDA_ARCH_FEAT_SM101_ALL) || defined(__CUDA_ARCH_SPECIFIC__)
#define HAS_TC 1
#else
#define HAS_TC 0
#endif

typedef unsigned long long ull;

__device__ float          g_h[N_NODES * F_OUT];
__device__ unsigned short g_hT_hi[F_OUT * N_NODES];
__device__ unsigned short g_hT_lo[F_OUT * N_NODES];
__device__ float          g_s1[N_NODES];
__device__ float          g_s2[N_NODES];
__device__ float          g_p1[N_NODES];    // exp(s1)
__device__ float          g_q1[N_NODES];    // exp(0.2 s1)
__device__ float          g_e1[N_NODES];    // exp(-s1)
__device__ float          g_r2[N_NODES];    // exp(s2)
__device__ float          g_t2[N_NODES];    // exp(0.2 s2)
__device__ float          g_accP[NSPLIT][N_NODES * F_OUT];
__device__ float          g_lP[NSPLIT][N_NODES];

// ---------------- generic helpers ----------------
__device__ __forceinline__ unsigned smem_u32(const void* p) {
    unsigned r;
    asm("{ .reg .u64 t; cvta.to.shared.u64 t, %1; cvt.u32.u64 %0, t; }" : "=r"(r) : "l"(p));
    return r;
}
__device__ __forceinline__ unsigned short bf16of(float v) {
    unsigned short h; asm("cvt.rn.bf16.f32 %0, %1;" : "=h"(h) : "f"(v)); return h;
}
__device__ __forceinline__ void ffma2(ull &d, ull a, ull b) {
    asm("fma.rn.f32x2 %0, %1, %2, %0;" : "+l"(d) : "l"(a), "l"(b));
}
__device__ __forceinline__ ull dup2(float x) {
    ull r; asm("mov.b64 %0, {%1, %1};" : "=l"(r) : "f"(x)); return r;
}
__device__ __forceinline__ float2 unpack2(ull v) {
    float2 r; asm("mov.b64 {%0, %1}, %2;" : "=f"(r.x), "=f"(r.y) : "l"(v)); return r;
}

#if HAS_TC
// ---------------- tcgen05 helpers ('a'-pass only) ----------------
__device__ __forceinline__ unsigned elect_one() {
    unsigned p;
    asm volatile("{ .reg .pred p; elect.sync _|p, 0xFFFFFFFF; selp.b32 %0, 1, 0, p; }" : "=r"(p));
    return p;
}
__device__ __forceinline__ unsigned pack2(float a, float b) {  // lower = a, upper = b
    unsigned r; asm("cvt.rn.bf16x2.f32 %0, %2, %1;" : "=r"(r) : "f"(a), "f"(b)); return r;
}
__device__ __forceinline__ void mma_f16_ss(unsigned d, ull a, ull b, unsigned idesc, unsigned en) {
    asm volatile(
        "{ .reg .pred p; setp.ne.u32 p, %4, 0;\n\t"
        "tcgen05.mma.cta_group::1.kind::f16 [%0], %1, %2, %3, {%5,%5,%5,%5}, p; }"
        :: "r"(d), "l"(a), "l"(b), "r"(idesc), "r"(en), "r"(0u) : "memory");
}
__device__ __forceinline__ void mbar_init(unsigned m, unsigned cnt) {
    asm volatile("mbarrier.init.shared.b64 [%0], %1;" :: "r"(m), "r"(cnt) : "memory");
}
__device__ __forceinline__ void mbar_arrive(unsigned m) {
    asm volatile("mbarrier.arrive.release.cta.shared::cta.b64 _, [%0];" :: "r"(m) : "memory");
}
__device__ __forceinline__ void mbar_wait(unsigned m, unsigned parity) {
    asm volatile(
        "{ .reg .pred P;\n\t"
        "WL_%=: mbarrier.try_wait.parity.acquire.cta.shared::cta.b64 P, [%0], %1, 0x989680;\n\t"
        "@P bra.uni WD_%=;\n\t"
        "bra.uni WL_%=;\n\t"
        "WD_%=: }"
        :: "r"(m), "r"(parity) : "memory");
}
__device__ __forceinline__ void tmem_alloc(unsigned smem_dst, unsigned ncols) {
    asm volatile("tcgen05.alloc.cta_group::1.sync.aligned.shared::cta.b32 [%0], %1;"
                 :: "r"(smem_dst), "r"(ncols) : "memory");
}
__device__ __forceinline__ void tmem_dealloc(unsigned tmem, unsigned ncols) {
    asm volatile("tcgen05.dealloc.cta_group::1.sync.aligned.b32 %0, %1;" :: "r"(tmem), "r"(ncols));
}
__device__ __forceinline__ void tmem_relinquish() {
    asm volatile("tcgen05.relinquish_alloc_permit.cta_group::1.sync.aligned;");
}
__device__ __forceinline__ void tc_commit(unsigned mbar) {
    asm volatile("tcgen05.commit.cta_group::1.mbarrier::arrive::one.shared::cluster.b64 [%0];"
                 :: "r"(mbar) : "memory");
}
__device__ __forceinline__ void fence_async_smem() {
    asm volatile("fence.proxy.async.shared::cta;" ::: "memory");
}
__device__ __forceinline__ void tc_fence_after() {
    asm volatile("tcgen05.fence::after_thread_sync;" ::: "memory");
}
__device__ __forceinline__ void tc_fence_before() {
    asm volatile("tcgen05.fence::before_thread_sync;" ::: "memory");
}
__device__ __forceinline__ void tmem_ld_x32(unsigned* r, unsigned addr) {
    asm volatile(
        "tcgen05.ld.sync.aligned.32x32b.x32.b32 "
        "{%0,%1,%2,%3,%4,%5,%6,%7,%8,%9,%10,%11,%12,%13,%14,%15,"
        "%16,%17,%18,%19,%20,%21,%22,%23,%24,%25,%26,%27,%28,%29,%30,%31}, [%32];"
        : "=r"(r[0]), "=r"(r[1]), "=r"(r[2]), "=r"(r[3]), "=r"(r[4]), "=r"(r[5]), "=r"(r[6]), "=r"(r[7]),
          "=r"(r[8]), "=r"(r[9]), "=r"(r[10]), "=r"(r[11]), "=r"(r[12]), "=r"(r[13]), "=r"(r[14]), "=r"(r[15]),
          "=r"(r[16]), "=r"(r[17]), "=r"(r[18]), "=r"(r[19]), "=r"(r[20]), "=r"(r[21]), "=r"(r[22]), "=r"(r[23]),
          "=r"(r[24]), "=r"(r[25]), "=r"(r[26]), "=r"(r[27]), "=r"(r[28]), "=r"(r[29]), "=r"(r[30]), "=r"(r[31])
        : "r"(addr));
}
__device__ __forceinline__ void tmem_wait_ld() {
    asm volatile("tcgen05.wait::ld.sync.aligned;" ::: "memory");
}
static constexpr ull DESC_BASE_SW128 =
    (2ull << 61) | (1ull << 46) | (64ull << 32) | (1ull << 16);
__device__ __forceinline__ ull smem_desc(unsigned addr) {
    return DESC_BASE_SW128 | ((ull)(addr >> 4) & 0x3FFFull);
}
#endif  // HAS_TC

// ---------------------------------------------------------------------------
// Kernel 1: h = input @ W (32 rows/CTA -> grid 256, 2 CTAs/SM), bf16 hi/lo
// transposed copies, fused s1/s2 + factorized-exp tables.
// ---------------------------------------------------------------------------
__global__ __launch_bounds__(256) void k_hproj(const float* __restrict__ inp,
                                               const float* __restrict__ W,
                                               const float* __restrict__ a) {
    __shared__ float inp_s[64 * 36];   // [k][row], 32 rows + pad
    __shared__ float W_s[64 * 68];     // [k][col]
    const int tid  = threadIdx.x;
    const int row0 = blockIdx.x * 32;
    const int rg = tid >> 4;           // 0..15 -> rows rg*2..+1
    const int cg = tid & 15;           // cols cg*4..+3
    const int lane = tid & 31;

    float acc[2][4];
#pragma unroll
    for (int i = 0; i < 2; i++)
#pragma unroll
        for (int j = 0; j < 4; j++) acc[i][j] = 0.f;

    for (int k0 = 0; k0 < F_IN; k0 += 64) {
        __syncthreads();
        {
            const int q = tid & 15;
            const int b = tid >> 4;
#pragma unroll
            for (int p = 0; p < 2; p++) {
                int r = b + p * 16;
                float4 v = *(const float4*)&inp[(size_t)(row0 + r) * F_IN + k0 + q * 4];
                inp_s[(q * 4 + 0) * 36 + r] = v.x;
                inp_s[(q * 4 + 1) * 36 + r] = v.y;
                inp_s[(q * 4 + 2) * 36 + r] = v.z;
                inp_s[(q * 4 + 3) * 36 + r] = v.w;
            }
#pragma unroll
            for (int p = 0; p < 4; p++) {
                int k = b + p * 16;
                *(float4*)&W_s[k * 68 + q * 4] =
                    *(const float4*)&W[(size_t)(k0 + k) * F_OUT + q * 4];
            }
        }
        __syncthreads();
#pragma unroll 8
        for (int kk = 0; kk < 64; kk++) {
            float2 a2 = *(const float2*)&inp_s[kk * 36 + rg * 2];
            float4 b4 = *(const float4*)&W_s[kk * 68 + cg * 4];
            float av[2] = {a2.x, a2.y};
            float bv[4] = {b4.x, b4.y, b4.z, b4.w};
#pragma unroll
            for (int i = 0; i < 2; i++)
#pragma unroll
                for (int j = 0; j < 4; j++) acc[i][j] += av[i] * bv[j];
        }
    }
#pragma unroll
    for (int i = 0; i < 2; i++) {
        float4 o = make_float4(acc[i][0], acc[i][1], acc[i][2], acc[i][3]);
        *(float4*)&g_h[(size_t)(row0 + rg * 2 + i) * F_OUT + cg * 4] = o;
#pragma unroll
        for (int j = 0; j < 4; j++) {
            float v = acc[i][j];
            unsigned short hb = bf16of(v);
            float fhi = __uint_as_float(((unsigned)hb) << 16);
            unsigned short lb = bf16of(v - fhi);
            size_t idx = (size_t)(cg * 4 + j) * N_NODES + row0 + rg * 2 + i;
            g_hT_hi[idx] = hb;
            g_hT_lo[idx] = lb;
        }
    }

    // fused scores (16-lane groups share a row)
    float4 a1v = *(const float4*)&a[cg * 4];
    float4 a2v = *(const float4*)&a[64 + cg * 4];
#pragma unroll
    for (int i = 0; i < 2; i++) {
        float d1 = acc[i][0] * a1v.x + acc[i][1] * a1v.y + acc[i][2] * a1v.z + acc[i][3] * a1v.w;
        float d2 = acc[i][0] * a2v.x + acc[i][1] * a2v.y + acc[i][2] * a2v.z + acc[i][3] * a2v.w;
#pragma unroll
        for (int o = 1; o < 16; o <<= 1) {
            d1 += __shfl_xor_sync(0xffffffffu, d1, o);
            d2 += __shfl_xor_sync(0xffffffffu, d2, o);
        }
        if ((lane & 15) == 0) {
            int row = row0 + rg * 2 + i;
            g_s1[row] = d1;  g_s2[row] = d2;
            g_p1[row] = __expf(d1);
            g_q1[row] = __expf(0.2f * d1);
            g_e1[row] = __expf(-d1);
            g_r2[row] = __expf(d2);
            g_t2[row] = __expf(0.2f * d2);
        }
    }
}

// ---------------------------------------------------------------------------
// Kernel 2: fused masked attention-weight x h via tcgen05. BJ=128 tiles
// (two 64-j SW128 column blocks per operand). Producer/consumer mbarriers,
// per-warp elected arrives (full count = 16). No in-loop __syncthreads.
// ---------------------------------------------------------------------------
__global__ __launch_bounds__(NTHR, 1) void k_attn_tc(const int* __restrict__ adj) {
    extern __shared__ char smem[];
    const int tid  = threadIdx.x;
    const int row0 = blockIdx.x * BM;
    const int s    = blockIdx.y;
    const int jbase = s * JCHUNK;

#if HAS_TC
    const unsigned sbase = smem_u32(smem);
    const int wid  = tid >> 5;
    const int lane = tid & 31;

    if (wid == 0) tmem_alloc(sbase + SM_TMEM, 64);
    if (tid == 0) {
        mbar_init(sbase + SM_DONE, 1);        // done0
        mbar_init(sbase + SM_DONE + 8, 1);    // done1
        mbar_init(sbase + SM_FULL, 16);       // full0 (one arrive per warp)
        mbar_init(sbase + SM_FULL + 8, 16);   // full1
    }
    __syncthreads();
    unsigned tmem;
    asm volatile("ld.shared.b32 %0, [%1];" : "=r"(tmem) : "r"(sbase + SM_TMEM));
    const unsigned doneb = sbase + SM_DONE;
    const unsigned fullb = sbase + SM_FULL;

    // phase-A mapping: warp w covers rows w*8..w*8+7; lane = r2*16 + jc.
    // thread: rows w*8 + u*2 + r2 (u=0..3), j = jc*8 .. jc*8+7 (fixed).
    const int r2 = lane >> 4;
    const int jc = lane & 15;
    const int jblk = jc >> 3;                 // A column block (0/1)
    const unsigned aoffbase = jblk * 16384 + (jc & 7) * 16;

    float P[4], Q[4], E[4], lp[4];
#pragma unroll
    for (int u = 0; u < 4; u++) {
        int r = row0 + wid * 8 + u * 2 + r2;
        P[u] = g_p1[r]; Q[u] = g_q1[r]; E[u] = g_e1[r];
        lp[u] = 0.f;
    }
    const int* adjBase = adj + (size_t)(row0 + wid * 8 + r2) * N_NODES + jbase + jc * 8;

    // B staging: 1024 int4 per 16KB hi/lo tile; 2 chunks per thread
    // chunk c: block = c>>9, feat = (c>>3)&63, unit = c&7;  c0 = tid, c1 = tid+512
    const int bfeat = tid >> 3, bunit = tid & 7;
    const unsigned boff0 = SW(bfeat * 128 + bunit * 16);           // block 0
    const unsigned boff1 = 8192 + boff0;                            // block 1

    // R/T for this thread's fixed j-range are reloaded per tile (L2-resident)

    // rolling adj prefetch (tile 0): 8 int4 (rows u=0..3, each 2 int4)
    int4 aCur[8];
#pragma unroll
    for (int u = 0; u < 4; u++) {
        aCur[u * 2]     = *(const int4*)(adjBase + (size_t)u * 2 * N_NODES);
        aCur[u * 2 + 1] = *(const int4*)(adjBase + (size_t)u * 2 * N_NODES + 4);
    }

    for (int t = 0; t < NT; t++) {
        const int j0 = jbase + t * BJ;
        const int st = t & 1;
        char* stage = smem + SM_STAGE0 + st * STAGE_SZ;
        const unsigned mbD = doneb + (st << 3);
        const unsigned mbF = fullb + (st << 3);

        // early global loads for this tile
        int4 bhi0 = *(const int4*)(g_hT_hi + (size_t)bfeat * N_NODES + j0 + bunit * 8);
        int4 bhi1 = *(const int4*)(g_hT_hi + (size_t)bfeat * N_NODES + j0 + 64 + bunit * 8);
        int4 blo0 = *(const int4*)(g_hT_lo + (size_t)bfeat * N_NODES + j0 + bunit * 8);
        int4 blo1 = *(const int4*)(g_hT_lo + (size_t)bfeat * N_NODES + j0 + 64 + bunit * 8);
        float4 R4a = *(const float4*)(g_r2 + j0 + jc * 8);
        float4 R4b = *(const float4*)(g_r2 + j0 + jc * 8 + 4);
        float4 T4a = *(const float4*)(g_t2 + j0 + jc * 8);
        float4 T4b = *(const float4*)(g_t2 + j0 + jc * 8 + 4);

        // gate on this stage's previous MMA (tile t-2, phase (t>>1)-1)
        if (t >= 2) mbar_wait(mbD, ((t >> 1) + 1) & 1);

        *(int4*)(stage + OFF_BHI + boff0) = bhi0;
        *(int4*)(stage + OFF_BHI + boff1) = bhi1;
        *(int4*)(stage + OFF_BLO + boff0) = blo0;
        *(int4*)(stage + OFF_BLO + boff1) = blo1;

#pragma unroll
        for (int u = 0; u < 4; u++) {
            int4 av0 = aCur[u * 2];
            int4 av1 = aCur[u * 2 + 1];
            if (t + 1 < NT) {
                aCur[u * 2]     = *(const int4*)(adjBase + (size_t)u * 2 * N_NODES + (t + 1) * BJ);
                aCur[u * 2 + 1] = *(const int4*)(adjBase + (size_t)u * 2 * N_NODES + (t + 1) * BJ + 4);
            }

            float w[8];
            {
                float m, n;
                m = (R4a.x > E[u]) ? P[u] : Q[u]; n = (R4a.x > E[u]) ? R4a.x : T4a.x;
                w[0] = (av0.x > 0) ? m * n : 0.f;
                m = (R4a.y > E[u]) ? P[u] : Q[u]; n = (R4a.y > E[u]) ? R4a.y : T4a.y;
                w[1] = (av0.y > 0) ? m * n : 0.f;
                m = (R4a.z > E[u]) ? P[u] : Q[u]; n = (R4a.z > E[u]) ? R4a.z : T4a.z;
                w[2] = (av0.z > 0) ? m * n : 0.f;
                m = (R4a.w > E[u]) ? P[u] : Q[u]; n = (R4a.w > E[u]) ? R4a.w : T4a.w;
                w[3] = (av0.w > 0) ? m * n : 0.f;
                m = (R4b.x > E[u]) ? P[u] : Q[u]; n = (R4b.x > E[u]) ? R4b.x : T4b.x;
                w[4] = (av1.x > 0) ? m * n : 0.f;
                m = (R4b.y > E[u]) ? P[u] : Q[u]; n = (R4b.y > E[u]) ? R4b.y : T4b.y;
                w[5] = (av1.y > 0) ? m * n : 0.f;
                m = (R4b.z > E[u]) ? P[u] : Q[u]; n = (R4b.z > E[u]) ? R4b.z : T4b.z;
                w[6] = (av1.z > 0) ? m * n : 0.f;
                m = (R4b.w > E[u]) ? P[u] : Q[u]; n = (R4b.w > E[u]) ? R4b.w : T4b.w;
                w[7] = (av1.w > 0) ? m * n : 0.f;
            }
            lp[u] += ((w[0] + w[1]) + (w[2] + w[3])) + ((w[4] + w[5]) + (w[6] + w[7]));

            unsigned hh[4], ll[4];
#pragma unroll
            for (int p = 0; p < 4; p++) {
                unsigned h = pack2(w[p * 2], w[p * 2 + 1]);
                float fa = __uint_as_float(h << 16);
                float fb = __uint_as_float(h & 0xffff0000u);
                hh[p] = h;
                ll[p] = pack2(w[p * 2] - fa, w[p * 2 + 1] - fb);
            }

            const int rloc = wid * 8 + u * 2 + r2;
            const unsigned aoff = jblk * 16384 + SW(rloc * 128 + (jc & 7) * 16);
            *(int4*)(stage + OFF_AHI + aoff) = make_int4(hh[0], hh[1], hh[2], hh[3]);
            *(int4*)(stage + OFF_ALO + aoff) = make_int4(ll[0], ll[1], ll[2], ll[3]);
        }

        // publish stores to async proxy; per-warp elected arrive
        fence_async_smem();
        __syncwarp();
        if (elect_one()) mbar_arrive(mbF);

        // consumer: warp 0 waits all 16 warp-arrivals, issues MMAs
        if (wid == 0) {
            mbar_wait(mbF, (t >> 1) & 1);
            if (elect_one()) {
                const unsigned sb = sbase + SM_STAGE0 + st * STAGE_SZ;
                ull dA[3] = {smem_desc(sb + OFF_AHI), smem_desc(sb + OFF_AHI),
                             smem_desc(sb + OFF_ALO)};
                ull dB[3] = {smem_desc(sb + OFF_BHI), smem_desc(sb + OFF_BLO),
                             smem_desc(sb + OFF_BHI)};
#pragma unroll
                for (int p = 0; p < 3; p++)
#pragma unroll
                    for (int k = 0; k < 8; k++) {
                        ull oa = (k < 4) ? (ull)(k * 2) : (ull)(1024 + (k - 4) * 2);
                        ull ob = (k < 4) ? (ull)(k * 2) : (ull)(512 + (k - 4) * 2);
                        mma_f16_ss(tmem, dA[p] + oa, dB[p] + ob, MMA_IDESC,
                                   !(t == 0 && p == 0 && k == 0));
                    }
                tc_commit(mbD);
            }
        }
    }

    // per-row l: reduce lp[u] across the 16 jc-lanes of each row
#pragma unroll
    for (int u = 0; u < 4; u++) {
        float v = lp[u];
        v += __shfl_xor_sync(0xffffffffu, v, 1);
        v += __shfl_xor_sync(0xffffffffu, v, 2);
        v += __shfl_xor_sync(0xffffffffu, v, 4);
        v += __shfl_xor_sync(0xffffffffu, v, 8);
        if (jc == 0)
            g_lP[s][row0 + wid * 8 + u * 2 + r2] = v;
    }

    // FULL DRAIN: last phase per done barrier = NT/2-1 = 15 (parity 1);
    // in-loop waits consumed phases <= 14, so these are next-in-order.
    mbar_wait(doneb,     ((NT / 2) - 1) & 1);
    mbar_wait(doneb + 8, ((NT / 2) - 1) & 1);
    tc_fence_after();
    if (wid < 4) {
        unsigned d0[32], d1[32];
        tmem_ld_x32(d0, tmem);
        tmem_ld_x32(d1, tmem + 32);
        tmem_wait_ld();
        tc_fence_before();
        float* dst = &g_accP[s][(size_t)(row0 + wid * 32 + lane) * F_OUT];
#pragma unroll
        for (int c = 0; c < 8; c++) {
            *(float4*)&dst[c * 4] = make_float4(
                __uint_as_float(d0[c * 4]), __uint_as_float(d0[c * 4 + 1]),
                __uint_as_float(d0[c * 4 + 2]), __uint_as_float(d0[c * 4 + 3]));
            *(float4*)&dst[32 + c * 4] = make_float4(
                __uint_as_float(d1[c * 4]), __uint_as_float(d1[c * 4 + 1]),
                __uint_as_float(d1[c * 4 + 2]), __uint_as_float(d1[c * 4 + 3]));
        }
    }
    __syncthreads();
    if (wid == 0) {
        tmem_relinquish();
        tmem_dealloc(tmem, 64);
    }

#else  // ------------------- FMA fallback (non-'a' pass) -------------------
    ull*   wT = (ull*)(smem + SMF_WT);
    float* hs = (float*)(smem + SMF_HS);

    const int rowA = tid >> 2;
    const int jh   = (tid & 3) * 8;
    const float s1r = g_s1[row0 + rowA];
    const int*   adjRow = adj + (size_t)(row0 + rowA) * N_NODES + jbase + jh;
    const float* s2p    = g_s2 + jbase + jh;
    float lpart = 0.f;

    const int rg = tid >> 4;
    const int fg = tid & 15;
    ull acc[8];
#pragma unroll
    for (int i = 0; i < 8; i++) acc[i] = 0ull;

    const int hjl = tid >> 4;
    const int hf4 = tid & 15;

    for (int t = 0; t < NT_F; t++) {
        const int jt = jbase + t * BJ_F;
        const int4* ap = (const int4*)(adjRow + t * BJ_F);
        int4 A0 = ap[0], A1 = ap[1];
        float4 S0 = *(const float4*)(s2p + t * BJ_F);
        float4 S1 = *(const float4*)(s2p + t * BJ_F + 4);
        float4 H0 = *(const float4*)&g_h[(size_t)(jt + hjl) * F_OUT + hf4 * 4];

        __syncthreads();

        *(float4*)&hs[hjl * HS_PITCH + hf4 * 4] = H0;

        int   av[8]; float sv[8];
        *(int4*)&av[0] = A0; *(int4*)&av[4] = A1;
        *(float4*)&sv[0] = S0; *(float4*)&sv[4] = S1;

#pragma unroll
        for (int jj = 0; jj < 8; jj++) {
            float e  = s1r + sv[jj];
            float le = fmaxf(e, 0.2f * e);
            float w  = __expf(le);
            w = (av[jj] > 0) ? w : 0.f;
            lpart += w;
            wT[(jh + jj) * WT_PITCH + rowA] = dup2(w);
        }
        __syncthreads();

#pragma unroll 4
        for (int jj = 0; jj < BJ_F; jj++) {
            const ulonglong2* wp = (const ulonglong2*)&wT[jj * WT_PITCH + rg * 4];
            ulonglong2 w01 = wp[0], w23 = wp[1];
            ulonglong2 hv  = *(const ulonglong2*)&hs[jj * HS_PITCH + fg * 4];
            ffma2(acc[0], w01.x, hv.x); ffma2(acc[1], w01.x, hv.y);
            ffma2(acc[2], w01.y, hv.x); ffma2(acc[3], w01.y, hv.y);
            ffma2(acc[4], w23.x, hv.x); ffma2(acc[5], w23.x, hv.y);
            ffma2(acc[6], w23.y, hv.x); ffma2(acc[7], w23.y, hv.y);
        }
    }

    float l1 = __shfl_xor_sync(0xffffffffu, lpart, 1);
    lpart += l1;
    float l2 = __shfl_xor_sync(0xffffffffu, lpart, 2);
    lpart += l2;
    if ((tid & 3) == 0) g_lP[s][row0 + rowA] = lpart;

    float* ap2 = g_accP[s];
#pragma unroll
    for (int r = 0; r < 4; r++) {
        float2 x = unpack2(acc[r * 2]);
        float2 y = unpack2(acc[r * 2 + 1]);
        float4 o = make_float4(x.x, x.y, y.x, y.y);
        *(float4*)&ap2[(size_t)(row0 + rg * 4 + r) * F_OUT + fg * 4] = o;
    }
#endif
}

// ---------------------------------------------------------------------------
// Kernel 3: out[i][f] = sum_s accP[s][i][f] / sum_s lP[s][i]  (float4)
// ---------------------------------------------------------------------------
__global__ __launch_bounds__(256) void k_norm(float* __restrict__ out) {
    const int idx = blockIdx.x * 256 + threadIdx.x;     // float4 index
    const int i = idx >> 4;                             // 16 float4 per row
    float4 v0 = ((const float4*)g_accP[0])[idx];
    float4 v1 = ((const float4*)g_accP[1])[idx];
    float inv = 1.f / (g_lP[0][i] + g_lP[1][i]);
    float4 o = make_float4((v0.x + v1.x) * inv, (v0.y + v1.y) * inv,
                           (v0.z + v1.z) * inv, (v0.w + v1.w) * inv);
    ((float4*)out)[idx] = o;
}

extern "C" void kernel_launch(void* const* d_in, const int* in_sizes, int n_in,
                              void* d_out, int out_size) {
    const float* inp = (const float*)d_in[0];
    const int*   adj = (const int*)d_in[1];
    const float* W   = (const float*)d_in[2];
    const float* a   = (const float*)d_in[3];
    float* out = (float*)d_out;

    cudaFuncSetAttribute(k_attn_tc, cudaFuncAttributeMaxDynamicSharedMemorySize, SM_TOT);

    k_hproj<<<N_NODES / 32, 256>>>(inp, W, a);
    dim3 g2(N_NODES / BM, NSPLIT);
    k_attn_tc<<<g2, NTHR, SM_TOT>>>(adj);
    k_norm<<<(N_NODES * F_OUT / 4) / 256, 256>>>(out);
}

// round 10
// speedup vs baseline: 3.1066x; 1.1272x over previous
#include <cuda_runtime.h>

#define N_NODES 8192
#define F_IN    512
#define F_OUT   64
#define NSPLIT  2
#define JCHUNK  (N_NODES / NSPLIT)   // 4096
#define BM      128
#define BJ      128
#define NT      (JCHUNK / BJ)        // 32 tiles per CTA
#define NTHR    512

// ---- k_attn smem: header + 2 stages of 96KB ----
#define SM_TMEM   0
#define SM_DONE   8                  // done0=8, done1=16
#define SM_FULL   24                 // full0=24, full1=32
#define SM_STAGE0 1024
#define STAGE_SZ  98304
#define OFF_AHI   0
#define OFF_ALO   32768
#define OFF_BHI   65536
#define OFF_BLO   81920
#define SM_TOT    (SM_STAGE0 + 2 * STAGE_SZ)   // 197632

// ---- k_hproj_tc smem: header + 2 stages of 48KB ----
#define HP_STAGE_SZ 49152
#define HP_AHI   0
#define HP_ALO   16384
#define HP_BHI   32768
#define HP_BLO   40960
#define HP_NT    8                   // 8 K-tiles of 64
#define HP_SMTOT (SM_STAGE0 + 2 * HP_STAGE_SZ) // 99328

// fallback (FMA) path smem layout inside the same dynamic buffer
#define BJ_F     32
#define NT_F     (JCHUNK / BJ_F)     // 128
#define WT_PITCH 130
#define HS_PITCH 68
#define SMF_WT   0
#define SMF_HS   (BJ_F * WT_PITCH * 8)

// idesc kind::f16: F32 accum, bf16 A/B, N=64, M=128
#define MMA_IDESC 0x08100490u

#define SW(x) ((x) ^ ((((unsigned)(x)) >> 3) & 0x70u))

#if defined(__CUDA_ARCH_FEAT_SM103_ALL) || defined(__CUDA_ARCH_FEAT_SM100_ALL) || \
    defined(__CUDA_ARCH_FEAT_SM101_ALL) || defined(__CUDA_ARCH_SPECIFIC__)
#define HAS_TC 1
#else
#define HAS_TC 0
#endif

typedef unsigned long long ull;

__device__ float          g_h[N_NODES * F_OUT];
__device__ unsigned short g_hT_hi[F_OUT * N_NODES];
__device__ unsigned short g_hT_lo[F_OUT * N_NODES];
__device__ unsigned short g_wT_hi[F_OUT * F_IN];   // [n][k] K-major
__device__ unsigned short g_wT_lo[F_OUT * F_IN];
__device__ float          g_s1[N_NODES];
__device__ float          g_s2[N_NODES];
__device__ float          g_p1[N_NODES];    // exp(s1)
__device__ float          g_q1[N_NODES];    // exp(0.2 s1)
__device__ float          g_e1[N_NODES];    // exp(-s1)
__device__ float          g_r2[N_NODES];    // exp(s2)
__device__ float          g_t2[N_NODES];    // exp(0.2 s2)
__device__ float          g_accP[NSPLIT][N_NODES * F_OUT];
__device__ float          g_lP[NSPLIT][N_NODES];

// ---------------- generic helpers ----------------
__device__ __forceinline__ unsigned smem_u32(const void* p) {
    unsigned r;
    asm("{ .reg .u64 t; cvta.to.shared.u64 t, %1; cvt.u32.u64 %0, t; }" : "=r"(r) : "l"(p));
    return r;
}
__device__ __forceinline__ unsigned short bf16of(float v) {
    unsigned short h; asm("cvt.rn.bf16.f32 %0, %1;" : "=h"(h) : "f"(v)); return h;
}
__device__ __forceinline__ void ffma2(ull &d, ull a, ull b) {
    asm("fma.rn.f32x2 %0, %1, %2, %0;" : "+l"(d) : "l"(a), "l"(b));
}
__device__ __forceinline__ ull dup2(float x) {
    ull r; asm("mov.b64 %0, {%1, %1};" : "=l"(r) : "f"(x)); return r;
}
__device__ __forceinline__ float2 unpack2(ull v) {
    float2 r; asm("mov.b64 {%0, %1}, %2;" : "=f"(r.x), "=f"(r.y) : "l"(v)); return r;
}

#if HAS_TC
// ---------------- tcgen05 helpers ('a'-pass only) ----------------
__device__ __forceinline__ unsigned elect_one() {
    unsigned p;
    asm volatile("{ .reg .pred p; elect.sync _|p, 0xFFFFFFFF; selp.b32 %0, 1, 0, p; }" : "=r"(p));
    return p;
}
__device__ __forceinline__ unsigned pack2(float a, float b) {  // lower = a, upper = b
    unsigned r; asm("cvt.rn.bf16x2.f32 %0, %2, %1;" : "=r"(r) : "f"(a), "f"(b)); return r;
}
__device__ __forceinline__ void mma_f16_ss(unsigned d, ull a, ull b, unsigned idesc, unsigned en) {
    asm volatile(
        "{ .reg .pred p; setp.ne.u32 p, %4, 0;\n\t"
        "tcgen05.mma.cta_group::1.kind::f16 [%0], %1, %2, %3, {%5,%5,%5,%5}, p; }"
        :: "r"(d), "l"(a), "l"(b), "r"(idesc), "r"(en), "r"(0u) : "memory");
}
__device__ __forceinline__ void mbar_init(unsigned m, unsigned cnt) {
    asm volatile("mbarrier.init.shared.b64 [%0], %1;" :: "r"(m), "r"(cnt) : "memory");
}
__device__ __forceinline__ void mbar_arrive(unsigned m) {
    asm volatile("mbarrier.arrive.release.cta.shared::cta.b64 _, [%0];" :: "r"(m) : "memory");
}
__device__ __forceinline__ void mbar_wait(unsigned m, unsigned parity) {
    asm volatile(
        "{ .reg .pred P;\n\t"
        "WL_%=: mbarrier.try_wait.parity.acquire.cta.shared::cta.b64 P, [%0], %1, 0x989680;\n\t"
        "@P bra.uni WD_%=;\n\t"
        "bra.uni WL_%=;\n\t"
        "WD_%=: }"
        :: "r"(m), "r"(parity) : "memory");
}
__device__ __forceinline__ void tmem_alloc(unsigned smem_dst, unsigned ncols) {
    asm volatile("tcgen05.alloc.cta_group::1.sync.aligned.shared::cta.b32 [%0], %1;"
                 :: "r"(smem_dst), "r"(ncols) : "memory");
}
__device__ __forceinline__ void tmem_dealloc(unsigned tmem, unsigned ncols) {
    asm volatile("tcgen05.dealloc.cta_group::1.sync.aligned.b32 %0, %1;" :: "r"(tmem), "r"(ncols));
}
__device__ __forceinline__ void tmem_relinquish() {
    asm volatile("tcgen05.relinquish_alloc_permit.cta_group::1.sync.aligned;");
}
__device__ __forceinline__ void tc_commit(unsigned mbar) {
    asm volatile("tcgen05.commit.cta_group::1.mbarrier::arrive::one.shared::cluster.b64 [%0];"
                 :: "r"(mbar) : "memory");
}
__device__ __forceinline__ void fence_async_smem() {
    asm volatile("fence.proxy.async.shared::cta;" ::: "memory");
}
__device__ __forceinline__ void tc_fence_after() {
    asm volatile("tcgen05.fence::after_thread_sync;" ::: "memory");
}
__device__ __forceinline__ void tc_fence_before() {
    asm volatile("tcgen05.fence::before_thread_sync;" ::: "memory");
}
__device__ __forceinline__ void tmem_ld_x32(unsigned* r, unsigned addr) {
    asm volatile(
        "tcgen05.ld.sync.aligned.32x32b.x32.b32 "
        "{%0,%1,%2,%3,%4,%5,%6,%7,%8,%9,%10,%11,%12,%13,%14,%15,"
        "%16,%17,%18,%19,%20,%21,%22,%23,%24,%25,%26,%27,%28,%29,%30,%31}, [%32];"
        : "=r"(r[0]), "=r"(r[1]), "=r"(r[2]), "=r"(r[3]), "=r"(r[4]), "=r"(r[5]), "=r"(r[6]), "=r"(r[7]),
          "=r"(r[8]), "=r"(r[9]), "=r"(r[10]), "=r"(r[11]), "=r"(r[12]), "=r"(r[13]), "=r"(r[14]), "=r"(r[15]),
          "=r"(r[16]), "=r"(r[17]), "=r"(r[18]), "=r"(r[19]), "=r"(r[20]), "=r"(r[21]), "=r"(r[22]), "=r"(r[23]),
          "=r"(r[24]), "=r"(r[25]), "=r"(r[26]), "=r"(r[27]), "=r"(r[28]), "=r"(r[29]), "=r"(r[30]), "=r"(r[31])
        : "r"(addr));
}
__device__ __forceinline__ void tmem_wait_ld() {
    asm volatile("tcgen05.wait::ld.sync.aligned;" ::: "memory");
}
static constexpr ull DESC_BASE_SW128 =
    (2ull << 61) | (1ull << 46) | (64ull << 32) | (1ull << 16);
__device__ __forceinline__ ull smem_desc(unsigned addr) {
    return DESC_BASE_SW128 | ((ull)(addr >> 4) & 0x3FFFull);
}
#endif  // HAS_TC

// ---------------------------------------------------------------------------
// Kernel 0: W[512][64] -> transposed bf16 hi/lo [64][512] (K-major, MMA-ready)
// ---------------------------------------------------------------------------
__global__ __launch_bounds__(512) void k_wprep(const float* __restrict__ W) {
    int e = blockIdx.x * 512 + threadIdx.x;   // 0..32767
    int k = e >> 6, n = e & 63;
    float v = W[e];
    unsigned short hb = bf16of(v);
    float fhi = __uint_as_float(((unsigned)hb) << 16);
    unsigned short lb = bf16of(v - fhi);
    g_wT_hi[n * F_IN + k] = hb;
    g_wT_lo[n * F_IN + k] = lb;
}

// ---------------------------------------------------------------------------
// Kernel 1: h = input @ W via tcgen05 (hi/lo bf16 3-product, fp32 TMEM).
// 64 CTAs x 128 rows; 8 K-tiles of 64. Epilogue writes g_h, hT hi/lo
// (coalesced: lane = row), and fused s1/s2 + exp tables (row in registers).
// ---------------------------------------------------------------------------
__global__ __launch_bounds__(NTHR, 1) void k_hproj_tc(const float* __restrict__ inp,
                                                      const float* __restrict__ W,
                                                      const float* __restrict__ a) {
    extern __shared__ char smem[];
    const int tid  = threadIdx.x;
    const int row0 = blockIdx.x * 128;

#if HAS_TC
    const unsigned sbase = smem_u32(smem);
    const int wid  = tid >> 5;
    const int lane = tid & 31;

    if (wid == 0) tmem_alloc(sbase + SM_TMEM, 64);
    if (tid == 0) {
        mbar_init(sbase + SM_DONE, 1);
        mbar_init(sbase + SM_DONE + 8, 1);
        mbar_init(sbase + SM_FULL, 16);
        mbar_init(sbase + SM_FULL + 8, 16);
    }
    __syncthreads();
    unsigned tmem;
    asm volatile("ld.shared.b32 %0, [%1];" : "=r"(tmem) : "r"(sbase + SM_TMEM));
    const unsigned doneb = sbase + SM_DONE;
    const unsigned fullb = sbase + SM_FULL;

    // A mapping: r = tid>>2 (0..127), kq = tid&3 -> 16 k-values
    const int r  = tid >> 2;
    const int kq = tid & 3;
    const float* inRow = inp + (size_t)(row0 + r) * F_IN + kq * 16;
    const unsigned aoff0 = SW(r * 128 + kq * 32);
    const unsigned aoff1 = SW(r * 128 + kq * 32 + 16);

    // B mapping: bn = tid>>3 (0..63), bu = tid&7 -> int4 of 8 bf16
    const int bn = tid >> 3, bu = tid & 7;
    const unsigned boff = SW(bn * 128 + bu * 16);
    const unsigned short* wHiP = g_wT_hi + (size_t)bn * F_IN + bu * 8;
    const unsigned short* wLoP = g_wT_lo + (size_t)bn * F_IN + bu * 8;

    for (int kt = 0; kt < HP_NT; kt++) {
        const int st = kt & 1;
        char* stage = smem + SM_STAGE0 + st * HP_STAGE_SZ;
        const unsigned mbD = doneb + (st << 3);
        const unsigned mbF = fullb + (st << 3);

        float4 x0 = *(const float4*)(inRow + kt * 64);
        float4 x1 = *(const float4*)(inRow + kt * 64 + 4);
        float4 x2 = *(const float4*)(inRow + kt * 64 + 8);
        float4 x3 = *(const float4*)(inRow + kt * 64 + 12);
        int4 whi = *(const int4*)(wHiP + kt * 64);
        int4 wlo = *(const int4*)(wLoP + kt * 64);

        if (kt >= 2) mbar_wait(mbD, ((kt >> 1) + 1) & 1);

        *(int4*)(stage + HP_BHI + boff) = whi;
        *(int4*)(stage + HP_BLO + boff) = wlo;

        float f[16];
        *(float4*)&f[0] = x0; *(float4*)&f[4] = x1;
        *(float4*)&f[8] = x2; *(float4*)&f[12] = x3;
        unsigned hh[8], ll[8];
#pragma unroll
        for (int i = 0; i < 8; i++) {
            unsigned h = pack2(f[i * 2], f[i * 2 + 1]);
            float fa = __uint_as_float(h << 16);
            float fb = __uint_as_float(h & 0xffff0000u);
            hh[i] = h;
            ll[i] = pack2(f[i * 2] - fa, f[i * 2 + 1] - fb);
        }
        *(int4*)(stage + HP_AHI + aoff0) = make_int4(hh[0], hh[1], hh[2], hh[3]);
        *(int4*)(stage + HP_AHI + aoff1) = make_int4(hh[4], hh[5], hh[6], hh[7]);
        *(int4*)(stage + HP_ALO + aoff0) = make_int4(ll[0], ll[1], ll[2], ll[3]);
        *(int4*)(stage + HP_ALO + aoff1) = make_int4(ll[4], ll[5], ll[6], ll[7]);

        fence_async_smem();
        __syncwarp();
        if (elect_one()) mbar_arrive(mbF);

        if (wid == 0) {
            mbar_wait(mbF, (kt >> 1) & 1);
            if (elect_one()) {
                const unsigned sb = sbase + SM_STAGE0 + st * HP_STAGE_SZ;
                ull dA[3] = {smem_desc(sb + HP_AHI), smem_desc(sb + HP_AHI),
                             smem_desc(sb + HP_ALO)};
                ull dB[3] = {smem_desc(sb + HP_BHI), smem_desc(sb + HP_BLO),
                             smem_desc(sb + HP_BHI)};
#pragma unroll
                for (int p = 0; p < 3; p++)
#pragma unroll
                    for (int k = 0; k < 4; k++)
                        mma_f16_ss(tmem, dA[p] + k * 2, dB[p] + k * 2, MMA_IDESC,
                                   !(kt == 0 && p == 0 && k == 0));
                tc_commit(mbD);
            }
        }
    }

    // drain: each done barrier: 4 commits, consumed phases <= 2; wait phase 3
    mbar_wait(doneb,     ((HP_NT / 2) - 1) & 1);
    mbar_wait(doneb + 8, ((HP_NT / 2) - 1) & 1);
    tc_fence_after();
    if (wid < 4) {
        unsigned d0[32], d1[32];
        tmem_ld_x32(d0, tmem);
        tmem_ld_x32(d1, tmem + 32);
        tmem_wait_ld();
        tc_fence_before();
        const int row = row0 + wid * 32 + lane;

        // g_h row (16 float4)
        float* hrow = &g_h[(size_t)row * F_OUT];
#pragma unroll
        for (int c = 0; c < 8; c++) {
            *(float4*)&hrow[c * 4] = make_float4(
                __uint_as_float(d0[c * 4]), __uint_as_float(d0[c * 4 + 1]),
                __uint_as_float(d0[c * 4 + 2]), __uint_as_float(d0[c * 4 + 3]));
            *(float4*)&hrow[32 + c * 4] = make_float4(
                __uint_as_float(d1[c * 4]), __uint_as_float(d1[c * 4 + 1]),
                __uint_as_float(d1[c * 4 + 2]), __uint_as_float(d1[c * 4 + 3]));
        }

        // hT hi/lo (coalesced across lanes) + fused scores
        float s1 = 0.f, s2 = 0.f;
#pragma unroll 8
        for (int f = 0; f < 64; f++) {
            float v = __uint_as_float(f < 32 ? d0[f] : d1[f - 32]);
            unsigned short hb = bf16of(v);
            float fhi = __uint_as_float(((unsigned)hb) << 16);
            unsigned short lb = bf16of(v - fhi);
            g_hT_hi[(size_t)f * N_NODES + row] = hb;
            g_hT_lo[(size_t)f * N_NODES + row] = lb;
            s1 += v * __ldg(&a[f]);
            s2 += v * __ldg(&a[64 + f]);
        }
        g_s1[row] = s1;  g_s2[row] = s2;
        g_p1[row] = __expf(s1);
        g_q1[row] = __expf(0.2f * s1);
        g_e1[row] = __expf(-s1);
        g_r2[row] = __expf(s2);
        g_t2[row] = __expf(0.2f * s2);
    }
    __syncthreads();
    if (wid == 0) {
        tmem_relinquish();
        tmem_dealloc(tmem, 64);
    }

#else  // ---------------- fallback (non-'a' pass), correctness-only --------
    const int r  = tid >> 2;
    const int cq = tid & 3;          // 16 cols: cq*16 .. +15
    float acc[16];
#pragma unroll
    for (int i = 0; i < 16; i++) acc[i] = 0.f;
    for (int k = 0; k < F_IN; k++) {
        float v = inp[(size_t)(row0 + r) * F_IN + k];
        const float* wr = W + (size_t)k * F_OUT + cq * 16;
#pragma unroll
        for (int i = 0; i < 16; i++) acc[i] += v * wr[i];
    }
    const int row = row0 + r;
    float s1p = 0.f, s2p = 0.f;
#pragma unroll
    for (int i = 0; i < 16; i++) {
        int f = cq * 16 + i;
        float v = acc[i];
        g_h[(size_t)row * F_OUT + f] = v;
        unsigned short hb = bf16of(v);
        float fhi = __uint_as_float(((unsigned)hb) << 16);
        unsigned short lb = bf16of(v - fhi);
        g_hT_hi[(size_t)f * N_NODES + row] = hb;
        g_hT_lo[(size_t)f * N_NODES + row] = lb;
        s1p += v * a[f];
        s2p += v * a[64 + f];
    }
    s1p += __shfl_xor_sync(0xffffffffu, s1p, 1);
    s1p += __shfl_xor_sync(0xffffffffu, s1p, 2);
    s2p += __shfl_xor_sync(0xffffffffu, s2p, 1);
    s2p += __shfl_xor_sync(0xffffffffu, s2p, 2);
    if (cq == 0) {
        g_s1[row] = s1p;  g_s2[row] = s2p;
        g_p1[row] = __expf(s1p);
        g_q1[row] = __expf(0.2f * s1p);
        g_e1[row] = __expf(-s1p);
        g_r2[row] = __expf(s2p);
        g_t2[row] = __expf(0.2f * s2p);
    }
#endif
}

// ---------------------------------------------------------------------------
// Kernel 2: fused masked attention-weight x h via tcgen05. BJ=128 tiles
// (two 64-j SW128 column blocks per operand). Producer/consumer mbarriers,
// per-warp elected arrives (full count = 16). No in-loop __syncthreads.
// ---------------------------------------------------------------------------
__global__ __launch_bounds__(NTHR, 1) void k_attn_tc(const int* __restrict__ adj) {
    extern __shared__ char smem[];
    const int tid  = threadIdx.x;
    const int row0 = blockIdx.x * BM;
    const int s    = blockIdx.y;
    const int jbase = s * JCHUNK;

#if HAS_TC
    const unsigned sbase = smem_u32(smem);
    const int wid  = tid >> 5;
    const int lane = tid & 31;

    if (wid == 0) tmem_alloc(sbase + SM_TMEM, 64);
    if (tid == 0) {
        mbar_init(sbase + SM_DONE, 1);
        mbar_init(sbase + SM_DONE + 8, 1);
        mbar_init(sbase + SM_FULL, 16);
        mbar_init(sbase + SM_FULL + 8, 16);
    }
    __syncthreads();
    unsigned tmem;
    asm volatile("ld.shared.b32 %0, [%1];" : "=r"(tmem) : "r"(sbase + SM_TMEM));
    const unsigned doneb = sbase + SM_DONE;
    const unsigned fullb = sbase + SM_FULL;

    const int r2 = lane >> 4;
    const int jc = lane & 15;
    const int jblk = jc >> 3;

    float P[4], Q[4], E[4], lp[4];
#pragma unroll
    for (int u = 0; u < 4; u++) {
        int r = row0 + wid * 8 + u * 2 + r2;
        P[u] = g_p1[r]; Q[u] = g_q1[r]; E[u] = g_e1[r];
        lp[u] = 0.f;
    }
    const int* adjBase = adj + (size_t)(row0 + wid * 8 + r2) * N_NODES + jbase + jc * 8;

    const int bfeat = tid >> 3, bunit = tid & 7;
    const unsigned boff0 = SW(bfeat * 128 + bunit * 16);
    const unsigned boff1 = 8192 + boff0;

    int4 aCur[8];
#pragma unroll
    for (int u = 0; u < 4; u++) {
        aCur[u * 2]     = *(const int4*)(adjBase + (size_t)u * 2 * N_NODES);
        aCur[u * 2 + 1] = *(const int4*)(adjBase + (size_t)u * 2 * N_NODES + 4);
    }

    for (int t = 0; t < NT; t++) {
        const int j0 = jbase + t * BJ;
        const int st = t & 1;
        char* stage = smem + SM_STAGE0 + st * STAGE_SZ;
        const unsigned mbD = doneb + (st << 3);
        const unsigned mbF = fullb + (st << 3);

        int4 bhi0 = *(const int4*)(g_hT_hi + (size_t)bfeat * N_NODES + j0 + bunit * 8);
        int4 bhi1 = *(const int4*)(g_hT_hi + (size_t)bfeat * N_NODES + j0 + 64 + bunit * 8);
        int4 blo0 = *(const int4*)(g_hT_lo + (size_t)bfeat * N_NODES + j0 + bunit * 8);
        int4 blo1 = *(const int4*)(g_hT_lo + (size_t)bfeat * N_NODES + j0 + 64 + bunit * 8);
        float4 R4a = *(const float4*)(g_r2 + j0 + jc * 8);
        float4 R4b = *(const float4*)(g_r2 + j0 + jc * 8 + 4);
        float4 T4a = *(const float4*)(g_t2 + j0 + jc * 8);
        float4 T4b = *(const float4*)(g_t2 + j0 + jc * 8 + 4);

        if (t >= 2) mbar_wait(mbD, ((t >> 1) + 1) & 1);

        *(int4*)(stage + OFF_BHI + boff0) = bhi0;
        *(int4*)(stage + OFF_BHI + boff1) = bhi1;
        *(int4*)(stage + OFF_BLO + boff0) = blo0;
        *(int4*)(stage + OFF_BLO + boff1) = blo1;

#pragma unroll
        for (int u = 0; u < 4; u++) {
            int4 av0 = aCur[u * 2];
            int4 av1 = aCur[u * 2 + 1];
            if (t + 1 < NT) {
                aCur[u * 2]     = *(const int4*)(adjBase + (size_t)u * 2 * N_NODES + (t + 1) * BJ);
                aCur[u * 2 + 1] = *(const int4*)(adjBase + (size_t)u * 2 * N_NODES + (t + 1) * BJ + 4);
            }

            float w[8];
            {
                float m, n;
                m = (R4a.x > E[u]) ? P[u] : Q[u]; n = (R4a.x > E[u]) ? R4a.x : T4a.x;
                w[0] = (av0.x > 0) ? m * n : 0.f;
                m = (R4a.y > E[u]) ? P[u] : Q[u]; n = (R4a.y > E[u]) ? R4a.y : T4a.y;
                w[1] = (av0.y > 0) ? m * n : 0.f;
                m = (R4a.z > E[u]) ? P[u] : Q[u]; n = (R4a.z > E[u]) ? R4a.z : T4a.z;
                w[2] = (av0.z > 0) ? m * n : 0.f;
                m = (R4a.w > E[u]) ? P[u] : Q[u]; n = (R4a.w > E[u]) ? R4a.w : T4a.w;
                w[3] = (av0.w > 0) ? m * n : 0.f;
                m = (R4b.x > E[u]) ? P[u] : Q[u]; n = (R4b.x > E[u]) ? R4b.x : T4b.x;
                w[4] = (av1.x > 0) ? m * n : 0.f;
                m = (R4b.y > E[u]) ? P[u] : Q[u]; n = (R4b.y > E[u]) ? R4b.y : T4b.y;
                w[5] = (av1.y > 0) ? m * n : 0.f;
                m = (R4b.z > E[u]) ? P[u] : Q[u]; n = (R4b.z > E[u]) ? R4b.z : T4b.z;
                w[6] = (av1.z > 0) ? m * n : 0.f;
                m = (R4b.w > E[u]) ? P[u] : Q[u]; n = (R4b.w > E[u]) ? R4b.w : T4b.w;
                w[7] = (av1.w > 0) ? m * n : 0.f;
            }
            lp[u] += ((w[0] + w[1]) + (w[2] + w[3])) + ((w[4] + w[5]) + (w[6] + w[7]));

            unsigned hh[4], ll[4];
#pragma unroll
            for (int p = 0; p < 4; p++) {
                unsigned h = pack2(w[p * 2], w[p * 2 + 1]);
                float fa = __uint_as_float(h << 16);
                float fb = __uint_as_float(h & 0xffff0000u);
                hh[p] = h;
                ll[p] = pack2(w[p * 2] - fa, w[p * 2 + 1] - fb);
            }

            const int rloc = wid * 8 + u * 2 + r2;
            const unsigned aoff = jblk * 16384 + SW(rloc * 128 + (jc & 7) * 16);
            *(int4*)(stage + OFF_AHI + aoff) = make_int4(hh[0], hh[1], hh[2], hh[3]);
            *(int4*)(stage + OFF_ALO + aoff) = make_int4(ll[0], ll[1], ll[2], ll[3]);
        }

        fence_async_smem();
        __syncwarp();
        if (elect_one()) mbar_arrive(mbF);

        if (wid == 0) {
            mbar_wait(mbF, (t >> 1) & 1);
            if (elect_one()) {
                const unsigned sb = sbase + SM_STAGE0 + st * STAGE_SZ;
                ull dA[3] = {smem_desc(sb + OFF_AHI), smem_desc(sb + OFF_AHI),
                             smem_desc(sb + OFF_ALO)};
                ull dB[3] = {smem_desc(sb + OFF_BHI), smem_desc(sb + OFF_BLO),
                             smem_desc(sb + OFF_BHI)};
#pragma unroll
                for (int p = 0; p < 3; p++)
#pragma unroll
                    for (int k = 0; k < 8; k++) {
                        ull oa = (k < 4) ? (ull)(k * 2) : (ull)(1024 + (k - 4) * 2);
                        ull ob = (k < 4) ? (ull)(k * 2) : (ull)(512 + (k - 4) * 2);
                        mma_f16_ss(tmem, dA[p] + oa, dB[p] + ob, MMA_IDESC,
                                   !(t == 0 && p == 0 && k == 0));
                    }
                tc_commit(mbD);
            }
        }
    }

#pragma unroll
    for (int u = 0; u < 4; u++) {
        float v = lp[u];
        v += __shfl_xor_sync(0xffffffffu, v, 1);
        v += __shfl_xor_sync(0xffffffffu, v, 2);
        v += __shfl_xor_sync(0xffffffffu, v, 4);
        v += __shfl_xor_sync(0xffffffffu, v, 8);
        if (jc == 0)
            g_lP[s][row0 + wid * 8 + u * 2 + r2] = v;
    }

    mbar_wait(doneb,     ((NT / 2) - 1) & 1);
    mbar_wait(doneb + 8, ((NT / 2) - 1) & 1);
    tc_fence_after();
    if (wid < 4) {
        unsigned d0[32], d1[32];
        tmem_ld_x32(d0, tmem);
        tmem_ld_x32(d1, tmem + 32);
        tmem_wait_ld();
        tc_fence_before();
        float* dst = &g_accP[s][(size_t)(row0 + wid * 32 + lane) * F_OUT];
#pragma unroll
        for (int c = 0; c < 8; c++) {
            *(float4*)&dst[c * 4] = make_float4(
                __uint_as_float(d0[c * 4]), __uint_as_float(d0[c * 4 + 1]),
                __uint_as_float(d0[c * 4 + 2]), __uint_as_float(d0[c * 4 + 3]));
            *(float4*)&dst[32 + c * 4] = make_float4(
                __uint_as_float(d1[c * 4]), __uint_as_float(d1[c * 4 + 1]),
                __uint_as_float(d1[c * 4 + 2]), __uint_as_float(d1[c * 4 + 3]));
        }
    }
    __syncthreads();
    if (wid == 0) {
        tmem_relinquish();
        tmem_dealloc(tmem, 64);
    }

#else  // ------------------- FMA fallback (non-'a' pass) -------------------
    ull*   wT = (ull*)(smem + SMF_WT);
    float* hs = (float*)(smem + SMF_HS);

    const int rowA = tid >> 2;
    const int jh   = (tid & 3) * 8;
    const float s1r = g_s1[row0 + rowA];
    const int*   adjRow = adj + (size_t)(row0 + rowA) * N_NODES + jbase + jh;
    const float* s2p    = g_s2 + jbase + jh;
    float lpart = 0.f;

    const int rg = tid >> 4;
    const int fg = tid & 15;
    ull acc[8];
#pragma unroll
    for (int i = 0; i < 8; i++) acc[i] = 0ull;

    const int hjl = tid >> 4;
    const int hf4 = tid & 15;

    for (int t = 0; t < NT_F; t++) {
        const int jt = jbase + t * BJ_F;
        const int4* ap = (const int4*)(adjRow + t * BJ_F);
        int4 A0 = ap[0], A1 = ap[1];
        float4 S0 = *(const float4*)(s2p + t * BJ_F);
        float4 S1 = *(const float4*)(s2p + t * BJ_F + 4);
        float4 H0 = *(const float4*)&g_h[(size_t)(jt + hjl) * F_OUT + hf4 * 4];

        __syncthreads();

        *(float4*)&hs[hjl * HS_PITCH + hf4 * 4] = H0;

        int   av[8]; float sv[8];
        *(int4*)&av[0] = A0; *(int4*)&av[4] = A1;
        *(float4*)&sv[0] = S0; *(float4*)&sv[4] = S1;

#pragma unroll
        for (int jj = 0; jj < 8; jj++) {
            float e  = s1r + sv[jj];
            float le = fmaxf(e, 0.2f * e);
            float w  = __expf(le);
            w = (av[jj] > 0) ? w : 0.f;
            lpart += w;
            wT[(jh + jj) * WT_PITCH + rowA] = dup2(w);
        }
        __syncthreads();

#pragma unroll 4
        for (int jj = 0; jj < BJ_F; jj++) {
            const ulonglong2* wp = (const ulonglong2*)&wT[jj * WT_PITCH + rg * 4];
            ulonglong2 w01 = wp[0], w23 = wp[1];
            ulonglong2 hv  = *(const ulonglong2*)&hs[jj * HS_PITCH + fg * 4];
            ffma2(acc[0], w01.x, hv.x); ffma2(acc[1], w01.x, hv.y);
            ffma2(acc[2], w01.y, hv.x); ffma2(acc[3], w01.y, hv.y);
            ffma2(acc[4], w23.x, hv.x); ffma2(acc[5], w23.x, hv.y);
            ffma2(acc[6], w23.y, hv.x); ffma2(acc[7], w23.y, hv.y);
        }
    }

    float l1 = __shfl_xor_sync(0xffffffffu, lpart, 1);
    lpart += l1;
    float l2 = __shfl_xor_sync(0xffffffffu, lpart, 2);
    lpart += l2;
    if ((tid & 3) == 0) g_lP[s][row0 + rowA] = lpart;

    float* ap2 = g_accP[s];
#pragma unroll
    for (int r = 0; r < 4; r++) {
        float2 x = unpack2(acc[r * 2]);
        float2 y = unpack2(acc[r * 2 + 1]);
        float4 o = make_float4(x.x, x.y, y.x, y.y);
        *(float4*)&ap2[(size_t)(row0 + rg * 4 + r) * F_OUT + fg * 4] = o;
    }
#endif
}

// ---------------------------------------------------------------------------
// Kernel 3: out[i][f] = sum_s accP[s][i][f] / sum_s lP[s][i]  (float4)
// ---------------------------------------------------------------------------
__global__ __launch_bounds__(256) void k_norm(float* __restrict__ out) {
    const int idx = blockIdx.x * 256 + threadIdx.x;
    const int i = idx >> 4;
    float4 v0 = ((const float4*)g_accP[0])[idx];
    float4 v1 = ((const float4*)g_accP[1])[idx];
    float inv = 1.f / (g_lP[0][i] + g_lP[1][i]);
    float4 o = make_float4((v0.x + v1.x) * inv, (v0.y + v1.y) * inv,
                           (v0.z + v1.z) * inv, (v0.w + v1.w) * inv);
    ((float4*)out)[idx] = o;
}

extern "C" void kernel_launch(void* const* d_in, const int* in_sizes, int n_in,
                              void* d_out, int out_size) {
    const float* inp = (const float*)d_in[0];
    const int*   adj = (const int*)d_in[1];
    const float* W   = (const float*)d_in[2];
    const float* a   = (const float*)d_in[3];
    float* out = (float*)d_out;

    cudaFuncSetAttribute(k_hproj_tc, cudaFuncAttributeMaxDynamicSharedMemorySize, HP_SMTOT);
    cudaFuncSetAttribute(k_attn_tc, cudaFuncAttributeMaxDynamicSharedMemorySize, SM_TOT);

    k_wprep<<<64, 512>>>(W);
    k_hproj_tc<<<N_NODES / 128, NTHR, HP_SMTOT>>>(inp, W, a);
    dim3 g2(N_NODES / BM, NSPLIT);
    k_attn_tc<<<g2, NTHR, SM_TOT>>>(adj);
    k_norm<<<(N_NODES * F_OUT / 4) / 256, 256>>>(out);
}

// round 11
// speedup vs baseline: 3.1507x; 1.0142x over previous
#include <cuda_runtime.h>

#define N_NODES 8192
#define F_IN    512
#define F_OUT   64
#define NSPLIT  2
#define JCHUNK  (N_NODES / NSPLIT)   // 4096
#define BM      128
#define BJ      128
#define NT      (JCHUNK / BJ)        // 32 tiles per CTA
#define NTHR    512

// ---- k_attn smem: header + 2 stages of 96KB ----
#define SM_TMEM   0
#define SM_DONE   8                  // done0=8, done1=16
#define SM_FULL   24                 // full0=24, full1=32
#define SM_STAGE0 1024
#define STAGE_SZ  98304
#define OFF_AHI   0
#define OFF_ALO   32768
#define OFF_BHI   65536
#define OFF_BLO   81920
#define SM_TOT    (SM_STAGE0 + 2 * STAGE_SZ)   // 197632

// ---- k_hproj_tc smem: header + 2 stages of 48KB ----
#define HP_STAGE_SZ 49152
#define HP_AHI   0
#define HP_ALO   16384
#define HP_BHI   32768
#define HP_BLO   40960
#define HP_NT    8                   // 8 K-tiles of 64
#define HP_SMTOT (SM_STAGE0 + 2 * HP_STAGE_SZ) // 99328

// fallback (FMA) path smem layout inside the same dynamic buffer
#define BJ_F     32
#define NT_F     (JCHUNK / BJ_F)     // 128
#define WT_PITCH 130
#define HS_PITCH 68
#define SMF_WT   0
#define SMF_HS   (BJ_F * WT_PITCH * 8)

// idesc kind::f16: F32 accum, bf16 A/B, N=64, M=128
#define MMA_IDESC 0x08100490u

#define SW(x) ((x) ^ ((((unsigned)(x)) >> 3) & 0x70u))

#if defined(__CUDA_ARCH_FEAT_SM103_ALL) || defined(__CUDA_ARCH_FEAT_SM100_ALL) || \
    defined(__CUDA_ARCH_FEAT_SM101_ALL) || defined(__CUDA_ARCH_SPECIFIC__)
#define HAS_TC 1
#else
#define HAS_TC 0
#endif

typedef unsigned long long ull;

__device__ float          g_h[N_NODES * F_OUT];
__device__ unsigned short g_hT_hi[F_OUT * N_NODES];
__device__ unsigned short g_hT_lo[F_OUT * N_NODES];
__device__ unsigned short g_wT_hi[F_OUT * F_IN];   // [n][k] K-major
__device__ unsigned short g_wT_lo[F_OUT * F_IN];
__device__ float          g_s1[N_NODES];
__device__ float          g_s2[N_NODES];
__device__ float          g_p1[N_NODES];    // exp(s1)
__device__ float          g_q1[N_NODES];    // exp(0.2 s1)
__device__ float          g_r2[N_NODES];    // exp(s2)
__device__ float          g_t2[N_NODES];    // exp(0.2 s2)
__device__ float          g_accP[NSPLIT][N_NODES * F_OUT];
__device__ float          g_lP[NSPLIT][N_NODES];

// ---------------- generic helpers ----------------
__device__ __forceinline__ unsigned smem_u32(const void* p) {
    unsigned r;
    asm("{ .reg .u64 t; cvta.to.shared.u64 t, %1; cvt.u32.u64 %0, t; }" : "=r"(r) : "l"(p));
    return r;
}
__device__ __forceinline__ unsigned short bf16of(float v) {
    unsigned short h; asm("cvt.rn.bf16.f32 %0, %1;" : "=h"(h) : "f"(v)); return h;
}
__device__ __forceinline__ void ffma2(ull &d, ull a, ull b) {
    asm("fma.rn.f32x2 %0, %1, %2, %0;" : "+l"(d) : "l"(a), "l"(b));
}
__device__ __forceinline__ ull dup2(float x) {
    ull r; asm("mov.b64 %0, {%1, %1};" : "=l"(r) : "f"(x)); return r;
}
__device__ __forceinline__ float2 unpack2(ull v) {
    float2 r; asm("mov.b64 {%0, %1}, %2;" : "=f"(r.x), "=f"(r.y) : "l"(v)); return r;
}

#if HAS_TC
// ---------------- tcgen05 helpers ('a'-pass only) ----------------
__device__ __forceinline__ unsigned elect_one() {
    unsigned p;
    asm volatile("{ .reg .pred p; elect.sync _|p, 0xFFFFFFFF; selp.b32 %0, 1, 0, p; }" : "=r"(p));
    return p;
}
__device__ __forceinline__ unsigned pack2(float a, float b) {  // lower = a, upper = b
    unsigned r; asm("cvt.rn.bf16x2.f32 %0, %2, %1;" : "=r"(r) : "f"(a), "f"(b)); return r;
}
__device__ __forceinline__ void mma_f16_ss(unsigned d, ull a, ull b, unsigned idesc, unsigned en) {
    asm volatile(
        "{ .reg .pred p; setp.ne.u32 p, %4, 0;\n\t"
        "tcgen05.mma.cta_group::1.kind::f16 [%0], %1, %2, %3, {%5,%5,%5,%5}, p; }"
        :: "r"(d), "l"(a), "l"(b), "r"(idesc), "r"(en), "r"(0u) : "memory");
}
__device__ __forceinline__ void mbar_init(unsigned m, unsigned cnt) {
    asm volatile("mbarrier.init.shared.b64 [%0], %1;" :: "r"(m), "r"(cnt) : "memory");
}
__device__ __forceinline__ void mbar_arrive(unsigned m) {
    asm volatile("mbarrier.arrive.release.cta.shared::cta.b64 _, [%0];" :: "r"(m) : "memory");
}
__device__ __forceinline__ void mbar_wait(unsigned m, unsigned parity) {
    asm volatile(
        "{ .reg .pred P;\n\t"
        "WL_%=: mbarrier.try_wait.parity.acquire.cta.shared::cta.b64 P, [%0], %1, 0x989680;\n\t"
        "@P bra.uni WD_%=;\n\t"
        "bra.uni WL_%=;\n\t"
        "WD_%=: }"
        :: "r"(m), "r"(parity) : "memory");
}
__device__ __forceinline__ void tmem_alloc(unsigned smem_dst, unsigned ncols) {
    asm volatile("tcgen05.alloc.cta_group::1.sync.aligned.shared::cta.b32 [%0], %1;"
                 :: "r"(smem_dst), "r"(ncols) : "memory");
}
__device__ __forceinline__ void tmem_dealloc(unsigned tmem, unsigned ncols) {
    asm volatile("tcgen05.dealloc.cta_group::1.sync.aligned.b32 %0, %1;" :: "r"(tmem), "r"(ncols));
}
__device__ __forceinline__ void tmem_relinquish() {
    asm volatile("tcgen05.relinquish_alloc_permit.cta_group::1.sync.aligned;");
}
__device__ __forceinline__ void tc_commit(unsigned mbar) {
    asm volatile("tcgen05.commit.cta_group::1.mbarrier::arrive::one.shared::cluster.b64 [%0];"
                 :: "r"(mbar) : "memory");
}
__device__ __forceinline__ void fence_async_smem() {
    asm volatile("fence.proxy.async.shared::cta;" ::: "memory");
}
__device__ __forceinline__ void tc_fence_after() {
    asm volatile("tcgen05.fence::after_thread_sync;" ::: "memory");
}
__device__ __forceinline__ void tc_fence_before() {
    asm volatile("tcgen05.fence::before_thread_sync;" ::: "memory");
}
__device__ __forceinline__ void tmem_ld_x32(unsigned* r, unsigned addr) {
    asm volatile(
        "tcgen05.ld.sync.aligned.32x32b.x32.b32 "
        "{%0,%1,%2,%3,%4,%5,%6,%7,%8,%9,%10,%11,%12,%13,%14,%15,"
        "%16,%17,%18,%19,%20,%21,%22,%23,%24,%25,%26,%27,%28,%29,%30,%31}, [%32];"
        : "=r"(r[0]), "=r"(r[1]), "=r"(r[2]), "=r"(r[3]), "=r"(r[4]), "=r"(r[5]), "=r"(r[6]), "=r"(r[7]),
          "=r"(r[8]), "=r"(r[9]), "=r"(r[10]), "=r"(r[11]), "=r"(r[12]), "=r"(r[13]), "=r"(r[14]), "=r"(r[15]),
          "=r"(r[16]), "=r"(r[17]), "=r"(r[18]), "=r"(r[19]), "=r"(r[20]), "=r"(r[21]), "=r"(r[22]), "=r"(r[23]),
          "=r"(r[24]), "=r"(r[25]), "=r"(r[26]), "=r"(r[27]), "=r"(r[28]), "=r"(r[29]), "=r"(r[30]), "=r"(r[31])
        : "r"(addr));
}
__device__ __forceinline__ void tmem_wait_ld() {
    asm volatile("tcgen05.wait::ld.sync.aligned;" ::: "memory");
}
static constexpr ull DESC_BASE_SW128 =
    (2ull << 61) | (1ull << 46) | (64ull << 32) | (1ull << 16);
__device__ __forceinline__ ull smem_desc(unsigned addr) {
    return DESC_BASE_SW128 | ((ull)(addr >> 4) & 0x3FFFull);
}
#endif  // HAS_TC

// ---------------------------------------------------------------------------
// Kernel 0: W[512][64] -> transposed bf16 hi/lo [64][512] (K-major, MMA-ready)
// ---------------------------------------------------------------------------
__global__ __launch_bounds__(512) void k_wprep(const float* __restrict__ W) {
    int e = blockIdx.x * 512 + threadIdx.x;   // 0..32767
    int k = e >> 6, n = e & 63;
    float v = W[e];
    unsigned short hb = bf16of(v);
    float fhi = __uint_as_float(((unsigned)hb) << 16);
    unsigned short lb = bf16of(v - fhi);
    g_wT_hi[n * F_IN + k] = hb;
    g_wT_lo[n * F_IN + k] = lb;
}

// ---------------------------------------------------------------------------
// Kernel 1: h = input @ W via tcgen05 (hi/lo bf16 3-product, fp32 TMEM).
// 64 CTAs x 128 rows; 8 K-tiles of 64. Epilogue writes g_h, hT hi/lo
// (coalesced: lane = row), and fused s1/s2 + exp tables (row in registers).
// ---------------------------------------------------------------------------
__global__ __launch_bounds__(NTHR, 1) void k_hproj_tc(const float* __restrict__ inp,
                                                      const float* __restrict__ W,
                                                      const float* __restrict__ a) {
    extern __shared__ char smem[];
    const int tid  = threadIdx.x;
    const int row0 = blockIdx.x * 128;

#if HAS_TC
    const unsigned sbase = smem_u32(smem);
    const int wid  = tid >> 5;
    const int lane = tid & 31;

    if (wid == 0) tmem_alloc(sbase + SM_TMEM, 64);
    if (tid == 0) {
        mbar_init(sbase + SM_DONE, 1);
        mbar_init(sbase + SM_DONE + 8, 1);
        mbar_init(sbase + SM_FULL, 16);
        mbar_init(sbase + SM_FULL + 8, 16);
    }
    __syncthreads();
    unsigned tmem;
    asm volatile("ld.shared.b32 %0, [%1];" : "=r"(tmem) : "r"(sbase + SM_TMEM));
    const unsigned doneb = sbase + SM_DONE;
    const unsigned fullb = sbase + SM_FULL;

    // A mapping: r = tid>>2 (0..127), kq = tid&3 -> 16 k-values
    const int r  = tid >> 2;
    const int kq = tid & 3;
    const float* inRow = inp + (size_t)(row0 + r) * F_IN + kq * 16;
    const unsigned aoff0 = SW(r * 128 + kq * 32);
    const unsigned aoff1 = SW(r * 128 + kq * 32 + 16);

    // B mapping: bn = tid>>3 (0..63), bu = tid&7 -> int4 of 8 bf16
    const int bn = tid >> 3, bu = tid & 7;
    const unsigned boff = SW(bn * 128 + bu * 16);
    const unsigned short* wHiP = g_wT_hi + (size_t)bn * F_IN + bu * 8;
    const unsigned short* wLoP = g_wT_lo + (size_t)bn * F_IN + bu * 8;

    for (int kt = 0; kt < HP_NT; kt++) {
        const int st = kt & 1;
        char* stage = smem + SM_STAGE0 + st * HP_STAGE_SZ;
        const unsigned mbD = doneb + (st << 3);
        const unsigned mbF = fullb + (st << 3);

        float4 x0 = *(const float4*)(inRow + kt * 64);
        float4 x1 = *(const float4*)(inRow + kt * 64 + 4);
        float4 x2 = *(const float4*)(inRow + kt * 64 + 8);
        float4 x3 = *(const float4*)(inRow + kt * 64 + 12);
        int4 whi = *(const int4*)(wHiP + kt * 64);
        int4 wlo = *(const int4*)(wLoP + kt * 64);

        if (kt >= 2) mbar_wait(mbD, ((kt >> 1) + 1) & 1);

        *(int4*)(stage + HP_BHI + boff) = whi;
        *(int4*)(stage + HP_BLO + boff) = wlo;

        float f[16];
        *(float4*)&f[0] = x0; *(float4*)&f[4] = x1;
        *(float4*)&f[8] = x2; *(float4*)&f[12] = x3;
        unsigned hh[8], ll[8];
#pragma unroll
        for (int i = 0; i < 8; i++) {
            unsigned h = pack2(f[i * 2], f[i * 2 + 1]);
            float fa = __uint_as_float(h << 16);
            float fb = __uint_as_float(h & 0xffff0000u);
            hh[i] = h;
            ll[i] = pack2(f[i * 2] - fa, f[i * 2 + 1] - fb);
        }
        *(int4*)(stage + HP_AHI + aoff0) = make_int4(hh[0], hh[1], hh[2], hh[3]);
        *(int4*)(stage + HP_AHI + aoff1) = make_int4(hh[4], hh[5], hh[6], hh[7]);
        *(int4*)(stage + HP_ALO + aoff0) = make_int4(ll[0], ll[1], ll[2], ll[3]);
        *(int4*)(stage + HP_ALO + aoff1) = make_int4(ll[4], ll[5], ll[6], ll[7]);

        fence_async_smem();
        __syncwarp();
        if (elect_one()) mbar_arrive(mbF);

        if (wid == 15) {
            mbar_wait(mbF, (kt >> 1) & 1);
            if (elect_one()) {
                const unsigned sb = sbase + SM_STAGE0 + st * HP_STAGE_SZ;
                ull dA[3] = {smem_desc(sb + HP_AHI), smem_desc(sb + HP_AHI),
                             smem_desc(sb + HP_ALO)};
                ull dB[3] = {smem_desc(sb + HP_BHI), smem_desc(sb + HP_BLO),
                             smem_desc(sb + HP_BHI)};
#pragma unroll
                for (int p = 0; p < 3; p++)
#pragma unroll
                    for (int k = 0; k < 4; k++)
                        mma_f16_ss(tmem, dA[p] + k * 2, dB[p] + k * 2, MMA_IDESC,
                                   !(kt == 0 && p == 0 && k == 0));
                tc_commit(mbD);
            }
        }
    }

    // drain: each done barrier: 4 commits, consumed phases <= 2; wait phase 3
    mbar_wait(doneb,     ((HP_NT / 2) - 1) & 1);
    mbar_wait(doneb + 8, ((HP_NT / 2) - 1) & 1);
    tc_fence_after();
    if (wid < 4) {
        unsigned d0[32], d1[32];
        tmem_ld_x32(d0, tmem);
        tmem_ld_x32(d1, tmem + 32);
        tmem_wait_ld();
        tc_fence_before();
        const int row = row0 + wid * 32 + lane;

        float* hrow = &g_h[(size_t)row * F_OUT];
#pragma unroll
        for (int c = 0; c < 8; c++) {
            *(float4*)&hrow[c * 4] = make_float4(
                __uint_as_float(d0[c * 4]), __uint_as_float(d0[c * 4 + 1]),
                __uint_as_float(d0[c * 4 + 2]), __uint_as_float(d0[c * 4 + 3]));
            *(float4*)&hrow[32 + c * 4] = make_float4(
                __uint_as_float(d1[c * 4]), __uint_as_float(d1[c * 4 + 1]),
                __uint_as_float(d1[c * 4 + 2]), __uint_as_float(d1[c * 4 + 3]));
        }

        float s1 = 0.f, s2 = 0.f;
#pragma unroll 8
        for (int f = 0; f < 64; f++) {
            float v = __uint_as_float(f < 32 ? d0[f] : d1[f - 32]);
            unsigned short hb = bf16of(v);
            float fhi = __uint_as_float(((unsigned)hb) << 16);
            unsigned short lb = bf16of(v - fhi);
            g_hT_hi[(size_t)f * N_NODES + row] = hb;
            g_hT_lo[(size_t)f * N_NODES + row] = lb;
            s1 += v * __ldg(&a[f]);
            s2 += v * __ldg(&a[64 + f]);
        }
        g_s1[row] = s1;  g_s2[row] = s2;
        g_p1[row] = __expf(s1);
        g_q1[row] = __expf(0.2f * s1);
        g_r2[row] = __expf(s2);
        g_t2[row] = __expf(0.2f * s2);
    }
    __syncthreads();
    if (wid == 0) {
        tmem_relinquish();
        tmem_dealloc(tmem, 64);
    }

#else  // ---------------- fallback (non-'a' pass), correctness-only --------
    const int r  = tid >> 2;
    const int cq = tid & 3;
    float acc[16];
#pragma unroll
    for (int i = 0; i < 16; i++) acc[i] = 0.f;
    for (int k = 0; k < F_IN; k++) {
        float v = inp[(size_t)(row0 + r) * F_IN + k];
        const float* wr = W + (size_t)k * F_OUT + cq * 16;
#pragma unroll
        for (int i = 0; i < 16; i++) acc[i] += v * wr[i];
    }
    const int row = row0 + r;
    float s1p = 0.f, s2p = 0.f;
#pragma unroll
    for (int i = 0; i < 16; i++) {
        int f = cq * 16 + i;
        float v = acc[i];
        g_h[(size_t)row * F_OUT + f] = v;
        unsigned short hb = bf16of(v);
        float fhi = __uint_as_float(((unsigned)hb) << 16);
        unsigned short lb = bf16of(v - fhi);
        g_hT_hi[(size_t)f * N_NODES + row] = hb;
        g_hT_lo[(size_t)f * N_NODES + row] = lb;
        s1p += v * a[f];
        s2p += v * a[64 + f];
    }
    s1p += __shfl_xor_sync(0xffffffffu, s1p, 1);
    s1p += __shfl_xor_sync(0xffffffffu, s1p, 2);
    s2p += __shfl_xor_sync(0xffffffffu, s2p, 1);
    s2p += __shfl_xor_sync(0xffffffffu, s2p, 2);
    if (cq == 0) {
        g_s1[row] = s1p;  g_s2[row] = s2p;
        g_p1[row] = __expf(s1p);
        g_q1[row] = __expf(0.2f * s1p);
        g_r2[row] = __expf(s2p);
        g_t2[row] = __expf(0.2f * s2p);
    }
#endif
}

// ---------------------------------------------------------------------------
// Kernel 2: fused masked attention-weight x h via tcgen05. BJ=128 tiles.
// Consumer = warp 15 (hi-wid-first arbiter priority). Per-element weight:
// w = adj ? max(P*R, Q*T) : 0   (exp monotone => max-form == leaky softmax
// numerator; no compare-vs-E needed).
// ---------------------------------------------------------------------------
__global__ __launch_bounds__(NTHR, 1) void k_attn_tc(const int* __restrict__ adj) {
    extern __shared__ char smem[];
    const int tid  = threadIdx.x;
    const int row0 = blockIdx.x * BM;
    const int s    = blockIdx.y;
    const int jbase = s * JCHUNK;

#if HAS_TC
    const unsigned sbase = smem_u32(smem);
    const int wid  = tid >> 5;
    const int lane = tid & 31;

    if (wid == 0) tmem_alloc(sbase + SM_TMEM, 64);
    if (tid == 0) {
        mbar_init(sbase + SM_DONE, 1);
        mbar_init(sbase + SM_DONE + 8, 1);
        mbar_init(sbase + SM_FULL, 16);
        mbar_init(sbase + SM_FULL + 8, 16);
    }
    __syncthreads();
    unsigned tmem;
    asm volatile("ld.shared.b32 %0, [%1];" : "=r"(tmem) : "r"(sbase + SM_TMEM));
    const unsigned doneb = sbase + SM_DONE;
    const unsigned fullb = sbase + SM_FULL;

    const int r2 = lane >> 4;
    const int jc = lane & 15;
    const int jblk = jc >> 3;

    float P[4], Q[4], lp[4];
#pragma unroll
    for (int u = 0; u < 4; u++) {
        int r = row0 + wid * 8 + u * 2 + r2;
        P[u] = g_p1[r]; Q[u] = g_q1[r];
        lp[u] = 0.f;
    }
    const int* adjBase = adj + (size_t)(row0 + wid * 8 + r2) * N_NODES + jbase + jc * 8;

    const int bfeat = tid >> 3, bunit = tid & 7;
    const unsigned boff0 = SW(bfeat * 128 + bunit * 16);
    const unsigned boff1 = 8192 + boff0;

    int4 aCur[8];
#pragma unroll
    for (int u = 0; u < 4; u++) {
        aCur[u * 2]     = *(const int4*)(adjBase + (size_t)u * 2 * N_NODES);
        aCur[u * 2 + 1] = *(const int4*)(adjBase + (size_t)u * 2 * N_NODES + 4);
    }

    for (int t = 0; t < NT; t++) {
        const int j0 = jbase + t * BJ;
        const int st = t & 1;
        char* stage = smem + SM_STAGE0 + st * STAGE_SZ;
        const unsigned mbD = doneb + (st << 3);
        const unsigned mbF = fullb + (st << 3);

        int4 bhi0 = *(const int4*)(g_hT_hi + (size_t)bfeat * N_NODES + j0 + bunit * 8);
        int4 bhi1 = *(const int4*)(g_hT_hi + (size_t)bfeat * N_NODES + j0 + 64 + bunit * 8);
        int4 blo0 = *(const int4*)(g_hT_lo + (size_t)bfeat * N_NODES + j0 + bunit * 8);
        int4 blo1 = *(const int4*)(g_hT_lo + (size_t)bfeat * N_NODES + j0 + 64 + bunit * 8);
        float4 R4a = *(const float4*)(g_r2 + j0 + jc * 8);
        float4 R4b = *(const float4*)(g_r2 + j0 + jc * 8 + 4);
        float4 T4a = *(const float4*)(g_t2 + j0 + jc * 8);
        float4 T4b = *(const float4*)(g_t2 + j0 + jc * 8 + 4);

        if (t >= 2) mbar_wait(mbD, ((t >> 1) + 1) & 1);

        *(int4*)(stage + OFF_BHI + boff0) = bhi0;
        *(int4*)(stage + OFF_BHI + boff1) = bhi1;
        *(int4*)(stage + OFF_BLO + boff0) = blo0;
        *(int4*)(stage + OFF_BLO + boff1) = blo1;

#pragma unroll
        for (int u = 0; u < 4; u++) {
            int4 av0 = aCur[u * 2];
            int4 av1 = aCur[u * 2 + 1];
            if (t + 1 < NT) {
                aCur[u * 2]     = *(const int4*)(adjBase + (size_t)u * 2 * N_NODES + (t + 1) * BJ);
                aCur[u * 2 + 1] = *(const int4*)(adjBase + (size_t)u * 2 * N_NODES + (t + 1) * BJ + 4);
            }

            // w = adj ? max(P*R, Q*T) : 0
            float w[8];
            w[0] = (av0.x > 0) ? fmaxf(P[u] * R4a.x, Q[u] * T4a.x) : 0.f;
            w[1] = (av0.y > 0) ? fmaxf(P[u] * R4a.y, Q[u] * T4a.y) : 0.f;
            w[2] = (av0.z > 0) ? fmaxf(P[u] * R4a.z, Q[u] * T4a.z) : 0.f;
            w[3] = (av0.w > 0) ? fmaxf(P[u] * R4a.w, Q[u] * T4a.w) : 0.f;
            w[4] = (av1.x > 0) ? fmaxf(P[u] * R4b.x, Q[u] * T4b.x) : 0.f;
            w[5] = (av1.y > 0) ? fmaxf(P[u] * R4b.y, Q[u] * T4b.y) : 0.f;
            w[6] = (av1.z > 0) ? fmaxf(P[u] * R4b.z, Q[u] * T4b.z) : 0.f;
            w[7] = (av1.w > 0) ? fmaxf(P[u] * R4b.w, Q[u] * T4b.w) : 0.f;
            lp[u] += ((w[0] + w[1]) + (w[2] + w[3])) + ((w[4] + w[5]) + (w[6] + w[7]));

            unsigned hh[4], ll[4];
#pragma unroll
            for (int p = 0; p < 4; p++) {
                unsigned h = pack2(w[p * 2], w[p * 2 + 1]);
                float fa = __uint_as_float(h << 16);
                float fb = __uint_as_float(h & 0xffff0000u);
                hh[p] = h;
                ll[p] = pack2(w[p * 2] - fa, w[p * 2 + 1] - fb);
            }

            const int rloc = wid * 8 + u * 2 + r2;
            const unsigned aoff = jblk * 16384 + SW(rloc * 128 + (jc & 7) * 16);
            *(int4*)(stage + OFF_AHI + aoff) = make_int4(hh[0], hh[1], hh[2], hh[3]);
            *(int4*)(stage + OFF_ALO + aoff) = make_int4(ll[0], ll[1], ll[2], ll[3]);
        }

        fence_async_smem();
        __syncwarp();
        if (elect_one()) mbar_arrive(mbF);

        // consumer = warp 15: highest arbiter priority (hi-wid-first)
        if (wid == 15) {
            mbar_wait(mbF, (t >> 1) & 1);
            if (elect_one()) {
                const unsigned sb = sbase + SM_STAGE0 + st * STAGE_SZ;
                ull dA[3] = {smem_desc(sb + OFF_AHI), smem_desc(sb + OFF_AHI),
                             smem_desc(sb + OFF_ALO)};
                ull dB[3] = {smem_desc(sb + OFF_BHI), smem_desc(sb + OFF_BLO),
                             smem_desc(sb + OFF_BHI)};
#pragma unroll
                for (int p = 0; p < 3; p++)
#pragma unroll
                    for (int k = 0; k < 8; k++) {
                        ull oa = (k < 4) ? (ull)(k * 2) : (ull)(1024 + (k - 4) * 2);
                        ull ob = (k < 4) ? (ull)(k * 2) : (ull)(512 + (k - 4) * 2);
                        mma_f16_ss(tmem, dA[p] + oa, dB[p] + ob, MMA_IDESC,
                                   !(t == 0 && p == 0 && k == 0));
                    }
                tc_commit(mbD);
            }
        }
    }

#pragma unroll
    for (int u = 0; u < 4; u++) {
        float v = lp[u];
        v += __shfl_xor_sync(0xffffffffu, v, 1);
        v += __shfl_xor_sync(0xffffffffu, v, 2);
        v += __shfl_xor_sync(0xffffffffu, v, 4);
        v += __shfl_xor_sync(0xffffffffu, v, 8);
        if (jc == 0)
            g_lP[s][row0 + wid * 8 + u * 2 + r2] = v;
    }

    mbar_wait(doneb,     ((NT / 2) - 1) & 1);
    mbar_wait(doneb + 8, ((NT / 2) - 1) & 1);
    tc_fence_after();
    if (wid < 4) {
        unsigned d0[32], d1[32];
        tmem_ld_x32(d0, tmem);
        tmem_ld_x32(d1, tmem + 32);
        tmem_wait_ld();
        tc_fence_before();
        float* dst = &g_accP[s][(size_t)(row0 + wid * 32 + lane) * F_OUT];
#pragma unroll
        for (int c = 0; c < 8; c++) {
            *(float4*)&dst[c * 4] = make_float4(
                __uint_as_float(d0[c * 4]), __uint_as_float(d0[c * 4 + 1]),
                __uint_as_float(d0[c * 4 + 2]), __uint_as_float(d0[c * 4 + 3]));
            *(float4*)&dst[32 + c * 4] = make_float4(
                __uint_as_float(d1[c * 4]), __uint_as_float(d1[c * 4 + 1]),
                __uint_as_float(d1[c * 4 + 2]), __uint_as_float(d1[c * 4 + 3]));
        }
    }
    __syncthreads();
    if (wid == 0) {
        tmem_relinquish();
        tmem_dealloc(tmem, 64);
    }

#else  // ------------------- FMA fallback (non-'a' pass) -------------------
    ull*   wT = (ull*)(smem + SMF_WT);
    float* hs = (float*)(smem + SMF_HS);

    const int rowA = tid >> 2;
    const int jh   = (tid & 3) * 8;
    const float s1r = g_s1[row0 + rowA];
    const int*   adjRow = adj + (size_t)(row0 + rowA) * N_NODES + jbase + jh;
    const float* s2p    = g_s2 + jbase + jh;
    float lpart = 0.f;

    const int rg = tid >> 4;
    const int fg = tid & 15;
    ull acc[8];
#pragma unroll
    for (int i = 0; i < 8; i++) acc[i] = 0ull;

    const int hjl = tid >> 4;
    const int hf4 = tid & 15;

    for (int t = 0; t < NT_F; t++) {
        const int jt = jbase + t * BJ_F;
        const int4* ap = (const int4*)(adjRow + t * BJ_F);
        int4 A0 = ap[0], A1 = ap[1];
        float4 S0 = *(const float4*)(s2p + t * BJ_F);
        float4 S1 = *(const float4*)(s2p + t * BJ_F + 4);
        float4 H0 = *(const float4*)&g_h[(size_t)(jt + hjl) * F_OUT + hf4 * 4];

        __syncthreads();

        *(float4*)&hs[hjl * HS_PITCH + hf4 * 4] = H0;

        int   av[8]; float sv[8];
        *(int4*)&av[0] = A0; *(int4*)&av[4] = A1;
        *(float4*)&sv[0] = S0; *(float4*)&sv[4] = S1;

#pragma unroll
        for (int jj = 0; jj < 8; jj++) {
            float e  = s1r + sv[jj];
            float le = fmaxf(e, 0.2f * e);
            float w  = __expf(le);
            w = (av[jj] > 0) ? w : 0.f;
            lpart += w;
            wT[(jh + jj) * WT_PITCH + rowA] = dup2(w);
        }
        __syncthreads();

#pragma unroll 4
        for (int jj = 0; jj < BJ_F; jj++) {
            const ulonglong2* wp = (const ulonglong2*)&wT[jj * WT_PITCH + rg * 4];
            ulonglong2 w01 = wp[0], w23 = wp[1];
            ulonglong2 hv  = *(const ulonglong2*)&hs[jj * HS_PITCH + fg * 4];
            ffma2(acc[0], w01.x, hv.x); ffma2(acc[1], w01.x, hv.y);
            ffma2(acc[2], w01.y, hv.x); ffma2(acc[3], w01.y, hv.y);
            ffma2(acc[4], w23.x, hv.x); ffma2(acc[5], w23.x, hv.y);
            ffma2(acc[6], w23.y, hv.x); ffma2(acc[7], w23.y, hv.y);
        }
    }

    float l1 = __shfl_xor_sync(0xffffffffu, lpart, 1);
    lpart += l1;
    float l2 = __shfl_xor_sync(0xffffffffu, lpart, 2);
    lpart += l2;
    if ((tid & 3) == 0) g_lP[s][row0 + rowA] = lpart;

    float* ap2 = g_accP[s];
#pragma unroll
    for (int r = 0; r < 4; r++) {
        float2 x = unpack2(acc[r * 2]);
        float2 y = unpack2(acc[r * 2 + 1]);
        float4 o = make_float4(x.x, x.y, y.x, y.y);
        *(float4*)&ap2[(size_t)(row0 + rg * 4 + r) * F_OUT + fg * 4] = o;
    }
#endif
}

// ---------------------------------------------------------------------------
// Kernel 3: out[i][f] = sum_s accP[s][i][f] / sum_s lP[s][i]  (float4)
// ---------------------------------------------------------------------------
__global__ __launch_bounds__(256) void k_norm(float* __restrict__ out) {
    const int idx = blockIdx.x * 256 + threadIdx.x;
    const int i = idx >> 4;
    float4 v0 = ((const float4*)g_accP[0])[idx];
    float4 v1 = ((const float4*)g_accP[1])[idx];
    float inv = 1.f / (g_lP[0][i] + g_lP[1][i]);
    float4 o = make_float4((v0.x + v1.x) * inv, (v0.y + v1.y) * inv,
                           (v0.z + v1.z) * inv, (v0.w + v1.w) * inv);
    ((float4*)out)[idx] = o;
}

extern "C" void kernel_launch(void* const* d_in, const int* in_sizes, int n_in,
                              void* d_out, int out_size) {
    const float* inp = (const float*)d_in[0];
    const int*   adj = (const int*)d_in[1];
    const float* W   = (const float*)d_in[2];
    const float* a   = (const float*)d_in[3];
    float* out = (float*)d_out;

    cudaFuncSetAttribute(k_hproj_tc, cudaFuncAttributeMaxDynamicSharedMemorySize, HP_SMTOT);
    cudaFuncSetAttribute(k_attn_tc, cudaFuncAttributeMaxDynamicSharedMemorySize, SM_TOT);

    k_wprep<<<64, 512>>>(W);
    k_hproj_tc<<<N_NODES / 128, NTHR, HP_SMTOT>>>(inp, W, a);
    dim3 g2(N_NODES / BM, NSPLIT);
    k_attn_tc<<<g2, NTHR, SM_TOT>>>(adj);
    k_norm<<<(N_NODES * F_OUT / 4) / 256, 256>>>(out);
}

// round 12
// speedup vs baseline: 3.4573x; 1.0973x over previous
#include <cuda_runtime.h>

#define N_NODES 8192
#define F_IN    512
#define F_OUT   64
#define NSPLIT  2
#define JCHUNK  (N_NODES / NSPLIT)   // 4096
#define BM      128
#define BJ      64
#define NT      (JCHUNK / BJ)        // 64 tiles per CTA
#define NTHR_A  256
#define NTHR_H  512

// ---- k_attn smem: header + 2 stages of 48KB (fits 2 CTAs/SM) ----
#define SM_TMEM   0
#define SM_DONE   8                  // done0=8, done1=16
#define SM_FULL   24                 // full0=24, full1=32
#define SM_STAGE0 1024
#define STAGE_SZ  49152
#define OFF_AHI   0                  // 16KB: 128 rows x 64 j bf16
#define OFF_ALO   16384
#define OFF_BHI   32768              // 8KB: 64 feat x 64 j bf16
#define OFF_BLO   40960
#define SM_TOT    (SM_STAGE0 + 2 * STAGE_SZ)   // 99328

// ---- k_hproj_tc smem: header + 2 stages of 48KB ----
#define HP_STAGE_SZ 49152
#define HP_AHI   0
#define HP_ALO   16384
#define HP_BHI   32768
#define HP_BLO   40960
#define HP_NT    8
#define HP_SMTOT (SM_STAGE0 + 2 * HP_STAGE_SZ) // 99328

// fallback (FMA) path smem layout inside the same dynamic buffer
#define BJ_F     32
#define NT_F     (JCHUNK / BJ_F)     // 128
#define WT_PITCH 130
#define HS_PITCH 68
#define SMF_WT   0
#define SMF_HS   (BJ_F * WT_PITCH * 8)

// idesc kind::f16: F32 accum, bf16 A/B, N=64, M=128
#define MMA_IDESC 0x08100490u

#define SW(x) ((x) ^ ((((unsigned)(x)) >> 3) & 0x70u))

#if defined(__CUDA_ARCH_FEAT_SM103_ALL) || defined(__CUDA_ARCH_FEAT_SM100_ALL) || \
    defined(__CUDA_ARCH_FEAT_SM101_ALL) || defined(__CUDA_ARCH_SPECIFIC__)
#define HAS_TC 1
#else
#define HAS_TC 0
#endif

typedef unsigned long long ull;

__device__ float          g_h[N_NODES * F_OUT];
__device__ unsigned short g_hT_hi[F_OUT * N_NODES];
__device__ unsigned short g_hT_lo[F_OUT * N_NODES];
__device__ unsigned short g_wT_hi[F_OUT * F_IN];   // [n][k] K-major
__device__ unsigned short g_wT_lo[F_OUT * F_IN];
__device__ float          g_s1[N_NODES];
__device__ float          g_s2[N_NODES];
__device__ float          g_p1[N_NODES];    // exp(s1)
__device__ float          g_q1[N_NODES];    // exp(0.2 s1)
__device__ float          g_r2[N_NODES];    // exp(s2)
__device__ float          g_t2[N_NODES];    // exp(0.2 s2)
__device__ float          g_accP[NSPLIT][N_NODES * F_OUT];
__device__ float          g_lP[NSPLIT][N_NODES];

// ---------------- generic helpers ----------------
__device__ __forceinline__ unsigned smem_u32(const void* p) {
    unsigned r;
    asm("{ .reg .u64 t; cvta.to.shared.u64 t, %1; cvt.u32.u64 %0, t; }" : "=r"(r) : "l"(p));
    return r;
}
__device__ __forceinline__ unsigned short bf16of(float v) {
    unsigned short h; asm("cvt.rn.bf16.f32 %0, %1;" : "=h"(h) : "f"(v)); return h;
}
__device__ __forceinline__ void ffma2(ull &d, ull a, ull b) {
    asm("fma.rn.f32x2 %0, %1, %2, %0;" : "+l"(d) : "l"(a), "l"(b));
}
__device__ __forceinline__ ull dup2(float x) {
    ull r; asm("mov.b64 %0, {%1, %1};" : "=l"(r) : "f"(x)); return r;
}
__device__ __forceinline__ float2 unpack2(ull v) {
    float2 r; asm("mov.b64 {%0, %1}, %2;" : "=f"(r.x), "=f"(r.y) : "l"(v)); return r;
}

#if HAS_TC
// ---------------- tcgen05 helpers ('a'-pass only) ----------------
__device__ __forceinline__ unsigned elect_one() {
    unsigned p;
    asm volatile("{ .reg .pred p; elect.sync _|p, 0xFFFFFFFF; selp.b32 %0, 1, 0, p; }" : "=r"(p));
    return p;
}
__device__ __forceinline__ unsigned pack2(float a, float b) {  // lower = a, upper = b
    unsigned r; asm("cvt.rn.bf16x2.f32 %0, %2, %1;" : "=r"(r) : "f"(a), "f"(b)); return r;
}
__device__ __forceinline__ void mma_f16_ss(unsigned d, ull a, ull b, unsigned idesc, unsigned en) {
    asm volatile(
        "{ .reg .pred p; setp.ne.u32 p, %4, 0;\n\t"
        "tcgen05.mma.cta_group::1.kind::f16 [%0], %1, %2, %3, {%5,%5,%5,%5}, p; }"
        :: "r"(d), "l"(a), "l"(b), "r"(idesc), "r"(en), "r"(0u) : "memory");
}
__device__ __forceinline__ void mbar_init(unsigned m, unsigned cnt) {
    asm volatile("mbarrier.init.shared.b64 [%0], %1;" :: "r"(m), "r"(cnt) : "memory");
}
__device__ __forceinline__ void mbar_arrive(unsigned m) {
    asm volatile("mbarrier.arrive.release.cta.shared::cta.b64 _, [%0];" :: "r"(m) : "memory");
}
__device__ __forceinline__ void mbar_wait(unsigned m, unsigned parity) {
    asm volatile(
        "{ .reg .pred P;\n\t"
        "WL_%=: mbarrier.try_wait.parity.acquire.cta.shared::cta.b64 P, [%0], %1, 0x989680;\n\t"
        "@P bra.uni WD_%=;\n\t"
        "bra.uni WL_%=;\n\t"
        "WD_%=: }"
        :: "r"(m), "r"(parity) : "memory");
}
__device__ __forceinline__ void tmem_alloc(unsigned smem_dst, unsigned ncols) {
    asm volatile("tcgen05.alloc.cta_group::1.sync.aligned.shared::cta.b32 [%0], %1;"
                 :: "r"(smem_dst), "r"(ncols) : "memory");
}
__device__ __forceinline__ void tmem_dealloc(unsigned tmem, unsigned ncols) {
    asm volatile("tcgen05.dealloc.cta_group::1.sync.aligned.b32 %0, %1;" :: "r"(tmem), "r"(ncols));
}
__device__ __forceinline__ void tmem_relinquish() {
    asm volatile("tcgen05.relinquish_alloc_permit.cta_group::1.sync.aligned;");
}
__device__ __forceinline__ void tc_commit(unsigned mbar) {
    asm volatile("tcgen05.commit.cta_group::1.mbarrier::arrive::one.shared::cluster.b64 [%0];"
                 :: "r"(mbar) : "memory");
}
__device__ __forceinline__ void fence_async_smem() {
    asm volatile("fence.proxy.async.shared::cta;" ::: "memory");
}
__device__ __forceinline__ void tc_fence_after() {
    asm volatile("tcgen05.fence::after_thread_sync;" ::: "memory");
}
__device__ __forceinline__ void tc_fence_before() {
    asm volatile("tcgen05.fence::before_thread_sync;" ::: "memory");
}
__device__ __forceinline__ void tmem_ld_x32(unsigned* r, unsigned addr) {
    asm volatile(
        "tcgen05.ld.sync.aligned.32x32b.x32.b32 "
        "{%0,%1,%2,%3,%4,%5,%6,%7,%8,%9,%10,%11,%12,%13,%14,%15,"
        "%16,%17,%18,%19,%20,%21,%22,%23,%24,%25,%26,%27,%28,%29,%30,%31}, [%32];"
        : "=r"(r[0]), "=r"(r[1]), "=r"(r[2]), "=r"(r[3]), "=r"(r[4]), "=r"(r[5]), "=r"(r[6]), "=r"(r[7]),
          "=r"(r[8]), "=r"(r[9]), "=r"(r[10]), "=r"(r[11]), "=r"(r[12]), "=r"(r[13]), "=r"(r[14]), "=r"(r[15]),
          "=r"(r[16]), "=r"(r[17]), "=r"(r[18]), "=r"(r[19]), "=r"(r[20]), "=r"(r[21]), "=r"(r[22]), "=r"(r[23]),
          "=r"(r[24]), "=r"(r[25]), "=r"(r[26]), "=r"(r[27]), "=r"(r[28]), "=r"(r[29]), "=r"(r[30]), "=r"(r[31])
        : "r"(addr));
}
__device__ __forceinline__ void tmem_wait_ld() {
    asm volatile("tcgen05.wait::ld.sync.aligned;" ::: "memory");
}
static constexpr ull DESC_BASE_SW128 =
    (2ull << 61) | (1ull << 46) | (64ull << 32) | (1ull << 16);
__device__ __forceinline__ ull smem_desc(unsigned addr) {
    return DESC_BASE_SW128 | ((ull)(addr >> 4) & 0x3FFFull);
}
#endif  // HAS_TC

// ---------------------------------------------------------------------------
// Kernel 0: W[512][64] -> transposed bf16 hi/lo [64][512] (K-major, MMA-ready)
// ---------------------------------------------------------------------------
__global__ __launch_bounds__(512) void k_wprep(const float* __restrict__ W) {
    int e = blockIdx.x * 512 + threadIdx.x;
    int k = e >> 6, n = e & 63;
    float v = W[e];
    unsigned short hb = bf16of(v);
    float fhi = __uint_as_float(((unsigned)hb) << 16);
    unsigned short lb = bf16of(v - fhi);
    g_wT_hi[n * F_IN + k] = hb;
    g_wT_lo[n * F_IN + k] = lb;
}

// ---------------------------------------------------------------------------
// Kernel 1: h = input @ W via tcgen05 (hi/lo bf16 3-product, fp32 TMEM).
// ---------------------------------------------------------------------------
__global__ __launch_bounds__(NTHR_H, 1) void k_hproj_tc(const float* __restrict__ inp,
                                                        const float* __restrict__ W,
                                                        const float* __restrict__ a) {
    extern __shared__ char smem[];
    const int tid  = threadIdx.x;
    const int row0 = blockIdx.x * 128;

#if HAS_TC
    const unsigned sbase = smem_u32(smem);
    const int wid  = tid >> 5;
    const int lane = tid & 31;

    if (wid == 0) { tmem_alloc(sbase + SM_TMEM, 64); tmem_relinquish(); }
    if (tid == 0) {
        mbar_init(sbase + SM_DONE, 1);
        mbar_init(sbase + SM_DONE + 8, 1);
        mbar_init(sbase + SM_FULL, 16);
        mbar_init(sbase + SM_FULL + 8, 16);
    }
    __syncthreads();
    unsigned tmem;
    asm volatile("ld.shared.b32 %0, [%1];" : "=r"(tmem) : "r"(sbase + SM_TMEM));
    const unsigned doneb = sbase + SM_DONE;
    const unsigned fullb = sbase + SM_FULL;

    const int r  = tid >> 2;
    const int kq = tid & 3;
    const float* inRow = inp + (size_t)(row0 + r) * F_IN + kq * 16;
    const unsigned aoff0 = SW(r * 128 + kq * 32);
    const unsigned aoff1 = SW(r * 128 + kq * 32 + 16);

    const int bn = tid >> 3, bu = tid & 7;
    const unsigned boff = SW(bn * 128 + bu * 16);
    const unsigned short* wHiP = g_wT_hi + (size_t)bn * F_IN + bu * 8;
    const unsigned short* wLoP = g_wT_lo + (size_t)bn * F_IN + bu * 8;

    for (int kt = 0; kt < HP_NT; kt++) {
        const int st = kt & 1;
        char* stage = smem + SM_STAGE0 + st * HP_STAGE_SZ;
        const unsigned mbD = doneb + (st << 3);
        const unsigned mbF = fullb + (st << 3);

        float4 x0 = *(const float4*)(inRow + kt * 64);
        float4 x1 = *(const float4*)(inRow + kt * 64 + 4);
        float4 x2 = *(const float4*)(inRow + kt * 64 + 8);
        float4 x3 = *(const float4*)(inRow + kt * 64 + 12);
        int4 whi = *(const int4*)(wHiP + kt * 64);
        int4 wlo = *(const int4*)(wLoP + kt * 64);

        if (kt >= 2) mbar_wait(mbD, ((kt >> 1) + 1) & 1);

        *(int4*)(stage + HP_BHI + boff) = whi;
        *(int4*)(stage + HP_BLO + boff) = wlo;

        float f[16];
        *(float4*)&f[0] = x0; *(float4*)&f[4] = x1;
        *(float4*)&f[8] = x2; *(float4*)&f[12] = x3;
        unsigned hh[8], ll[8];
#pragma unroll
        for (int i = 0; i < 8; i++) {
            unsigned h = pack2(f[i * 2], f[i * 2 + 1]);
            float fa = __uint_as_float(h << 16);
            float fb = __uint_as_float(h & 0xffff0000u);
            hh[i] = h;
            ll[i] = pack2(f[i * 2] - fa, f[i * 2 + 1] - fb);
        }
        *(int4*)(stage + HP_AHI + aoff0) = make_int4(hh[0], hh[1], hh[2], hh[3]);
        *(int4*)(stage + HP_AHI + aoff1) = make_int4(hh[4], hh[5], hh[6], hh[7]);
        *(int4*)(stage + HP_ALO + aoff0) = make_int4(ll[0], ll[1], ll[2], ll[3]);
        *(int4*)(stage + HP_ALO + aoff1) = make_int4(ll[4], ll[5], ll[6], ll[7]);

        fence_async_smem();
        __syncwarp();
        if (elect_one()) mbar_arrive(mbF);

        if (wid == 15) {
            mbar_wait(mbF, (kt >> 1) & 1);
            if (elect_one()) {
                const unsigned sb = sbase + SM_STAGE0 + st * HP_STAGE_SZ;
                ull dA[3] = {smem_desc(sb + HP_AHI), smem_desc(sb + HP_AHI),
                             smem_desc(sb + HP_ALO)};
                ull dB[3] = {smem_desc(sb + HP_BHI), smem_desc(sb + HP_BLO),
                             smem_desc(sb + HP_BHI)};
#pragma unroll
                for (int p = 0; p < 3; p++)
#pragma unroll
                    for (int k = 0; k < 4; k++)
                        mma_f16_ss(tmem, dA[p] + k * 2, dB[p] + k * 2, MMA_IDESC,
                                   !(kt == 0 && p == 0 && k == 0));
                tc_commit(mbD);
            }
        }
    }

    mbar_wait(doneb,     ((HP_NT / 2) - 1) & 1);
    mbar_wait(doneb + 8, ((HP_NT / 2) - 1) & 1);
    tc_fence_after();
    if (wid < 4) {
        unsigned d0[32], d1[32];
        tmem_ld_x32(d0, tmem);
        tmem_ld_x32(d1, tmem + 32);
        tmem_wait_ld();
        tc_fence_before();
        const int row = row0 + wid * 32 + lane;

        float* hrow = &g_h[(size_t)row * F_OUT];
#pragma unroll
        for (int c = 0; c < 8; c++) {
            *(float4*)&hrow[c * 4] = make_float4(
                __uint_as_float(d0[c * 4]), __uint_as_float(d0[c * 4 + 1]),
                __uint_as_float(d0[c * 4 + 2]), __uint_as_float(d0[c * 4 + 3]));
            *(float4*)&hrow[32 + c * 4] = make_float4(
                __uint_as_float(d1[c * 4]), __uint_as_float(d1[c * 4 + 1]),
                __uint_as_float(d1[c * 4 + 2]), __uint_as_float(d1[c * 4 + 3]));
        }

        float s1 = 0.f, s2 = 0.f;
#pragma unroll 8
        for (int f = 0; f < 64; f++) {
            float v = __uint_as_float(f < 32 ? d0[f] : d1[f - 32]);
            unsigned short hb = bf16of(v);
            float fhi = __uint_as_float(((unsigned)hb) << 16);
            unsigned short lb = bf16of(v - fhi);
            g_hT_hi[(size_t)f * N_NODES + row] = hb;
            g_hT_lo[(size_t)f * N_NODES + row] = lb;
            s1 += v * __ldg(&a[f]);
            s2 += v * __ldg(&a[64 + f]);
        }
        g_s1[row] = s1;  g_s2[row] = s2;
        g_p1[row] = __expf(s1);
        g_q1[row] = __expf(0.2f * s1);
        g_r2[row] = __expf(s2);
        g_t2[row] = __expf(0.2f * s2);
    }
    __syncthreads();
    if (wid == 0) tmem_dealloc(tmem, 64);

#else  // ---------------- fallback (non-'a' pass), correctness-only --------
    const int r  = tid >> 2;
    const int cq = tid & 3;
    float acc[16];
#pragma unroll
    for (int i = 0; i < 16; i++) acc[i] = 0.f;
    for (int k = 0; k < F_IN; k++) {
        float v = inp[(size_t)(row0 + r) * F_IN + k];
        const float* wr = W + (size_t)k * F_OUT + cq * 16;
#pragma unroll
        for (int i = 0; i < 16; i++) acc[i] += v * wr[i];
    }
    const int row = row0 + r;
    float s1p = 0.f, s2p = 0.f;
#pragma unroll
    for (int i = 0; i < 16; i++) {
        int f = cq * 16 + i;
        float v = acc[i];
        g_h[(size_t)row * F_OUT + f] = v;
        unsigned short hb = bf16of(v);
        float fhi = __uint_as_float(((unsigned)hb) << 16);
        unsigned short lb = bf16of(v - fhi);
        g_hT_hi[(size_t)f * N_NODES + row] = hb;
        g_hT_lo[(size_t)f * N_NODES + row] = lb;
        s1p += v * a[f];
        s2p += v * a[64 + f];
    }
    s1p += __shfl_xor_sync(0xffffffffu, s1p, 1);
    s1p += __shfl_xor_sync(0xffffffffu, s1p, 2);
    s2p += __shfl_xor_sync(0xffffffffu, s2p, 1);
    s2p += __shfl_xor_sync(0xffffffffu, s2p, 2);
    if (cq == 0) {
        g_s1[row] = s1p;  g_s2[row] = s2p;
        g_p1[row] = __expf(s1p);
        g_q1[row] = __expf(0.2f * s1p);
        g_r2[row] = __expf(s2p);
        g_t2[row] = __expf(0.2f * s2p);
    }
#endif
}

// ---------------------------------------------------------------------------
// Kernel 2: fused masked attention-weight x h via tcgen05. BJ=64 tiles,
// 256 threads, 2 CTAs/SM (48KB stages). All global streams prefetched one
// tile ahead in registers. Consumer = warp 7. w = adj ? max(P*R, Q*T) : 0.
// ---------------------------------------------------------------------------
__global__ __launch_bounds__(NTHR_A, 2) void k_attn_tc(const int* __restrict__ adj) {
    extern __shared__ char smem[];
    const int tid  = threadIdx.x;
    const int row0 = blockIdx.x * BM;
    const int s    = blockIdx.y;
    const int jbase = s * JCHUNK;

#if HAS_TC
    const unsigned sbase = smem_u32(smem);
    const int wid  = tid >> 5;
    const int lane = tid & 31;

    // alloc + immediate relinquish: co-resident CTA must be able to alloc too
    if (wid == 0) { tmem_alloc(sbase + SM_TMEM, 64); tmem_relinquish(); }
    if (tid == 0) {
        mbar_init(sbase + SM_DONE, 1);
        mbar_init(sbase + SM_DONE + 8, 1);
        mbar_init(sbase + SM_FULL, 8);       // one arrive per warp (8 warps)
        mbar_init(sbase + SM_FULL + 8, 8);
    }
    __syncthreads();
    unsigned tmem;
    asm volatile("ld.shared.b32 %0, [%1];" : "=r"(tmem) : "r"(sbase + SM_TMEM));
    const unsigned doneb = sbase + SM_DONE;
    const unsigned fullb = sbase + SM_FULL;

    // mapping: warp w covers rows w*16..+15; lane = r2*16 + jc
    // thread: rows w*16 + u*2 + r2 (u=0..7), j = jc*4..+3
    const int r2 = lane >> 4;
    const int jc = lane & 15;

    float P[8], Q[8], lp[8];
#pragma unroll
    for (int u = 0; u < 8; u++) {
        int r = row0 + wid * 16 + u * 2 + r2;
        P[u] = g_p1[r]; Q[u] = g_q1[r];
        lp[u] = 0.f;
    }
    const int* adjBase = adj + (size_t)(row0 + wid * 16 + r2) * N_NODES + jbase + jc * 4;

    // B staging: 512 int4 per 8KB tile; 2 consecutive per thread
    const int bfeat = tid >> 2;              // (tid*2)>>3
    const int bunit = (tid & 3) * 2;         // (tid*2)&7
    const unsigned boff0 = SW(bfeat * 128 + bunit * 16);
    const unsigned boff1 = SW(bfeat * 128 + (bunit + 1) * 16);
    const unsigned short* bHiP = g_hT_hi + (size_t)bfeat * N_NODES + bunit * 8;
    const unsigned short* bLoP = g_hT_lo + (size_t)bfeat * N_NODES + bunit * 8;

    // prefetch tile 0: adj, B, R/T
    int4 aCur[8];
#pragma unroll
    for (int u = 0; u < 8; u++)
        aCur[u] = *(const int4*)(adjBase + (size_t)u * 2 * N_NODES);
    int4 bh0 = *(const int4*)(bHiP + jbase);
    int4 bh1 = *(const int4*)(bHiP + jbase + 8);
    int4 bl0 = *(const int4*)(bLoP + jbase);
    int4 bl1 = *(const int4*)(bLoP + jbase + 8);
    float4 Rc = *(const float4*)(g_r2 + jbase + jc * 4);
    float4 Tc = *(const float4*)(g_t2 + jbase + jc * 4);

    for (int t = 0; t < NT; t++) {
        const int st = t & 1;
        char* stage = smem + SM_STAGE0 + st * STAGE_SZ;
        const unsigned mbD = doneb + (st << 3);
        const unsigned mbF = fullb + (st << 3);

        // gate on this stage's previous MMA (tile t-2)
        if (t >= 2) mbar_wait(mbD, ((t >> 1) + 1) & 1);

        // store current B tile (prefetched last iteration)
        *(int4*)(stage + OFF_BHI + boff0) = bh0;
        *(int4*)(stage + OFF_BHI + boff1) = bh1;
        *(int4*)(stage + OFF_BLO + boff0) = bl0;
        *(int4*)(stage + OFF_BLO + boff1) = bl1;

        // prefetch next tile's B and R/T (full tile of latency cover)
        float4 Ru = Rc, Tu = Tc;
        if (t + 1 < NT) {
            const int jn = jbase + (t + 1) * BJ;
            bh0 = *(const int4*)(bHiP + jn);
            bh1 = *(const int4*)(bHiP + jn + 8);
            bl0 = *(const int4*)(bLoP + jn);
            bl1 = *(const int4*)(bLoP + jn + 8);
            Rc = *(const float4*)(g_r2 + jn + jc * 4);
            Tc = *(const float4*)(g_t2 + jn + jc * 4);
        }

#pragma unroll
        for (int u = 0; u < 8; u++) {
            int4 av = aCur[u];
            if (t + 1 < NT)
                aCur[u] = *(const int4*)(adjBase + (size_t)u * 2 * N_NODES + (t + 1) * BJ);

            float w0 = (av.x > 0) ? fmaxf(P[u] * Ru.x, Q[u] * Tu.x) : 0.f;
            float w1 = (av.y > 0) ? fmaxf(P[u] * Ru.y, Q[u] * Tu.y) : 0.f;
            float w2 = (av.z > 0) ? fmaxf(P[u] * Ru.z, Q[u] * Tu.z) : 0.f;
            float w3 = (av.w > 0) ? fmaxf(P[u] * Ru.w, Q[u] * Tu.w) : 0.f;
            lp[u] += (w0 + w1) + (w2 + w3);

            unsigned hh01 = pack2(w0, w1);
            unsigned hh23 = pack2(w2, w3);
            float f0 = __uint_as_float(hh01 << 16);
            float f1 = __uint_as_float(hh01 & 0xffff0000u);
            float f2 = __uint_as_float(hh23 << 16);
            float f3 = __uint_as_float(hh23 & 0xffff0000u);
            unsigned ll01 = pack2(w0 - f0, w1 - f1);
            unsigned ll23 = pack2(w2 - f2, w3 - f3);

            const int rloc = wid * 16 + u * 2 + r2;
            const unsigned aoff = SW(rloc * 128 + jc * 8);
            *(uint2*)(stage + OFF_AHI + aoff) = make_uint2(hh01, hh23);
            *(uint2*)(stage + OFF_ALO + aoff) = make_uint2(ll01, ll23);
        }

        fence_async_smem();
        __syncwarp();
        if (elect_one()) mbar_arrive(mbF);

        // consumer = warp 7 (highest priority of 8)
        if (wid == 7) {
            mbar_wait(mbF, (t >> 1) & 1);
            if (elect_one()) {
                const unsigned sb = sbase + SM_STAGE0 + st * STAGE_SZ;
                ull dA[3] = {smem_desc(sb + OFF_AHI), smem_desc(sb + OFF_AHI),
                             smem_desc(sb + OFF_ALO)};
                ull dB[3] = {smem_desc(sb + OFF_BHI), smem_desc(sb + OFF_BLO),
                             smem_desc(sb + OFF_BHI)};
#pragma unroll
                for (int p = 0; p < 3; p++)
#pragma unroll
                    for (int k = 0; k < 4; k++)
                        mma_f16_ss(tmem, dA[p] + k * 2, dB[p] + k * 2, MMA_IDESC,
                                   !(t == 0 && p == 0 && k == 0));
                tc_commit(mbD);
            }
        }
    }

    // per-row l: reduce lp[u] across the 16 jc-lanes of each row
#pragma unroll
    for (int u = 0; u < 8; u++) {
        float v = lp[u];
        v += __shfl_xor_sync(0xffffffffu, v, 1);
        v += __shfl_xor_sync(0xffffffffu, v, 2);
        v += __shfl_xor_sync(0xffffffffu, v, 4);
        v += __shfl_xor_sync(0xffffffffu, v, 8);
        if (jc == 0)
            g_lP[s][row0 + wid * 16 + u * 2 + r2] = v;
    }

    // FULL DRAIN: each barrier last phase = NT/2-1 = 31 (parity 1), in order.
    mbar_wait(doneb,     ((NT / 2) - 1) & 1);
    mbar_wait(doneb + 8, ((NT / 2) - 1) & 1);
    tc_fence_after();
    if (wid < 4) {
        unsigned d0[32], d1[32];
        tmem_ld_x32(d0, tmem);
        tmem_ld_x32(d1, tmem + 32);
        tmem_wait_ld();
        tc_fence_before();
        float* dst = &g_accP[s][(size_t)(row0 + wid * 32 + lane) * F_OUT];
#pragma unroll
        for (int c = 0; c < 8; c++) {
            *(float4*)&dst[c * 4] = make_float4(
                __uint_as_float(d0[c * 4]), __uint_as_float(d0[c * 4 + 1]),
                __uint_as_float(d0[c * 4 + 2]), __uint_as_float(d0[c * 4 + 3]));
            *(float4*)&dst[32 + c * 4] = make_float4(
                __uint_as_float(d1[c * 4]), __uint_as_float(d1[c * 4 + 1]),
                __uint_as_float(d1[c * 4 + 2]), __uint_as_float(d1[c * 4 + 3]));
        }
    }
    __syncthreads();
    if (wid == 0) tmem_dealloc(tmem, 64);

#else  // ------------------- FMA fallback (non-'a' pass) -------------------
    ull*   wT = (ull*)(smem + SMF_WT);
    float* hs = (float*)(smem + SMF_HS);

    const int rowA = tid >> 1;
    const int jh   = (tid & 1) * 16;
    const float s1r = g_s1[row0 + rowA];
    const int*   adjRow = adj + (size_t)(row0 + rowA) * N_NODES + jbase + jh;
    const float* s2p    = g_s2 + jbase + jh;
    float lpart = 0.f;

    const int rg = tid >> 4;
    const int fg = tid & 15;
    ull acc[16];
#pragma unroll
    for (int i = 0; i < 16; i++) acc[i] = 0ull;

    const int hjl = tid >> 4;
    const int hf4 = tid & 15;

    for (int t = 0; t < NT_F; t++) {
        const int jt = jbase + t * BJ_F;
        const int4* ap = (const int4*)(adjRow + t * BJ_F);
        int4 A0 = ap[0], A1 = ap[1], A2 = ap[2], A3 = ap[3];
        float4 S0 = *(const float4*)(s2p + t * BJ_F);
        float4 S1 = *(const float4*)(s2p + t * BJ_F + 4);
        float4 S2 = *(const float4*)(s2p + t * BJ_F + 8);
        float4 S3 = *(const float4*)(s2p + t * BJ_F + 12);
        float4 H0 = *(const float4*)&g_h[(size_t)(jt + hjl) * F_OUT + hf4 * 4];
        float4 H1 = *(const float4*)&g_h[(size_t)(jt + 16 + hjl) * F_OUT + hf4 * 4];

        __syncthreads();

        *(float4*)&hs[hjl * HS_PITCH + hf4 * 4]        = H0;
        *(float4*)&hs[(16 + hjl) * HS_PITCH + hf4 * 4] = H1;

        int   av[16]; float sv[16];
        *(int4*)&av[0] = A0; *(int4*)&av[4] = A1; *(int4*)&av[8] = A2; *(int4*)&av[12] = A3;
        *(float4*)&sv[0] = S0; *(float4*)&sv[4] = S1; *(float4*)&sv[8] = S2; *(float4*)&sv[12] = S3;

#pragma unroll
        for (int jj = 0; jj < 16; jj++) {
            float e  = s1r + sv[jj];
            float le = fmaxf(e, 0.2f * e);
            float w  = __expf(le);
            w = (av[jj] > 0) ? w : 0.f;
            lpart += w;
            wT[(jh + jj) * WT_PITCH + rowA] = dup2(w);
        }
        __syncthreads();

#pragma unroll 4
        for (int jj = 0; jj < BJ_F; jj++) {
            const ulonglong2* wp = (const ulonglong2*)&wT[jj * WT_PITCH + rg * 8];
            ulonglong2 w01 = wp[0], w23 = wp[1], w45 = wp[2], w67 = wp[3];
            ulonglong2 hv  = *(const ulonglong2*)&hs[jj * HS_PITCH + fg * 4];
            ffma2(acc[0],  w01.x, hv.x); ffma2(acc[1],  w01.x, hv.y);
            ffma2(acc[2],  w01.y, hv.x); ffma2(acc[3],  w01.y, hv.y);
            ffma2(acc[4],  w23.x, hv.x); ffma2(acc[5],  w23.x, hv.y);
            ffma2(acc[6],  w23.y, hv.x); ffma2(acc[7],  w23.y, hv.y);
            ffma2(acc[8],  w45.x, hv.x); ffma2(acc[9],  w45.x, hv.y);
            ffma2(acc[10], w45.y, hv.x); ffma2(acc[11], w45.y, hv.y);
            ffma2(acc[12], w67.x, hv.x); ffma2(acc[13], w67.x, hv.y);
            ffma2(acc[14], w67.y, hv.x); ffma2(acc[15], w67.y, hv.y);
        }
    }

    float lo2 = __shfl_xor_sync(0xffffffffu, lpart, 1);
    if ((tid & 1) == 0) g_lP[s][row0 + rowA] = lpart + lo2;

    float* ap2 = g_accP[s];
#pragma unroll
    for (int r = 0; r < 8; r++) {
        float2 x = unpack2(acc[r * 2]);
        float2 y = unpack2(acc[r * 2 + 1]);
        float4 o = make_float4(x.x, x.y, y.x, y.y);
        *(float4*)&ap2[(size_t)(row0 + rg * 8 + r) * F_OUT + fg * 4] = o;
    }
#endif
}

// ---------------------------------------------------------------------------
// Kernel 3: out[i][f] = sum_s accP[s][i][f] / sum_s lP[s][i]  (float4)
// ---------------------------------------------------------------------------
__global__ __launch_bounds__(256) void k_norm(float* __restrict__ out) {
    const int idx = blockIdx.x * 256 + threadIdx.x;
    const int i = idx >> 4;
    float4 v0 = ((const float4*)g_accP[0])[idx];
    float4 v1 = ((const float4*)g_accP[1])[idx];
    float inv = 1.f / (g_lP[0][i] + g_lP[1][i]);
    float4 o = make_float4((v0.x + v1.x) * inv, (v0.y + v1.y) * inv,
                           (v0.z + v1.z) * inv, (v0.w + v1.w) * inv);
    ((float4*)out)[idx] = o;
}

extern "C" void kernel_launch(void* const* d_in, const int* in_sizes, int n_in,
                              void* d_out, int out_size) {
    const float* inp = (const float*)d_in[0];
    const int*   adj = (const int*)d_in[1];
    const float* W   = (const float*)d_in[2];
    const float* a   = (const float*)d_in[3];
    float* out = (float*)d_out;

    cudaFuncSetAttribute(k_hproj_tc, cudaFuncAttributeMaxDynamicSharedMemorySize, HP_SMTOT);
    cudaFuncSetAttribute(k_attn_tc, cudaFuncAttributeMaxDynamicSharedMemorySize, SM_TOT);

    k_wprep<<<64, 512>>>(W);
    k_hproj_tc<<<N_NODES / 128, NTHR_H, HP_SMTOT>>>(inp, W, a);
    dim3 g2(N_NODES / BM, NSPLIT);
    k_attn_tc<<<g2, NTHR_A, SM_TOT>>>(adj);
    k_norm<<<(N_NODES * F_OUT / 4) / 256, 256>>>(out);
}

// round 13
// speedup vs baseline: 4.1912x; 1.2123x over previous
#include <cuda_runtime.h>

#define N_NODES 8192
#define F_IN    512
#define F_OUT   64
#define NSPLIT  4
#define JCHUNK  (N_NODES / NSPLIT)   // 2048
#define BM      128
#define BJ      64
#define NT      (JCHUNK / BJ)        // 32 tiles per CTA
#define NTHR_A  256
#define NTHR_H  512

// ---- k_attn smem: header + 2 stages of 48KB (fits 2 CTAs/SM) ----
#define SM_TMEM   0
#define SM_DONE   8                  // done0=8, done1=16
#define SM_FULL   24                 // full0=24, full1=32
#define SM_STAGE0 1024
#define STAGE_SZ  49152
#define OFF_AHI   0                  // 16KB: 128 rows x 64 j bf16
#define OFF_ALO   16384
#define OFF_BHI   32768              // 8KB: 64 feat x 64 j bf16
#define OFF_BLO   40960
#define SM_TOT    (SM_STAGE0 + 2 * STAGE_SZ)   // 99328

// ---- k_hproj_tc smem: header + 2 stages of 48KB ----
#define HP_STAGE_SZ 49152
#define HP_AHI   0
#define HP_ALO   16384
#define HP_BHI   32768
#define HP_BLO   40960
#define HP_NT    8
#define HP_SMTOT (SM_STAGE0 + 2 * HP_STAGE_SZ) // 99328

// fallback (FMA) path smem layout inside the same dynamic buffer
#define BJ_F     32
#define NT_F     (JCHUNK / BJ_F)     // 64
#define WT_PITCH 130
#define HS_PITCH 68
#define SMF_WT   0
#define SMF_HS   (BJ_F * WT_PITCH * 8)

// idesc kind::f16: F32 accum, bf16 A/B, N=64, M=128
#define MMA_IDESC 0x08100490u

#define SW(x) ((x) ^ ((((unsigned)(x)) >> 3) & 0x70u))

#if defined(__CUDA_ARCH_FEAT_SM103_ALL) || defined(__CUDA_ARCH_FEAT_SM100_ALL) || \
    defined(__CUDA_ARCH_FEAT_SM101_ALL) || defined(__CUDA_ARCH_SPECIFIC__)
#define HAS_TC 1
#else
#define HAS_TC 0
#endif

typedef unsigned long long ull;

__device__ float          g_h[N_NODES * F_OUT];
__device__ unsigned short g_hT_hi[F_OUT * N_NODES];
__device__ unsigned short g_hT_lo[F_OUT * N_NODES];
__device__ unsigned short g_wT_hi[F_OUT * F_IN];   // [n][k] K-major
__device__ unsigned short g_wT_lo[F_OUT * F_IN];
__device__ float          g_s1[N_NODES];
__device__ float          g_s2[N_NODES];
__device__ float          g_p1[N_NODES];    // exp(s1)
__device__ float          g_q1[N_NODES];    // exp(0.2 s1)
__device__ float          g_r2[N_NODES];    // exp(s2)
__device__ float          g_t2[N_NODES];    // exp(0.2 s2)
__device__ float          g_accP[NSPLIT][N_NODES * F_OUT];
__device__ float          g_lP[NSPLIT][N_NODES];

// ---------------- generic helpers ----------------
__device__ __forceinline__ unsigned smem_u32(const void* p) {
    unsigned r;
    asm("{ .reg .u64 t; cvta.to.shared.u64 t, %1; cvt.u32.u64 %0, t; }" : "=r"(r) : "l"(p));
    return r;
}
__device__ __forceinline__ unsigned short bf16of(float v) {
    unsigned short h; asm("cvt.rn.bf16.f32 %0, %1;" : "=h"(h) : "f"(v)); return h;
}
__device__ __forceinline__ void ffma2(ull &d, ull a, ull b) {
    asm("fma.rn.f32x2 %0, %1, %2, %0;" : "+l"(d) : "l"(a), "l"(b));
}
__device__ __forceinline__ ull dup2(float x) {
    ull r; asm("mov.b64 %0, {%1, %1};" : "=l"(r) : "f"(x)); return r;
}
__device__ __forceinline__ float2 unpack2(ull v) {
    float2 r; asm("mov.b64 {%0, %1}, %2;" : "=f"(r.x), "=f"(r.y) : "l"(v)); return r;
}

#if HAS_TC
// ---------------- tcgen05 helpers ('a'-pass only) ----------------
__device__ __forceinline__ unsigned elect_one() {
    unsigned p;
    asm volatile("{ .reg .pred p; elect.sync _|p, 0xFFFFFFFF; selp.b32 %0, 1, 0, p; }" : "=r"(p));
    return p;
}
__device__ __forceinline__ unsigned pack2(float a, float b) {  // lower = a, upper = b
    unsigned r; asm("cvt.rn.bf16x2.f32 %0, %2, %1;" : "=r"(r) : "f"(a), "f"(b)); return r;
}
__device__ __forceinline__ void mma_f16_ss(unsigned d, ull a, ull b, unsigned idesc, unsigned en) {
    asm volatile(
        "{ .reg .pred p; setp.ne.u32 p, %4, 0;\n\t"
        "tcgen05.mma.cta_group::1.kind::f16 [%0], %1, %2, %3, {%5,%5,%5,%5}, p; }"
        :: "r"(d), "l"(a), "l"(b), "r"(idesc), "r"(en), "r"(0u) : "memory");
}
__device__ __forceinline__ void mbar_init(unsigned m, unsigned cnt) {
    asm volatile("mbarrier.init.shared.b64 [%0], %1;" :: "r"(m), "r"(cnt) : "memory");
}
__device__ __forceinline__ void mbar_arrive(unsigned m) {
    asm volatile("mbarrier.arrive.release.cta.shared::cta.b64 _, [%0];" :: "r"(m) : "memory");
}
__device__ __forceinline__ void mbar_wait(unsigned m, unsigned parity) {
    asm volatile(
        "{ .reg .pred P;\n\t"
        "WL_%=: mbarrier.try_wait.parity.acquire.cta.shared::cta.b64 P, [%0], %1, 0x989680;\n\t"
        "@P bra.uni WD_%=;\n\t"
        "bra.uni WL_%=;\n\t"
        "WD_%=: }"
        :: "r"(m), "r"(parity) : "memory");
}
__device__ __forceinline__ void tmem_alloc(unsigned smem_dst, unsigned ncols) {
    asm volatile("tcgen05.alloc.cta_group::1.sync.aligned.shared::cta.b32 [%0], %1;"
                 :: "r"(smem_dst), "r"(ncols) : "memory");
}
__device__ __forceinline__ void tmem_dealloc(unsigned tmem, unsigned ncols) {
    asm volatile("tcgen05.dealloc.cta_group::1.sync.aligned.b32 %0, %1;" :: "r"(tmem), "r"(ncols));
}
__device__ __forceinline__ void tmem_relinquish() {
    asm volatile("tcgen05.relinquish_alloc_permit.cta_group::1.sync.aligned;");
}
__device__ __forceinline__ void tc_commit(unsigned mbar) {
    asm volatile("tcgen05.commit.cta_group::1.mbarrier::arrive::one.shared::cluster.b64 [%0];"
                 :: "r"(mbar) : "memory");
}
__device__ __forceinline__ void fence_async_smem() {
    asm volatile("fence.proxy.async.shared::cta;" ::: "memory");
}
__device__ __forceinline__ void tc_fence_after() {
    asm volatile("tcgen05.fence::after_thread_sync;" ::: "memory");
}
__device__ __forceinline__ void tc_fence_before() {
    asm volatile("tcgen05.fence::before_thread_sync;" ::: "memory");
}
__device__ __forceinline__ void tmem_ld_x32(unsigned* r, unsigned addr) {
    asm volatile(
        "tcgen05.ld.sync.aligned.32x32b.x32.b32 "
        "{%0,%1,%2,%3,%4,%5,%6,%7,%8,%9,%10,%11,%12,%13,%14,%15,"
        "%16,%17,%18,%19,%20,%21,%22,%23,%24,%25,%26,%27,%28,%29,%30,%31}, [%32];"
        : "=r"(r[0]), "=r"(r[1]), "=r"(r[2]), "=r"(r[3]), "=r"(r[4]), "=r"(r[5]), "=r"(r[6]), "=r"(r[7]),
          "=r"(r[8]), "=r"(r[9]), "=r"(r[10]), "=r"(r[11]), "=r"(r[12]), "=r"(r[13]), "=r"(r[14]), "=r"(r[15]),
          "=r"(r[16]), "=r"(r[17]), "=r"(r[18]), "=r"(r[19]), "=r"(r[20]), "=r"(r[21]), "=r"(r[22]), "=r"(r[23]),
          "=r"(r[24]), "=r"(r[25]), "=r"(r[26]), "=r"(r[27]), "=r"(r[28]), "=r"(r[29]), "=r"(r[30]), "=r"(r[31])
        : "r"(addr));
}
__device__ __forceinline__ void tmem_wait_ld() {
    asm volatile("tcgen05.wait::ld.sync.aligned;" ::: "memory");
}
static constexpr ull DESC_BASE_SW128 =
    (2ull << 61) | (1ull << 46) | (64ull << 32) | (1ull << 16);
__device__ __forceinline__ ull smem_desc(unsigned addr) {
    return DESC_BASE_SW128 | ((ull)(addr >> 4) & 0x3FFFull);
}
#endif  // HAS_TC

// ---------------------------------------------------------------------------
// Kernel 0: W[512][64] -> transposed bf16 hi/lo [64][512] (K-major, MMA-ready)
// ---------------------------------------------------------------------------
__global__ __launch_bounds__(512) void k_wprep(const float* __restrict__ W) {
    int e = blockIdx.x * 512 + threadIdx.x;
    int k = e >> 6, n = e & 63;
    float v = W[e];
    unsigned short hb = bf16of(v);
    float fhi = __uint_as_float(((unsigned)hb) << 16);
    unsigned short lb = bf16of(v - fhi);
    g_wT_hi[n * F_IN + k] = hb;
    g_wT_lo[n * F_IN + k] = lb;
}

// ---------------------------------------------------------------------------
// Kernel 1: h = input @ W via tcgen05 (hi/lo bf16 3-product, fp32 TMEM).
// ---------------------------------------------------------------------------
__global__ __launch_bounds__(NTHR_H, 1) void k_hproj_tc(const float* __restrict__ inp,
                                                        const float* __restrict__ W,
                                                        const float* __restrict__ a) {
    extern __shared__ char smem[];
    const int tid  = threadIdx.x;
    const int row0 = blockIdx.x * 128;

#if HAS_TC
    const unsigned sbase = smem_u32(smem);
    const int wid  = tid >> 5;
    const int lane = tid & 31;

    if (wid == 0) { tmem_alloc(sbase + SM_TMEM, 64); tmem_relinquish(); }
    if (tid == 0) {
        mbar_init(sbase + SM_DONE, 1);
        mbar_init(sbase + SM_DONE + 8, 1);
        mbar_init(sbase + SM_FULL, 16);
        mbar_init(sbase + SM_FULL + 8, 16);
    }
    __syncthreads();
    unsigned tmem;
    asm volatile("ld.shared.b32 %0, [%1];" : "=r"(tmem) : "r"(sbase + SM_TMEM));
    const unsigned doneb = sbase + SM_DONE;
    const unsigned fullb = sbase + SM_FULL;

    const int r  = tid >> 2;
    const int kq = tid & 3;
    const float* inRow = inp + (size_t)(row0 + r) * F_IN + kq * 16;
    const unsigned aoff0 = SW(r * 128 + kq * 32);
    const unsigned aoff1 = SW(r * 128 + kq * 32 + 16);

    const int bn = tid >> 3, bu = tid & 7;
    const unsigned boff = SW(bn * 128 + bu * 16);
    const unsigned short* wHiP = g_wT_hi + (size_t)bn * F_IN + bu * 8;
    const unsigned short* wLoP = g_wT_lo + (size_t)bn * F_IN + bu * 8;

    for (int kt = 0; kt < HP_NT; kt++) {
        const int st = kt & 1;
        char* stage = smem + SM_STAGE0 + st * HP_STAGE_SZ;
        const unsigned mbD = doneb + (st << 3);
        const unsigned mbF = fullb + (st << 3);

        float4 x0 = *(const float4*)(inRow + kt * 64);
        float4 x1 = *(const float4*)(inRow + kt * 64 + 4);
        float4 x2 = *(const float4*)(inRow + kt * 64 + 8);
        float4 x3 = *(const float4*)(inRow + kt * 64 + 12);
        int4 whi = *(const int4*)(wHiP + kt * 64);
        int4 wlo = *(const int4*)(wLoP + kt * 64);

        if (kt >= 2) mbar_wait(mbD, ((kt >> 1) + 1) & 1);

        *(int4*)(stage + HP_BHI + boff) = whi;
        *(int4*)(stage + HP_BLO + boff) = wlo;

        float f[16];
        *(float4*)&f[0] = x0; *(float4*)&f[4] = x1;
        *(float4*)&f[8] = x2; *(float4*)&f[12] = x3;
        unsigned hh[8], ll[8];
#pragma unroll
        for (int i = 0; i < 8; i++) {
            unsigned h = pack2(f[i * 2], f[i * 2 + 1]);
            float fa = __uint_as_float(h << 16);
            float fb = __uint_as_float(h & 0xffff0000u);
            hh[i] = h;
            ll[i] = pack2(f[i * 2] - fa, f[i * 2 + 1] - fb);
        }
        *(int4*)(stage + HP_AHI + aoff0) = make_int4(hh[0], hh[1], hh[2], hh[3]);
        *(int4*)(stage + HP_AHI + aoff1) = make_int4(hh[4], hh[5], hh[6], hh[7]);
        *(int4*)(stage + HP_ALO + aoff0) = make_int4(ll[0], ll[1], ll[2], ll[3]);
        *(int4*)(stage + HP_ALO + aoff1) = make_int4(ll[4], ll[5], ll[6], ll[7]);

        fence_async_smem();
        __syncwarp();
        if (elect_one()) mbar_arrive(mbF);

        if (wid == 15) {
            mbar_wait(mbF, (kt >> 1) & 1);
            if (elect_one()) {
                const unsigned sb = sbase + SM_STAGE0 + st * HP_STAGE_SZ;
                ull dA[3] = {smem_desc(sb + HP_AHI), smem_desc(sb + HP_AHI),
                             smem_desc(sb + HP_ALO)};
                ull dB[3] = {smem_desc(sb + HP_BHI), smem_desc(sb + HP_BLO),
                             smem_desc(sb + HP_BHI)};
#pragma unroll
                for (int p = 0; p < 3; p++)
#pragma unroll
                    for (int k = 0; k < 4; k++)
                        mma_f16_ss(tmem, dA[p] + k * 2, dB[p] + k * 2, MMA_IDESC,
                                   !(kt == 0 && p == 0 && k == 0));
                tc_commit(mbD);
            }
        }
    }

    mbar_wait(doneb,     ((HP_NT / 2) - 1) & 1);
    mbar_wait(doneb + 8, ((HP_NT / 2) - 1) & 1);
    tc_fence_after();
    if (wid < 4) {
        unsigned d0[32], d1[32];
        tmem_ld_x32(d0, tmem);
        tmem_ld_x32(d1, tmem + 32);
        tmem_wait_ld();
        tc_fence_before();
        const int row = row0 + wid * 32 + lane;

        float* hrow = &g_h[(size_t)row * F_OUT];
#pragma unroll
        for (int c = 0; c < 8; c++) {
            *(float4*)&hrow[c * 4] = make_float4(
                __uint_as_float(d0[c * 4]), __uint_as_float(d0[c * 4 + 1]),
                __uint_as_float(d0[c * 4 + 2]), __uint_as_float(d0[c * 4 + 3]));
            *(float4*)&hrow[32 + c * 4] = make_float4(
                __uint_as_float(d1[c * 4]), __uint_as_float(d1[c * 4 + 1]),
                __uint_as_float(d1[c * 4 + 2]), __uint_as_float(d1[c * 4 + 3]));
        }

        float s1 = 0.f, s2 = 0.f;
#pragma unroll 8
        for (int f = 0; f < 64; f++) {
            float v = __uint_as_float(f < 32 ? d0[f] : d1[f - 32]);
            unsigned short hb = bf16of(v);
            float fhi = __uint_as_float(((unsigned)hb) << 16);
            unsigned short lb = bf16of(v - fhi);
            g_hT_hi[(size_t)f * N_NODES + row] = hb;
            g_hT_lo[(size_t)f * N_NODES + row] = lb;
            s1 += v * __ldg(&a[f]);
            s2 += v * __ldg(&a[64 + f]);
        }
        g_s1[row] = s1;  g_s2[row] = s2;
        g_p1[row] = __expf(s1);
        g_q1[row] = __expf(0.2f * s1);
        g_r2[row] = __expf(s2);
        g_t2[row] = __expf(0.2f * s2);
    }
    __syncthreads();
    if (wid == 0) tmem_dealloc(tmem, 64);

#else  // ---------------- fallback (non-'a' pass), correctness-only --------
    const int r  = tid >> 2;
    const int cq = tid & 3;
    float acc[16];
#pragma unroll
    for (int i = 0; i < 16; i++) acc[i] = 0.f;
    for (int k = 0; k < F_IN; k++) {
        float v = inp[(size_t)(row0 + r) * F_IN + k];
        const float* wr = W + (size_t)k * F_OUT + cq * 16;
#pragma unroll
        for (int i = 0; i < 16; i++) acc[i] += v * wr[i];
    }
    const int row = row0 + r;
    float s1p = 0.f, s2p = 0.f;
#pragma unroll
    for (int i = 0; i < 16; i++) {
        int f = cq * 16 + i;
        float v = acc[i];
        g_h[(size_t)row * F_OUT + f] = v;
        unsigned short hb = bf16of(v);
        float fhi = __uint_as_float(((unsigned)hb) << 16);
        unsigned short lb = bf16of(v - fhi);
        g_hT_hi[(size_t)f * N_NODES + row] = hb;
        g_hT_lo[(size_t)f * N_NODES + row] = lb;
        s1p += v * a[f];
        s2p += v * a[64 + f];
    }
    s1p += __shfl_xor_sync(0xffffffffu, s1p, 1);
    s1p += __shfl_xor_sync(0xffffffffu, s1p, 2);
    s2p += __shfl_xor_sync(0xffffffffu, s2p, 1);
    s2p += __shfl_xor_sync(0xffffffffu, s2p, 2);
    if (cq == 0) {
        g_s1[row] = s1p;  g_s2[row] = s2p;
        g_p1[row] = __expf(s1p);
        g_q1[row] = __expf(0.2f * s1p);
        g_r2[row] = __expf(s2p);
        g_t2[row] = __expf(0.2f * s2p);
    }
#endif
}

// ---------------------------------------------------------------------------
// Kernel 2: fused masked attention-weight x h via tcgen05. BJ=64 tiles,
// 256 threads, grid (64, NSPLIT=4) = 256 CTAs -> all 148 SMs busy, 108 SMs
// host 2 co-resident pipelines. All global streams prefetched one tile
// ahead. Consumer = warp 7. w = adj ? max(P*R, Q*T) : 0.
// ---------------------------------------------------------------------------
__global__ __launch_bounds__(NTHR_A, 2) void k_attn_tc(const int* __restrict__ adj) {
    extern __shared__ char smem[];
    const int tid  = threadIdx.x;
    const int row0 = blockIdx.x * BM;
    const int s    = blockIdx.y;
    const int jbase = s * JCHUNK;

#if HAS_TC
    const unsigned sbase = smem_u32(smem);
    const int wid  = tid >> 5;
    const int lane = tid & 31;

    if (wid == 0) { tmem_alloc(sbase + SM_TMEM, 64); tmem_relinquish(); }
    if (tid == 0) {
        mbar_init(sbase + SM_DONE, 1);
        mbar_init(sbase + SM_DONE + 8, 1);
        mbar_init(sbase + SM_FULL, 8);
        mbar_init(sbase + SM_FULL + 8, 8);
    }
    __syncthreads();
    unsigned tmem;
    asm volatile("ld.shared.b32 %0, [%1];" : "=r"(tmem) : "r"(sbase + SM_TMEM));
    const unsigned doneb = sbase + SM_DONE;
    const unsigned fullb = sbase + SM_FULL;

    const int r2 = lane >> 4;
    const int jc = lane & 15;

    float P[8], Q[8], lp[8];
#pragma unroll
    for (int u = 0; u < 8; u++) {
        int r = row0 + wid * 16 + u * 2 + r2;
        P[u] = g_p1[r]; Q[u] = g_q1[r];
        lp[u] = 0.f;
    }
    const int* adjBase = adj + (size_t)(row0 + wid * 16 + r2) * N_NODES + jbase + jc * 4;

    const int bfeat = tid >> 2;
    const int bunit = (tid & 3) * 2;
    const unsigned boff0 = SW(bfeat * 128 + bunit * 16);
    const unsigned boff1 = SW(bfeat * 128 + (bunit + 1) * 16);
    const unsigned short* bHiP = g_hT_hi + (size_t)bfeat * N_NODES + bunit * 8;
    const unsigned short* bLoP = g_hT_lo + (size_t)bfeat * N_NODES + bunit * 8;

    int4 aCur[8];
#pragma unroll
    for (int u = 0; u < 8; u++)
        aCur[u] = *(const int4*)(adjBase + (size_t)u * 2 * N_NODES);
    int4 bh0 = *(const int4*)(bHiP + jbase);
    int4 bh1 = *(const int4*)(bHiP + jbase + 8);
    int4 bl0 = *(const int4*)(bLoP + jbase);
    int4 bl1 = *(const int4*)(bLoP + jbase + 8);
    float4 Rc = *(const float4*)(g_r2 + jbase + jc * 4);
    float4 Tc = *(const float4*)(g_t2 + jbase + jc * 4);

    for (int t = 0; t < NT; t++) {
        const int st = t & 1;
        char* stage = smem + SM_STAGE0 + st * STAGE_SZ;
        const unsigned mbD = doneb + (st << 3);
        const unsigned mbF = fullb + (st << 3);

        if (t >= 2) mbar_wait(mbD, ((t >> 1) + 1) & 1);

        *(int4*)(stage + OFF_BHI + boff0) = bh0;
        *(int4*)(stage + OFF_BHI + boff1) = bh1;
        *(int4*)(stage + OFF_BLO + boff0) = bl0;
        *(int4*)(stage + OFF_BLO + boff1) = bl1;

        float4 Ru = Rc, Tu = Tc;
        if (t + 1 < NT) {
            const int jn = jbase + (t + 1) * BJ;
            bh0 = *(const int4*)(bHiP + jn);
            bh1 = *(const int4*)(bHiP + jn + 8);
            bl0 = *(const int4*)(bLoP + jn);
            bl1 = *(const int4*)(bLoP + jn + 8);
            Rc = *(const float4*)(g_r2 + jn + jc * 4);
            Tc = *(const float4*)(g_t2 + jn + jc * 4);
        }

#pragma unroll
        for (int u = 0; u < 8; u++) {
            int4 av = aCur[u];
            if (t + 1 < NT)
                aCur[u] = *(const int4*)(adjBase + (size_t)u * 2 * N_NODES + (t + 1) * BJ);

            float w0 = (av.x > 0) ? fmaxf(P[u] * Ru.x, Q[u] * Tu.x) : 0.f;
            float w1 = (av.y > 0) ? fmaxf(P[u] * Ru.y, Q[u] * Tu.y) : 0.f;
            float w2 = (av.z > 0) ? fmaxf(P[u] * Ru.z, Q[u] * Tu.z) : 0.f;
            float w3 = (av.w > 0) ? fmaxf(P[u] * Ru.w, Q[u] * Tu.w) : 0.f;
            lp[u] += (w0 + w1) + (w2 + w3);

            unsigned hh01 = pack2(w0, w1);
            unsigned hh23 = pack2(w2, w3);
            float f0 = __uint_as_float(hh01 << 16);
            float f1 = __uint_as_float(hh01 & 0xffff0000u);
            float f2 = __uint_as_float(hh23 << 16);
            float f3 = __uint_as_float(hh23 & 0xffff0000u);
            unsigned ll01 = pack2(w0 - f0, w1 - f1);
            unsigned ll23 = pack2(w2 - f2, w3 - f3);

            const int rloc = wid * 16 + u * 2 + r2;
            const unsigned aoff = SW(rloc * 128 + jc * 8);
            *(uint2*)(stage + OFF_AHI + aoff) = make_uint2(hh01, hh23);
            *(uint2*)(stage + OFF_ALO + aoff) = make_uint2(ll01, ll23);
        }

        fence_async_smem();
        __syncwarp();
        if (elect_one()) mbar_arrive(mbF);

        if (wid == 7) {
            mbar_wait(mbF, (t >> 1) & 1);
            if (elect_one()) {
                const unsigned sb = sbase + SM_STAGE0 + st * STAGE_SZ;
                ull dA[3] = {smem_desc(sb + OFF_AHI), smem_desc(sb + OFF_AHI),
                             smem_desc(sb + OFF_ALO)};
                ull dB[3] = {smem_desc(sb + OFF_BHI), smem_desc(sb + OFF_BLO),
                             smem_desc(sb + OFF_BHI)};
#pragma unroll
                for (int p = 0; p < 3; p++)
#pragma unroll
                    for (int k = 0; k < 4; k++)
                        mma_f16_ss(tmem, dA[p] + k * 2, dB[p] + k * 2, MMA_IDESC,
                                   !(t == 0 && p == 0 && k == 0));
                tc_commit(mbD);
            }
        }
    }

#pragma unroll
    for (int u = 0; u < 8; u++) {
        float v = lp[u];
        v += __shfl_xor_sync(0xffffffffu, v, 1);
        v += __shfl_xor_sync(0xffffffffu, v, 2);
        v += __shfl_xor_sync(0xffffffffu, v, 4);
        v += __shfl_xor_sync(0xffffffffu, v, 8);
        if (jc == 0)
            g_lP[s][row0 + wid * 16 + u * 2 + r2] = v;
    }

    mbar_wait(doneb,     ((NT / 2) - 1) & 1);
    mbar_wait(doneb + 8, ((NT / 2) - 1) & 1);
    tc_fence_after();
    if (wid < 4) {
        unsigned d0[32], d1[32];
        tmem_ld_x32(d0, tmem);
        tmem_ld_x32(d1, tmem + 32);
        tmem_wait_ld();
        tc_fence_before();
        float* dst = &g_accP[s][(size_t)(row0 + wid * 32 + lane) * F_OUT];
#pragma unroll
        for (int c = 0; c < 8; c++) {
            *(float4*)&dst[c * 4] = make_float4(
                __uint_as_float(d0[c * 4]), __uint_as_float(d0[c * 4 + 1]),
                __uint_as_float(d0[c * 4 + 2]), __uint_as_float(d0[c * 4 + 3]));
            *(float4*)&dst[32 + c * 4] = make_float4(
                __uint_as_float(d1[c * 4]), __uint_as_float(d1[c * 4 + 1]),
                __uint_as_float(d1[c * 4 + 2]), __uint_as_float(d1[c * 4 + 3]));
        }
    }
    __syncthreads();
    if (wid == 0) tmem_dealloc(tmem, 64);

#else  // ------------------- FMA fallback (non-'a' pass) -------------------
    ull*   wT = (ull*)(smem + SMF_WT);
    float* hs = (float*)(smem + SMF_HS);

    const int rowA = tid >> 1;
    const int jh   = (tid & 1) * 16;
    const float s1r = g_s1[row0 + rowA];
    const int*   adjRow = adj + (size_t)(row0 + rowA) * N_NODES + jbase + jh;
    const float* s2p    = g_s2 + jbase + jh;
    float lpart = 0.f;

    const int rg = tid >> 4;
    const int fg = tid & 15;
    ull acc[16];
#pragma unroll
    for (int i = 0; i < 16; i++) acc[i] = 0ull;

    const int hjl = tid >> 4;
    const int hf4 = tid & 15;

    for (int t = 0; t < NT_F; t++) {
        const int jt = jbase + t * BJ_F;
        const int4* ap = (const int4*)(adjRow + t * BJ_F);
        int4 A0 = ap[0], A1 = ap[1], A2 = ap[2], A3 = ap[3];
        float4 S0 = *(const float4*)(s2p + t * BJ_F);
        float4 S1 = *(const float4*)(s2p + t * BJ_F + 4);
        float4 S2 = *(const float4*)(s2p + t * BJ_F + 8);
        float4 S3 = *(const float4*)(s2p + t * BJ_F + 12);
        float4 H0 = *(const float4*)&g_h[(size_t)(jt + hjl) * F_OUT + hf4 * 4];
        float4 H1 = *(const float4*)&g_h[(size_t)(jt + 16 + hjl) * F_OUT + hf4 * 4];

        __syncthreads();

        *(float4*)&hs[hjl * HS_PITCH + hf4 * 4]        = H0;
        *(float4*)&hs[(16 + hjl) * HS_PITCH + hf4 * 4] = H1;

        int   av[16]; float sv[16];
        *(int4*)&av[0] = A0; *(int4*)&av[4] = A1; *(int4*)&av[8] = A2; *(int4*)&av[12] = A3;
        *(float4*)&sv[0] = S0; *(float4*)&sv[4] = S1; *(float4*)&sv[8] = S2; *(float4*)&sv[12] = S3;

#pragma unroll
        for (int jj = 0; jj < 16; jj++) {
            float e  = s1r + sv[jj];
            float le = fmaxf(e, 0.2f * e);
            float w  = __expf(le);
            w = (av[jj] > 0) ? w : 0.f;
            lpart += w;
            wT[(jh + jj) * WT_PITCH + rowA] = dup2(w);
        }
        __syncthreads();

#pragma unroll 4
        for (int jj = 0; jj < BJ_F; jj++) {
            const ulonglong2* wp = (const ulonglong2*)&wT[jj * WT_PITCH + rg * 8];
            ulonglong2 w01 = wp[0], w23 = wp[1], w45 = wp[2], w67 = wp[3];
            ulonglong2 hv  = *(const ulonglong2*)&hs[jj * HS_PITCH + fg * 4];
            ffma2(acc[0],  w01.x, hv.x); ffma2(acc[1],  w01.x, hv.y);
            ffma2(acc[2],  w01.y, hv.x); ffma2(acc[3],  w01.y, hv.y);
            ffma2(acc[4],  w23.x, hv.x); ffma2(acc[5],  w23.x, hv.y);
            ffma2(acc[6],  w23.y, hv.x); ffma2(acc[7],  w23.y, hv.y);
            ffma2(acc[8],  w45.x, hv.x); ffma2(acc[9],  w45.x, hv.y);
            ffma2(acc[10], w45.y, hv.x); ffma2(acc[11], w45.y, hv.y);
            ffma2(acc[12], w67.x, hv.x); ffma2(acc[13], w67.x, hv.y);
            ffma2(acc[14], w67.y, hv.x); ffma2(acc[15], w67.y, hv.y);
        }
    }

    float lo2 = __shfl_xor_sync(0xffffffffu, lpart, 1);
    if ((tid & 1) == 0) g_lP[s][row0 + rowA] = lpart + lo2;

    float* ap2 = g_accP[s];
#pragma unroll
    for (int r = 0; r < 8; r++) {
        float2 x = unpack2(acc[r * 2]);
        float2 y = unpack2(acc[r * 2 + 1]);
        float4 o = make_float4(x.x, x.y, y.x, y.y);
        *(float4*)&ap2[(size_t)(row0 + rg * 8 + r) * F_OUT + fg * 4] = o;
    }
#endif
}

// ---------------------------------------------------------------------------
// Kernel 3: out[i][f] = sum_s accP[s][i][f] / sum_s lP[s][i]  (float4)
// ---------------------------------------------------------------------------
__global__ __launch_bounds__(256) void k_norm(float* __restrict__ out) {
    const int idx = blockIdx.x * 256 + threadIdx.x;
    const int i = idx >> 4;
    float4 v0 = ((const float4*)g_accP[0])[idx];
    float4 v1 = ((const float4*)g_accP[1])[idx];
    float4 v2 = ((const float4*)g_accP[2])[idx];
    float4 v3 = ((const float4*)g_accP[3])[idx];
    float inv = 1.f / ((g_lP[0][i] + g_lP[1][i]) + (g_lP[2][i] + g_lP[3][i]));
    float4 o = make_float4(((v0.x + v1.x) + (v2.x + v3.x)) * inv,
                           ((v0.y + v1.y) + (v2.y + v3.y)) * inv,
                           ((v0.z + v1.z) + (v2.z + v3.z)) * inv,
                           ((v0.w + v1.w) + (v2.w + v3.w)) * inv);
    ((float4*)out)[idx] = o;
}

extern "C" void kernel_launch(void* const* d_in, const int* in_sizes, int n_in,
                              void* d_out, int out_size) {
    const float* inp = (const float*)d_in[0];
    const int*   adj = (const int*)d_in[1];
    const float* W   = (const float*)d_in[2];
    const float* a   = (const float*)d_in[3];
    float* out = (float*)d_out;

    cudaFuncSetAttribute(k_hproj_tc, cudaFuncAttributeMaxDynamicSharedMemorySize, HP_SMTOT);
    cudaFuncSetAttribute(k_attn_tc, cudaFuncAttributeMaxDynamicSharedMemorySize, SM_TOT);

    k_wprep<<<64, 512>>>(W);
    k_hproj_tc<<<N_NODES / 128, NTHR_H, HP_SMTOT>>>(inp, W, a);
    dim3 g2(N_NODES / BM, NSPLIT);
    k_attn_tc<<<g2, NTHR_A, SM_TOT>>>(adj);
    k_norm<<<(N_NODES * F_OUT / 4) / 256, 256>>>(out);
}